// round 9
// baseline (speedup 1.0000x reference)
#include <cuda_runtime.h>
#include <math.h>

// ---- problem constants ----
#define BATCH   8
#define TT      256
#define BT      2048          // BATCH*TT
#define DM      256           // d_model
#define DI      512           // d_inner
#define DS      16            // d_state
#define DTR     16            // dt_rank

typedef unsigned long long u64;

__device__ __forceinline__ u64 pk2(float lo, float hi) {
    u64 d;
    asm("mov.b64 %0, {%1, %2};" : "=l"(d)
        : "r"(__float_as_uint(lo)), "r"(__float_as_uint(hi)));
    return d;
}
__device__ __forceinline__ u64 ffma2(u64 a, u64 b, u64 c) {
    u64 d;
    asm("fma.rn.f32x2 %0, %1, %2, %3;" : "=l"(d) : "l"(a), "l"(b), "l"(c));
    return d;
}
__device__ __forceinline__ float2 upk2(u64 v) {
    unsigned lo, hi;
    asm("mov.b64 {%0, %1}, %2;" : "=r"(lo), "=r"(hi) : "l"(v));
    return make_float2(__uint_as_float(lo), __uint_as_float(hi));
}
union F4U { float4 f; u64 u[2]; };

// ---- scratch ----
__device__ float  g_f1[2048*16*32*32];
__device__ float  g_f2[2048*32*16*16];
__device__ float  g_h [BT*DM];
__device__ float  g_xn[BT*DM];
__device__ float  g_xz[BT*2*DI];
__device__ float2 g_bc[BT*DS];
__device__ float2 g_du[BT*DI];
__device__ float  g_y [BT*DI];
__device__ float  g_hh[BT*64];
__device__ float  g_logits[BT];

// =====================================================================
// CNN
// =====================================================================
__global__ __launch_bounds__(512) void conv1_kernel(const float* __restrict__ x,
                             const float* __restrict__ w,
                             const float* __restrict__ b,
                             float* __restrict__ out)
{
    __shared__ __align__(16) float sin[65*65];
    __shared__ __align__(16) float sw[288];      // splatted
    __shared__ __align__(16) float sb[16];
    int f = blockIdx.x;
    const float* xf = x + (size_t)f*4096;
    for (int i = threadIdx.x; i < 65*65; i += 512) {
        int r = i / 65, c = i - r*65;
        sin[i] = (r < 64 && c < 64) ? xf[r*64+c] : 0.f;
    }
    if (threadIdx.x < 144) {
        float v = w[threadIdx.x];
        sw[2*threadIdx.x] = v; sw[2*threadIdx.x+1] = v;
    }
    if (threadIdx.x < 16)  sb[threadIdx.x] = b[threadIdx.x];
    __syncthreads();
    int xg = threadIdx.x & 3;
    int oy = (threadIdx.x >> 2) & 31;
    int cq = threadIdx.x >> 7;
    u64 acc2[4][4];
    #pragma unroll
    for (int c = 0; c < 4; c++) {
        float bb = sb[cq*4+c];
        u64 bp = pk2(bb, bb);
        #pragma unroll
        for (int p = 0; p < 4; p++) acc2[c][p] = bp;
    }
    int i0 = oy*2, j0 = xg*16;
    #pragma unroll
    for (int ky = 0; ky < 3; ky++) {
        const float* rp = sin + (i0+ky)*65 + j0;
        float r[17];
        #pragma unroll
        for (int t = 0; t < 17; t++) r[t] = rp[t];
        u64 pr[12];
        #pragma unroll
        for (int p = 0; p < 4; p++)
            #pragma unroll
            for (int l = 0; l < 3; l++)
                pr[p*3+l] = pk2(r[p*4+l], r[p*4+l+2]);
        #pragma unroll
        for (int c = 0; c < 4; c++) {
            const float* wp = sw + ((cq*4+c)*9 + ky*3)*2;
            u64 wd0 = *(const u64*)(wp+0);
            u64 wd1 = *(const u64*)(wp+2);
            u64 wd2 = *(const u64*)(wp+4);
            #pragma unroll
            for (int p = 0; p < 4; p++) {
                acc2[c][p] = ffma2(pr[p*3+0], wd0, acc2[c][p]);
                acc2[c][p] = ffma2(pr[p*3+1], wd1, acc2[c][p]);
                acc2[c][p] = ffma2(pr[p*3+2], wd2, acc2[c][p]);
            }
        }
    }
    #pragma unroll
    for (int c = 0; c < 4; c++)
        #pragma unroll
        for (int p = 0; p < 4; p++) {
            float2 v = upk2(acc2[c][p]);
            float2 o = make_float2(fmaxf(v.x, 0.f), fmaxf(v.y, 0.f));
            *(float2*)&out[((size_t)f*16 + cq*4+c)*1024 + oy*32 + xg*8 + 2*p] = o;
        }
}

__global__ __launch_bounds__(256) void conv2_kernel(const float* __restrict__ in,
                             const float* __restrict__ w,
                             const float* __restrict__ b,
                             float* __restrict__ out)
{
    __shared__ __align__(16) float sin[8*33*34];
    __shared__ __align__(16) float sw[4608];     // splatted 32co*8ci*9*2
    int f = blockIdx.x;
    int tid = threadIdx.x;
    int cg  = tid >> 5;
    int lane = tid & 31;
    int oy = lane >> 1;
    int xh = lane & 1;
    u64 acc2[4][4];
    #pragma unroll
    for (int c = 0; c < 4; c++) {
        float bb = __ldg(&b[cg*4+c]);
        u64 bp = pk2(bb, bb);
        #pragma unroll
        for (int p = 0; p < 4; p++) acc2[c][p] = bp;
    }
    #pragma unroll 1
    for (int pass = 0; pass < 2; pass++) {
        int ci0 = pass*8;
        __syncthreads();
        for (int idx = tid; idx < 8*33*33; idx += 256) {
            int ci = idx / 1089;
            int rem = idx - ci*1089;
            int i = rem / 33, j = rem - i*33;
            sin[ci*1122 + i*34 + j] = (i < 32 && j < 32)
                ? in[(size_t)f*16384 + (ci0+ci)*1024 + i*32 + j] : 0.f;
        }
        for (int idx = tid; idx < 2304; idx += 256) {
            int co = idx / 72;
            int rem = idx - co*72;
            int ci_l = rem / 9, k = rem - ci_l*9;
            float v = w[(co*16 + ci0 + ci_l)*9 + k];
            sw[2*idx] = v; sw[2*idx+1] = v;
        }
        __syncthreads();
        #pragma unroll 1
        for (int ci = 0; ci < 8; ci++) {
            const float* base = sin + ci*1122 + (2*oy)*34 + xh*16;
            #pragma unroll
            for (int row = 0; row < 3; row++) {
                const float* rp = base + row*34;
                float r[17];
                #pragma unroll
                for (int t = 0; t < 17; t++) r[t] = rp[t];
                u64 pr[12];
                #pragma unroll
                for (int p = 0; p < 4; p++)
                    #pragma unroll
                    for (int l = 0; l < 3; l++)
                        pr[p*3+l] = pk2(r[p*4+l], r[p*4+l+2]);
                #pragma unroll
                for (int c = 0; c < 4; c++) {
                    const float* wp = sw + ((cg*4+c)*72 + ci*9 + row*3)*2;
                    u64 wd0 = *(const u64*)(wp+0);
                    u64 wd1 = *(const u64*)(wp+2);
                    u64 wd2 = *(const u64*)(wp+4);
                    #pragma unroll
                    for (int p = 0; p < 4; p++) {
                        acc2[c][p] = ffma2(pr[p*3+0], wd0, acc2[c][p]);
                        acc2[c][p] = ffma2(pr[p*3+1], wd1, acc2[c][p]);
                        acc2[c][p] = ffma2(pr[p*3+2], wd2, acc2[c][p]);
                    }
                }
            }
        }
    }
    #pragma unroll
    for (int c = 0; c < 4; c++)
        #pragma unroll
        for (int p = 0; p < 4; p++) {
            float2 v = upk2(acc2[c][p]);
            float2 o = make_float2(fmaxf(v.x, 0.f), fmaxf(v.y, 0.f));
            *(float2*)&out[((size_t)f*32 + cg*4+c)*256 + oy*16 + xh*8 + 2*p] = o;
        }
}

// conv3 + relu + global avg pool + fc (32->256) fused; 2 frames per block
__global__ __launch_bounds__(256) void conv3poolfc_kernel(const float* __restrict__ in,
                                 const float* __restrict__ w,
                                 const float* __restrict__ b,
                                 const float* __restrict__ fcw,
                                 const float* __restrict__ fcb,
                                 float* __restrict__ h)
{
    __shared__ __align__(16) float sin[2*8*17*18];
    __shared__ __align__(16) float sw[4608];    // splatted
    __shared__ __align__(16) float zsh[64];
    int f0 = blockIdx.x * 2;
    int tid = threadIdx.x;
    int fr = tid >> 7;
    int t  = tid & 127;
    int cg = t >> 4;
    int oy = (t >> 1) & 7;
    int xh = t & 1;
    u64 acc2[4][2];
    #pragma unroll
    for (int c = 0; c < 4; c++) {
        float bb = __ldg(&b[cg*4+c]);
        u64 bp = pk2(bb, bb);
        acc2[c][0] = bp; acc2[c][1] = bp;
    }
    #pragma unroll 1
    for (int pass = 0; pass < 4; pass++) {
        int ci0 = pass*8;
        __syncthreads();
        for (int idx = tid; idx < 2*8*17*17; idx += 256) {
            int fr2 = idx / 2312;
            int rem = idx - fr2*2312;
            int ci = rem / 289;
            int r2 = rem - ci*289;
            int i = r2 / 17, j = r2 - i*17;
            sin[fr2*2448 + ci*306 + i*18 + j] = (i < 16 && j < 16)
                ? in[(size_t)(f0+fr2)*8192 + (ci0+ci)*256 + i*16 + j] : 0.f;
        }
        for (int idx = tid; idx < 2304; idx += 256) {
            int co = idx / 72;
            int rem = idx - co*72;
            int ci_l = rem / 9, k = rem - ci_l*9;
            float v = w[(co*32 + ci0 + ci_l)*9 + k];
            sw[2*idx] = v; sw[2*idx+1] = v;
        }
        __syncthreads();
        #pragma unroll 1
        for (int ci = 0; ci < 8; ci++) {
            const float* base = sin + fr*2448 + ci*306 + (2*oy)*18 + xh*8;
            #pragma unroll
            for (int row = 0; row < 3; row++) {
                const float* rp = base + row*18;
                float r[9];
                #pragma unroll
                for (int q = 0; q < 9; q++) r[q] = rp[q];
                u64 pr[6];
                #pragma unroll
                for (int p = 0; p < 2; p++)
                    #pragma unroll
                    for (int l = 0; l < 3; l++)
                        pr[p*3+l] = pk2(r[p*4+l], r[p*4+l+2]);
                #pragma unroll
                for (int c = 0; c < 4; c++) {
                    const float* wp = sw + ((cg*4+c)*72 + ci*9 + row*3)*2;
                    u64 wd0 = *(const u64*)(wp+0);
                    u64 wd1 = *(const u64*)(wp+2);
                    u64 wd2 = *(const u64*)(wp+4);
                    #pragma unroll
                    for (int p = 0; p < 2; p++) {
                        acc2[c][p] = ffma2(pr[p*3+0], wd0, acc2[c][p]);
                        acc2[c][p] = ffma2(pr[p*3+1], wd1, acc2[c][p]);
                        acc2[c][p] = ffma2(pr[p*3+2], wd2, acc2[c][p]);
                    }
                }
            }
        }
    }
    #pragma unroll
    for (int c = 0; c < 4; c++) {
        float2 v0 = upk2(acc2[c][0]), v1 = upk2(acc2[c][1]);
        float s = fmaxf(v0.x,0.f) + fmaxf(v0.y,0.f) + fmaxf(v1.x,0.f) + fmaxf(v1.y,0.f);
        #pragma unroll
        for (int o = 8; o > 0; o >>= 1) s += __shfl_down_sync(0xffffffffu, s, o, 16);
        if (oy == 0 && xh == 0) zsh[fr*32 + cg*4 + c] = s * (1.f/64.f);
    }
    __syncthreads();
    int fr2 = tid >> 7;
    int j = tid & 127;
    const float* zz = zsh + fr2*32;
    float a0 = fcb[j], a1 = fcb[j+128];
    const float4* w0p = (const float4*)(fcw + j*32);
    const float4* w1p = (const float4*)(fcw + (j+128)*32);
    #pragma unroll
    for (int k = 0; k < 8; k++) {
        float4 wv0 = w0p[k], wv1 = w1p[k];
        const float* zk = zz + k*4;
        a0 = fmaf(zk[0],wv0.x,fmaf(zk[1],wv0.y,fmaf(zk[2],wv0.z,fmaf(zk[3],wv0.w,a0))));
        a1 = fmaf(zk[0],wv1.x,fmaf(zk[1],wv1.y,fmaf(zk[2],wv1.z,fmaf(zk[3],wv1.w,a1))));
    }
    h[(size_t)(f0+fr2)*256 + j] = a0;
    h[(size_t)(f0+fr2)*256 + j + 128] = a1;
}

// =====================================================================
// Mamba pieces
// =====================================================================
__global__ __launch_bounds__(256) void rmsnorm_kernel(const float* __restrict__ x,
                               const float* __restrict__ w,
                               float* __restrict__ out)
{
    int tok = blockIdx.x*8 + (threadIdx.x >> 5);
    int lane = threadIdx.x & 31;
    const float4* xr = (const float4*)(x + (size_t)tok*256);
    float4 v0 = xr[lane*2], v1 = xr[lane*2+1];
    float ss = v0.x*v0.x + v0.y*v0.y + v0.z*v0.z + v0.w*v0.w
             + v1.x*v1.x + v1.y*v1.y + v1.z*v1.z + v1.w*v1.w;
    #pragma unroll
    for (int o = 16; o > 0; o >>= 1) ss += __shfl_xor_sync(0xffffffffu, ss, o);
    float scale = rsqrtf(ss * (1.f/256.f) + 1e-5f);
    const float4* wr = (const float4*)w;
    float4 w0 = wr[lane*2], w1 = wr[lane*2+1];
    float4 o0, o1;
    o0.x = v0.x*scale*w0.x; o0.y = v0.y*scale*w0.y; o0.z = v0.z*scale*w0.z; o0.w = v0.w*scale*w0.w;
    o1.x = v1.x*scale*w1.x; o1.y = v1.y*scale*w1.y; o1.z = v1.z*scale*w1.z; o1.w = v1.w*scale*w1.w;
    float4* outr = (float4*)(out + (size_t)tok*256);
    outr[lane*2] = o0; outr[lane*2+1] = o1;
}

// tile 64x64, 256 thr, 4x4 micro, f32x2 splatted-W + double buffer
__global__ __launch_bounds__(256) void gemm64_kernel(const float* __restrict__ A,
                              const float* __restrict__ W,
                              float* __restrict__ C,
                              int M, int N, int K)
{
    __shared__ __align__(16) float As[2][16][68];
    __shared__ __align__(16) float Ws[2][16][136];
    int bm = blockIdx.y * 64;
    int bn = blockIdx.x * 64;
    int tid = threadIdx.x;
    int tx = tid & 15, ty = tid >> 4;
    int r = tid >> 2, c = tid & 3;
    const float* Ap = &A[(size_t)(bm+r)*K + c*4];
    const float* Wp = &W[(size_t)(bn+r)*K + c*4];
    float4 va = *(const float4*)Ap;
    float4 vw = *(const float4*)Wp;
    u64 acc[2][4];
    #pragma unroll
    for (int i = 0; i < 2; i++)
        #pragma unroll
        for (int j = 0; j < 4; j++) acc[i][j] = 0ull;
    // stage tile 0
    #pragma unroll
    for (int i = 0; i < 4; i++) {
        As[0][c*4+i][r] = (&va.x)[i];
        float wv = (&vw.x)[i];
        *(float2*)&Ws[0][c*4+i][2*r] = make_float2(wv, wv);
    }
    __syncthreads();
    int buf = 0;
    for (int k0 = 0; k0 < K; k0 += 16) {
        bool more = (k0 + 16 < K);
        if (more) {
            va = *(const float4*)(Ap + k0 + 16);
            vw = *(const float4*)(Wp + k0 + 16);
        }
        #pragma unroll
        for (int k = 0; k < 16; k++) {
            F4U au; au.f = *(const float4*)&As[buf][k][ty*4];
            F4U b0, b1;
            b0.f = *(const float4*)&Ws[buf][k][tx*8];
            b1.f = *(const float4*)&Ws[buf][k][tx*8+4];
            acc[0][0] = ffma2(au.u[0], b0.u[0], acc[0][0]);
            acc[0][1] = ffma2(au.u[0], b0.u[1], acc[0][1]);
            acc[0][2] = ffma2(au.u[0], b1.u[0], acc[0][2]);
            acc[0][3] = ffma2(au.u[0], b1.u[1], acc[0][3]);
            acc[1][0] = ffma2(au.u[1], b0.u[0], acc[1][0]);
            acc[1][1] = ffma2(au.u[1], b0.u[1], acc[1][1]);
            acc[1][2] = ffma2(au.u[1], b1.u[0], acc[1][2]);
            acc[1][3] = ffma2(au.u[1], b1.u[1], acc[1][3]);
        }
        if (more) {
            int nb = buf ^ 1;
            #pragma unroll
            for (int i = 0; i < 4; i++) {
                As[nb][c*4+i][r] = (&va.x)[i];
                float wv = (&vw.x)[i];
                *(float2*)&Ws[nb][c*4+i][2*r] = make_float2(wv, wv);
            }
            __syncthreads();
            buf = nb;
        }
    }
    // acc[i][j]: lo = row (ty*4 + 2i... ) — mapping: au.u[0] = rows (ty*4, ty*4+1)
    #pragma unroll
    for (int rp = 0; rp < 2; rp++) {
        float2 q0 = upk2(acc[rp][0]), q1 = upk2(acc[rp][1]);
        float2 q2 = upk2(acc[rp][2]), q3 = upk2(acc[rp][3]);
        int m0 = bm + ty*4 + rp*2;
        *(float4*)&C[(size_t)m0*N + bn + tx*4]     = make_float4(q0.x, q1.x, q2.x, q3.x);
        *(float4*)&C[(size_t)(m0+1)*N + bn + tx*4] = make_float4(q0.y, q1.y, q2.y, q3.y);
    }
}

// tile 32x64, 256 thr, 2x4 micro, f32x2 splatted-W + double buffer.
// EPI: 1 accumulate, 2 bias+gelu
template<int EPI>
__global__ __launch_bounds__(256) void gemm32x64_kernel(const float* __restrict__ A,
                              const float* __restrict__ W,
                              const float* __restrict__ bias,
                              float* __restrict__ C,
                              int M, int N, int K)
{
    __shared__ __align__(16) float As[2][16][36];
    __shared__ __align__(16) float Ws[2][16][136];
    int bm = blockIdx.y * 32;
    int bn = blockIdx.x * 64;
    int tid = threadIdx.x;
    int tx = tid & 15, ty = tid >> 4;
    int r = tid >> 2, c = tid & 3;
    const float* Ap = &A[(size_t)(bm+r)*K + c*4];
    const float* Wp = &W[(size_t)(bn+r)*K + c*4];
    float4 va;
    if (tid < 128) va = *(const float4*)Ap;
    float4 vw = *(const float4*)Wp;
    u64 acc[4];
    acc[0]=0ull; acc[1]=0ull; acc[2]=0ull; acc[3]=0ull;
    if (tid < 128) {
        #pragma unroll
        for (int i = 0; i < 4; i++) As[0][c*4+i][r] = (&va.x)[i];
    }
    #pragma unroll
    for (int i = 0; i < 4; i++) {
        float wv = (&vw.x)[i];
        *(float2*)&Ws[0][c*4+i][2*r] = make_float2(wv, wv);
    }
    __syncthreads();
    int buf = 0;
    for (int k0 = 0; k0 < K; k0 += 16) {
        bool more = (k0 + 16 < K);
        if (more) {
            if (tid < 128) va = *(const float4*)(Ap + k0 + 16);
            vw = *(const float4*)(Wp + k0 + 16);
        }
        #pragma unroll
        for (int k = 0; k < 16; k++) {
            u64 ap = *(const u64*)&As[buf][k][ty*2];
            F4U b0, b1;
            b0.f = *(const float4*)&Ws[buf][k][tx*8];
            b1.f = *(const float4*)&Ws[buf][k][tx*8+4];
            acc[0] = ffma2(ap, b0.u[0], acc[0]);
            acc[1] = ffma2(ap, b0.u[1], acc[1]);
            acc[2] = ffma2(ap, b1.u[0], acc[2]);
            acc[3] = ffma2(ap, b1.u[1], acc[3]);
        }
        if (more) {
            int nb = buf ^ 1;
            if (tid < 128) {
                #pragma unroll
                for (int i = 0; i < 4; i++) As[nb][c*4+i][r] = (&va.x)[i];
            }
            #pragma unroll
            for (int i = 0; i < 4; i++) {
                float wv = (&vw.x)[i];
                *(float2*)&Ws[nb][c*4+i][2*r] = make_float2(wv, wv);
            }
            __syncthreads();
            buf = nb;
        }
    }
    float2 q0 = upk2(acc[0]), q1 = upk2(acc[1]);
    float2 q2 = upk2(acc[2]), q3 = upk2(acc[3]);
    float rowv[2][4] = {{q0.x,q1.x,q2.x,q3.x},{q0.y,q1.y,q2.y,q3.y}};
    #pragma unroll
    for (int i = 0; i < 2; i++) {
        int m = bm + ty*2 + i;
        size_t base = (size_t)m*N + bn + tx*4;
        if (EPI == 1) {
            float4 old = *(float4*)&C[base];
            old.x += rowv[i][0]; old.y += rowv[i][1];
            old.z += rowv[i][2]; old.w += rowv[i][3];
            *(float4*)&C[base] = old;
        } else {
            float4 o;
            float* op = &o.x;
            #pragma unroll
            for (int j = 0; j < 4; j++) {
                float v = rowv[i][j] + bias[bn + tx*4 + j];
                float v3 = v*v*v;
                op[j] = 0.5f * v * (1.f + tanhf(0.7978845608028654f * (v + 0.044715f*v3)));
            }
            *(float4*)&C[base] = o;
        }
    }
}

// Fused conv1d+silu + x_proj + dt_proj: per block 16 tokens.
#define SXIDX(tok, k) ((tok)*512 + (((k) + (tok)*4) & 511))
__global__ __launch_bounds__(256) void xproj_fused_kernel(
    const float* __restrict__ xz,
    const float* __restrict__ cw,
    const float* __restrict__ cb,
    const float* __restrict__ xpw,
    const float* __restrict__ dpw,
    const float* __restrict__ dpb,
    float2* __restrict__ bc,
    float2* __restrict__ du)
{
    __shared__ __align__(16) float sx[16*512];
    __shared__ __align__(16) float buf[48*68];
    __shared__ __align__(16) float sdt[16*16];
    int tok0 = blockIdx.x * 16;
    int tid = threadIdx.x;

    // ---- conv1d + silu from xz into sx ----
    for (int idx = tid; idx < 2048; idx += 256) {
        int e = idx >> 2, k = idx & 3;
        buf[k*512 + e] = cw[idx];
    }
    for (int idx = tid; idx < 512; idx += 256) buf[2048 + idx] = cb[idx];
    __syncthreads();
    int tl0 = tok0 & 255;
    #pragma unroll 1
    for (int s = 0; s < 8; s++) {
        int q = tid + s*256;
        int t = q >> 7;
        int e = (q & 127)*4;
        float4 acc = *(const float4*)&buf[2048 + e];
        #pragma unroll
        for (int k = 0; k < 4; k++) {
            if (tl0 + t - 3 + k >= 0) {
                float4 xv = *(const float4*)&xz[(size_t)(tok0 + t - 3 + k)*1024 + e];
                float4 wv = *(const float4*)&buf[k*512 + e];
                acc.x = fmaf(xv.x, wv.x, acc.x);
                acc.y = fmaf(xv.y, wv.y, acc.y);
                acc.z = fmaf(xv.z, wv.z, acc.z);
                acc.w = fmaf(xv.w, wv.w, acc.w);
            }
        }
        acc.x = acc.x / (1.f + __expf(-acc.x));
        acc.y = acc.y / (1.f + __expf(-acc.y));
        acc.z = acc.z / (1.f + __expf(-acc.z));
        acc.w = acc.w / (1.f + __expf(-acc.w));
        *(float4*)&sx[SXIDX(t, e)] = acc;
    }

    // ---- Phase A: dbc = xin . xpw^T (float4 k-unroll) ----
    int tg = tid & 15;
    int jg = tid >> 4;
    int rot = tg*4;
    const float* sxr = sx + tg*512;
    float acc0 = 0.f, acc1 = 0.f, acc2 = 0.f;
    #pragma unroll 1
    for (int kc = 0; kc < 8; kc++) {
        int k0 = kc*64;
        __syncthreads();
        #pragma unroll
        for (int s = 0; s < 3; s++) {
            int q = tid + s*256;
            int r = q >> 4, c = q & 15;
            float4 v = *(const float4*)&xpw[(size_t)r*512 + k0 + c*4];
            float* dst = buf + r*68 + c*4;
            dst[0]=v.x; dst[1]=v.y; dst[2]=v.z; dst[3]=v.w;
        }
        __syncthreads();
        const float* w0 = buf + (jg*3+0)*68;
        const float* w1 = buf + (jg*3+1)*68;
        const float* w2 = buf + (jg*3+2)*68;
        #pragma unroll
        for (int k4 = 0; k4 < 16; k4++) {
            int kk = (k0 + k4*4 + rot) & 511;
            float4 xv = *(const float4*)&sxr[kk];
            float4 a4 = *(const float4*)&w0[k4*4];
            float4 b4 = *(const float4*)&w1[k4*4];
            float4 c4 = *(const float4*)&w2[k4*4];
            acc0 = fmaf(xv.x,a4.x, fmaf(xv.y,a4.y, fmaf(xv.z,a4.z, fmaf(xv.w,a4.w, acc0))));
            acc1 = fmaf(xv.x,b4.x, fmaf(xv.y,b4.y, fmaf(xv.z,b4.z, fmaf(xv.w,b4.w, acc1))));
            acc2 = fmaf(xv.x,c4.x, fmaf(xv.y,c4.y, fmaf(xv.z,c4.z, fmaf(xv.w,c4.w, acc2))));
        }
    }
    {
        float av[3] = {acc0, acc1, acc2};
        #pragma unroll
        for (int jj = 0; jj < 3; jj++) {
            int j = jg*3 + jj;
            float v = av[jj];
            int tok = tok0 + tg;
            if (j < 16)       sdt[tg*16 + j] = v;
            else if (j < 32)  bc[tok*16 + (j-16)].x = v;
            else              bc[tok*16 + (j-32)].y = v;
        }
    }

    // ---- Phase B ----
    #pragma unroll 1
    for (int ec = 0; ec < 4; ec++) {
        int e0 = ec*128;
        __syncthreads();
        #pragma unroll
        for (int s = 0; s < 2; s++) {
            int q = tid + s*256;
            int r = q >> 2, c = q & 3;
            float4 v = *(const float4*)&dpw[(size_t)(e0+r)*16 + c*4];
            float* dst = buf + r*16 + c*4;
            dst[0]=v.x; dst[1]=v.y; dst[2]=v.z; dst[3]=v.w;
        }
        __syncthreads();
        #pragma unroll 1
        for (int s = 0; s < 8; s++) {
            int idx = tid + s*256;
            int e_l = idx & 127;
            int tok = idx >> 7;
            int e = e0 + e_l;
            const float* dr = sdt + tok*16;
            const float* wr = buf + e_l*16;
            float a = dpb[e];
            #pragma unroll
            for (int k = 0; k < 16; k++) a = fmaf(dr[k], wr[k], a);
            float sp = (a > 20.f) ? a : log1pf(expf(a));
            float u = sx[SXIDX(tok, e)];
            du[(size_t)(tok0+tok)*512 + e] = make_float2(sp, u);
        }
    }
}

// Selective scan: chunked register prefetch + pipelined shfl reduction
__global__ __launch_bounds__(256) void scan_kernel(const float2* __restrict__ du,
                            const float* __restrict__ xz,
                            const float2* __restrict__ bc,
                            const float* __restrict__ A_log,
                            const float* __restrict__ Dp,
                            float* __restrict__ yout)
{
    int tid = blockIdx.x * blockDim.x + threadIdx.x;
    int ch = tid >> 4;
    int n = tid & 15;
    int b = ch >> 9;
    int e = ch & 511;
    float A  = -expf(A_log[e*16 + n]);
    float Dv = Dp[e];
    const float2* duP = du + (size_t)(b*256)*512 + e;
    const float2* bcP = bc + (size_t)(b*256)*16 + n;
    const float*  zP  = xz + (size_t)(b*256)*1024 + 512 + e;
    float* yP = yout + (size_t)(b*256)*512 + e;

    float2 dv[2][8], bv[2][8];
    float  zv[2][8];
    #pragma unroll
    for (int i = 0; i < 8; i++) {
        dv[0][i] = duP[i*512];
        bv[0][i] = bcP[i*16];
    }
    if (n == 0) {
        #pragma unroll
        for (int i = 0; i < 8; i++) zv[0][i] = zP[i*1024];
    }
    float h = 0.f;
    int buf = 0;
    #pragma unroll 1
    for (int c = 0; c < 32; c++) {
        int nb = buf ^ 1;
        if (c < 31) {
            int t1 = c*8 + 8;
            #pragma unroll
            for (int i = 0; i < 8; i++) {
                dv[nb][i] = duP[(t1+i)*512];
                bv[nb][i] = bcP[(t1+i)*16];
            }
            if (n == 0) {
                #pragma unroll
                for (int i = 0; i < 8; i++) zv[nb][i] = zP[(size_t)(t1+i)*1024];
            }
        }
        float part[8];
        #pragma unroll
        for (int i = 0; i < 8; i++) {
            float2 duv = dv[buf][i];
            float2 bcv = bv[buf][i];
            float dA = __expf(duv.x * A);
            h = fmaf(h, dA, duv.x * bcv.x * duv.y);
            part[i] = h * bcv.y;
        }
        #pragma unroll
        for (int o = 8; o > 0; o >>= 1) {
            #pragma unroll
            for (int i = 0; i < 8; i++)
                part[i] += __shfl_down_sync(0xffffffffu, part[i], o, 16);
        }
        if (n == 0) {
            #pragma unroll
            for (int i = 0; i < 8; i++) {
                float z = zv[buf][i];
                float yy = part[i] + dv[buf][i].y * Dv;
                yP[(size_t)(c*8+i)*512] = yy * (z / (1.f + __expf(-z)));
            }
        }
        buf = nb;
    }
}

// =====================================================================
// Head tail
// =====================================================================
__global__ __launch_bounds__(256) void head2_kernel(const float* __restrict__ hh,
                             const float* __restrict__ w,
                             const float* __restrict__ b,
                             float* __restrict__ logits)
{
    int wid = (blockIdx.x * blockDim.x + threadIdx.x) >> 5;
    int lane = threadIdx.x & 31;
    const float* xr = hh + (size_t)wid*64;
    float acc = fmaf(xr[lane], w[lane], xr[lane+32]*w[lane+32]);
    #pragma unroll
    for (int o = 16; o > 0; o >>= 1) acc += __shfl_down_sync(0xffffffffu, acc, o);
    if (lane == 0) logits[wid] = acc + b[0];
}

__global__ __launch_bounds__(256) void softmax_kernel(const float* __restrict__ logits,
                               float* __restrict__ out)
{
    int b = blockIdx.x;
    int t = threadIdx.x;
    float v = logits[b*256 + t];
    __shared__ float red[8];
    __shared__ float sM, sS;
    float m = v;
    #pragma unroll
    for (int o = 16; o > 0; o >>= 1) m = fmaxf(m, __shfl_xor_sync(0xffffffffu, m, o));
    if ((t & 31) == 0) red[t >> 5] = m;
    __syncthreads();
    if (t < 8) {
        float mm = red[t];
        #pragma unroll
        for (int o = 4; o > 0; o >>= 1) mm = fmaxf(mm, __shfl_xor_sync(0xffu, mm, o, 8));
        if (t == 0) sM = mm;
    }
    __syncthreads();
    float e = expf(v - sM);
    float s = e;
    #pragma unroll
    for (int o = 16; o > 0; o >>= 1) s += __shfl_xor_sync(0xffffffffu, s, o);
    __syncthreads();
    if ((t & 31) == 0) red[t >> 5] = s;
    __syncthreads();
    if (t < 8) {
        float ss2 = red[t];
        #pragma unroll
        for (int o = 4; o > 0; o >>= 1) ss2 += __shfl_xor_sync(0xffu, ss2, o, 8);
        if (t == 0) sS = ss2;
    }
    __syncthreads();
    out[b*256 + t] = (t == 0) ? 0.f : e / sS;
}

// =====================================================================
// Launcher
// =====================================================================
extern "C" void kernel_launch(void* const* d_in, const int* in_sizes, int n_in,
                              void* d_out, int out_size)
{
    (void)in_sizes; (void)n_in; (void)out_size;
    const float* x        = (const float*)d_in[0];
    const float* cnn_w1   = (const float*)d_in[1];
    const float* cnn_b1   = (const float*)d_in[2];
    const float* cnn_w2   = (const float*)d_in[3];
    const float* cnn_b2   = (const float*)d_in[4];
    const float* cnn_w3   = (const float*)d_in[5];
    const float* cnn_b3   = (const float*)d_in[6];
    const float* fc_w     = (const float*)d_in[7];
    const float* fc_b     = (const float*)d_in[8];
    const float* norm_w   = (const float*)d_in[9];
    const float* in_proj_w= (const float*)d_in[10];
    const float* conv1d_w = (const float*)d_in[11];
    const float* conv1d_b = (const float*)d_in[12];
    const float* x_proj_w = (const float*)d_in[13];
    const float* dt_proj_w= (const float*)d_in[14];
    const float* dt_proj_b= (const float*)d_in[15];
    const float* A_log    = (const float*)d_in[16];
    const float* Dp       = (const float*)d_in[17];
    const float* out_proj_w=(const float*)d_in[18];
    const float* norm_f_w = (const float*)d_in[19];
    const float* head_w1  = (const float*)d_in[20];
    const float* head_b1  = (const float*)d_in[21];
    const float* head_w2  = (const float*)d_in[22];
    const float* head_b2  = (const float*)d_in[23];
    float* out = (float*)d_out;

    float *f1, *f2, *h, *xn, *xz, *y, *hh, *logits;
    float2 *bc, *du;
    cudaGetSymbolAddress((void**)&f1, g_f1);
    cudaGetSymbolAddress((void**)&f2, g_f2);
    cudaGetSymbolAddress((void**)&h,  g_h);
    cudaGetSymbolAddress((void**)&xn, g_xn);
    cudaGetSymbolAddress((void**)&xz, g_xz);
    cudaGetSymbolAddress((void**)&bc, g_bc);
    cudaGetSymbolAddress((void**)&du, g_du);
    cudaGetSymbolAddress((void**)&y,  g_y);
    cudaGetSymbolAddress((void**)&hh, g_hh);
    cudaGetSymbolAddress((void**)&logits, g_logits);

    // --- CNN encoder ---
    conv1_kernel<<<2048, 512>>>(x, cnn_w1, cnn_b1, f1);
    conv2_kernel<<<2048, 256>>>(f1, cnn_w2, cnn_b2, f2);
    conv3poolfc_kernel<<<1024, 256>>>(f2, cnn_w3, cnn_b3, fc_w, fc_b, h);

    // --- Mamba layers ---
    for (int l = 0; l < 6; l++) {
        const float* nw  = norm_w     + (size_t)l*DM;
        const float* ipw = in_proj_w  + (size_t)l*2*DI*DM;
        const float* cw  = conv1d_w   + (size_t)l*DI*4;
        const float* cb  = conv1d_b   + (size_t)l*DI;
        const float* xpw = x_proj_w   + (size_t)l*48*DI;
        const float* dpw = dt_proj_w  + (size_t)l*DI*DTR;
        const float* dpb = dt_proj_b  + (size_t)l*DI;
        const float* al  = A_log      + (size_t)l*DI*DS;
        const float* dv  = Dp         + (size_t)l*DI;
        const float* opw = out_proj_w + (size_t)l*DM*DI;

        rmsnorm_kernel<<<256, 256>>>(h, nw, xn);
        gemm64_kernel<<<dim3(16, 32), 256>>>(xn, ipw, xz, BT, 1024, 256);
        xproj_fused_kernel<<<128, 256>>>(xz, cw, cb, xpw, dpw, dpb, bc, du);
        scan_kernel<<<BATCH*DI*DS/256, 256>>>(du, xz, bc, al, dv, y);
        gemm32x64_kernel<1><<<dim3(4, 64), 256>>>(y, opw, nullptr, h, BT, 256, 512);
    }

    // --- Head ---
    rmsnorm_kernel<<<256, 256>>>(h, norm_f_w, xn);
    gemm32x64_kernel<2><<<dim3(1, 64), 256>>>(xn, head_w1, head_b1, hh, BT, 64, 256);
    head2_kernel<<<BT*32/256, 256>>>(hh, head_w2, head_b2, logits);
    softmax_kernel<<<BATCH, 256>>>(logits, out);
}

// round 10
// speedup vs baseline: 1.4098x; 1.4098x over previous
#include <cuda_runtime.h>
#include <math.h>

// ---- problem constants ----
#define BATCH   8
#define TT      256
#define BT      2048          // BATCH*TT
#define DM      256           // d_model
#define DI      512           // d_inner
#define DS      16            // d_state
#define DTR     16            // dt_rank

typedef unsigned long long u64;

__device__ __forceinline__ u64 pk2(float lo, float hi) {
    u64 d;
    asm("mov.b64 %0, {%1, %2};" : "=l"(d)
        : "r"(__float_as_uint(lo)), "r"(__float_as_uint(hi)));
    return d;
}
__device__ __forceinline__ u64 ffma2(u64 a, u64 b, u64 c) {
    u64 d;
    asm("fma.rn.f32x2 %0, %1, %2, %3;" : "=l"(d) : "l"(a), "l"(b), "l"(c));
    return d;
}
__device__ __forceinline__ float2 upk2(u64 v) {
    unsigned lo, hi;
    asm("mov.b64 {%0, %1}, %2;" : "=r"(lo), "=r"(hi) : "l"(v));
    return make_float2(__uint_as_float(lo), __uint_as_float(hi));
}
union F4U { float4 f; u64 u[2]; };

// ---- scratch ----
__device__ float  g_f1[2048*16*32*32];
__device__ float  g_f2[2048*32*16*16];
__device__ float  g_h [BT*DM];
__device__ float  g_xn[BT*DM];
__device__ float  g_xz[BT*2*DI];
__device__ float2 g_bc[BT*DS];
__device__ float2 g_du[BT*DI];
__device__ float  g_y [BT*DI];
__device__ float  g_hh[BT*64];
__device__ float  g_logits[BT];

// =====================================================================
// CNN (round-7 measured-good versions)
// =====================================================================
__global__ __launch_bounds__(512) void conv1_kernel(const float* __restrict__ x,
                             const float* __restrict__ w,
                             const float* __restrict__ b,
                             float* __restrict__ out)
{
    __shared__ __align__(16) float sin[65*65];
    __shared__ __align__(16) float sw[144];
    __shared__ __align__(16) float sb[16];
    int f = blockIdx.x;
    const float* xf = x + (size_t)f*4096;
    for (int i = threadIdx.x; i < 65*65; i += 512) {
        int r = i / 65, c = i - r*65;
        sin[i] = (r < 64 && c < 64) ? xf[r*64+c] : 0.f;
    }
    if (threadIdx.x < 144) sw[threadIdx.x] = w[threadIdx.x];
    if (threadIdx.x < 16)  sb[threadIdx.x] = b[threadIdx.x];
    __syncthreads();
    int xg = threadIdx.x & 3;
    int oy = (threadIdx.x >> 2) & 31;
    int cq = threadIdx.x >> 7;
    u64 acc2[4][4];
    #pragma unroll
    for (int c = 0; c < 4; c++) {
        float bb = sb[cq*4+c];
        u64 bp = pk2(bb, bb);
        #pragma unroll
        for (int p = 0; p < 4; p++) acc2[c][p] = bp;
    }
    int i0 = oy*2, j0 = xg*16;
    #pragma unroll
    for (int ky = 0; ky < 3; ky++) {
        const float* rp = sin + (i0+ky)*65 + j0;
        float r[17];
        #pragma unroll
        for (int t = 0; t < 17; t++) r[t] = rp[t];
        u64 pr[12];
        #pragma unroll
        for (int p = 0; p < 4; p++)
            #pragma unroll
            for (int l = 0; l < 3; l++)
                pr[p*3+l] = pk2(r[p*4+l], r[p*4+l+2]);
        #pragma unroll
        for (int c = 0; c < 4; c++) {
            const float* wp = sw + (cq*4+c)*9 + ky*3;
            u64 wd0 = pk2(wp[0], wp[0]);
            u64 wd1 = pk2(wp[1], wp[1]);
            u64 wd2 = pk2(wp[2], wp[2]);
            #pragma unroll
            for (int p = 0; p < 4; p++) {
                acc2[c][p] = ffma2(pr[p*3+0], wd0, acc2[c][p]);
                acc2[c][p] = ffma2(pr[p*3+1], wd1, acc2[c][p]);
                acc2[c][p] = ffma2(pr[p*3+2], wd2, acc2[c][p]);
            }
        }
    }
    #pragma unroll
    for (int c = 0; c < 4; c++)
        #pragma unroll
        for (int p = 0; p < 4; p++) {
            float2 v = upk2(acc2[c][p]);
            float2 o = make_float2(fmaxf(v.x, 0.f), fmaxf(v.y, 0.f));
            *(float2*)&out[((size_t)f*16 + cq*4+c)*1024 + oy*32 + xg*8 + 2*p] = o;
        }
}

__global__ __launch_bounds__(256) void conv2_kernel(const float* __restrict__ in,
                             const float* __restrict__ w,
                             const float* __restrict__ b,
                             float* __restrict__ out)
{
    __shared__ __align__(16) float sin[8*33*34];
    __shared__ __align__(16) float sw[2304];
    int f = blockIdx.x;
    int tid = threadIdx.x;
    int cg  = tid >> 5;
    int lane = tid & 31;
    int oy = lane >> 1;
    int xh = lane & 1;
    u64 acc2[4][4];
    #pragma unroll
    for (int c = 0; c < 4; c++) {
        float bb = __ldg(&b[cg*4+c]);
        u64 bp = pk2(bb, bb);
        #pragma unroll
        for (int p = 0; p < 4; p++) acc2[c][p] = bp;
    }
    #pragma unroll 1
    for (int pass = 0; pass < 2; pass++) {
        int ci0 = pass*8;
        __syncthreads();
        for (int idx = tid; idx < 8*33*33; idx += 256) {
            int ci = idx / 1089;
            int rem = idx - ci*1089;
            int i = rem / 33, j = rem - i*33;
            sin[ci*1122 + i*34 + j] = (i < 32 && j < 32)
                ? in[(size_t)f*16384 + (ci0+ci)*1024 + i*32 + j] : 0.f;
        }
        for (int idx = tid; idx < 2304; idx += 256) {
            int co = idx / 72;
            int rem = idx - co*72;
            int ci_l = rem / 9, k = rem - ci_l*9;
            sw[idx] = w[(co*16 + ci0 + ci_l)*9 + k];
        }
        __syncthreads();
        #pragma unroll 1
        for (int ci = 0; ci < 8; ci++) {
            const float* base = sin + ci*1122 + (2*oy)*34 + xh*16;
            #pragma unroll
            for (int row = 0; row < 3; row++) {
                const float* rp = base + row*34;
                float r[17];
                #pragma unroll
                for (int t = 0; t < 17; t++) r[t] = rp[t];
                u64 pr[12];
                #pragma unroll
                for (int p = 0; p < 4; p++)
                    #pragma unroll
                    for (int l = 0; l < 3; l++)
                        pr[p*3+l] = pk2(r[p*4+l], r[p*4+l+2]);
                #pragma unroll
                for (int c = 0; c < 4; c++) {
                    const float* wp = sw + (cg*4+c)*72 + ci*9 + row*3;
                    u64 wd0 = pk2(wp[0], wp[0]);
                    u64 wd1 = pk2(wp[1], wp[1]);
                    u64 wd2 = pk2(wp[2], wp[2]);
                    #pragma unroll
                    for (int p = 0; p < 4; p++) {
                        acc2[c][p] = ffma2(pr[p*3+0], wd0, acc2[c][p]);
                        acc2[c][p] = ffma2(pr[p*3+1], wd1, acc2[c][p]);
                        acc2[c][p] = ffma2(pr[p*3+2], wd2, acc2[c][p]);
                    }
                }
            }
        }
    }
    #pragma unroll
    for (int c = 0; c < 4; c++)
        #pragma unroll
        for (int p = 0; p < 4; p++) {
            float2 v = upk2(acc2[c][p]);
            float2 o = make_float2(fmaxf(v.x, 0.f), fmaxf(v.y, 0.f));
            *(float2*)&out[((size_t)f*32 + cg*4+c)*256 + oy*16 + xh*8 + 2*p] = o;
        }
}

// conv3 + relu + global avg pool + fc (32->256) fused; 2 frames per block
__global__ __launch_bounds__(256) void conv3poolfc_kernel(const float* __restrict__ in,
                                 const float* __restrict__ w,
                                 const float* __restrict__ b,
                                 const float* __restrict__ fcw,
                                 const float* __restrict__ fcb,
                                 float* __restrict__ h)
{
    __shared__ __align__(16) float sin[2*8*17*18];
    __shared__ __align__(16) float sw[32*8*9];
    __shared__ __align__(16) float zsh[64];
    int f0 = blockIdx.x * 2;
    int tid = threadIdx.x;
    int fr = tid >> 7;
    int t  = tid & 127;
    int cg = t >> 4;
    int oy = (t >> 1) & 7;
    int xh = t & 1;
    u64 acc2[4][2];
    #pragma unroll
    for (int c = 0; c < 4; c++) {
        float bb = __ldg(&b[cg*4+c]);
        u64 bp = pk2(bb, bb);
        acc2[c][0] = bp; acc2[c][1] = bp;
    }
    #pragma unroll 1
    for (int pass = 0; pass < 4; pass++) {
        int ci0 = pass*8;
        __syncthreads();
        for (int idx = tid; idx < 2*8*17*17; idx += 256) {
            int fr2 = idx / 2312;
            int rem = idx - fr2*2312;
            int ci = rem / 289;
            int r2 = rem - ci*289;
            int i = r2 / 17, j = r2 - i*17;
            sin[fr2*2448 + ci*306 + i*18 + j] = (i < 16 && j < 16)
                ? in[(size_t)(f0+fr2)*8192 + (ci0+ci)*256 + i*16 + j] : 0.f;
        }
        for (int idx = tid; idx < 2304; idx += 256) {
            int co = idx / 72;
            int rem = idx - co*72;
            int ci_l = rem / 9, k = rem - ci_l*9;
            sw[idx] = w[(co*32 + ci0 + ci_l)*9 + k];
        }
        __syncthreads();
        #pragma unroll 1
        for (int ci = 0; ci < 8; ci++) {
            const float* base = sin + fr*2448 + ci*306 + (2*oy)*18 + xh*8;
            #pragma unroll
            for (int row = 0; row < 3; row++) {
                const float* rp = base + row*18;
                float r[9];
                #pragma unroll
                for (int q = 0; q < 9; q++) r[q] = rp[q];
                u64 pr[6];
                #pragma unroll
                for (int p = 0; p < 2; p++)
                    #pragma unroll
                    for (int l = 0; l < 3; l++)
                        pr[p*3+l] = pk2(r[p*4+l], r[p*4+l+2]);
                #pragma unroll
                for (int c = 0; c < 4; c++) {
                    const float* wp = sw + (cg*4+c)*72 + ci*9 + row*3;
                    u64 wd0 = pk2(wp[0], wp[0]);
                    u64 wd1 = pk2(wp[1], wp[1]);
                    u64 wd2 = pk2(wp[2], wp[2]);
                    #pragma unroll
                    for (int p = 0; p < 2; p++) {
                        acc2[c][p] = ffma2(pr[p*3+0], wd0, acc2[c][p]);
                        acc2[c][p] = ffma2(pr[p*3+1], wd1, acc2[c][p]);
                        acc2[c][p] = ffma2(pr[p*3+2], wd2, acc2[c][p]);
                    }
                }
            }
        }
    }
    #pragma unroll
    for (int c = 0; c < 4; c++) {
        float2 v0 = upk2(acc2[c][0]), v1 = upk2(acc2[c][1]);
        float s = fmaxf(v0.x,0.f) + fmaxf(v0.y,0.f) + fmaxf(v1.x,0.f) + fmaxf(v1.y,0.f);
        #pragma unroll
        for (int o = 8; o > 0; o >>= 1) s += __shfl_down_sync(0xffffffffu, s, o, 16);
        if (oy == 0 && xh == 0) zsh[fr*32 + cg*4 + c] = s * (1.f/64.f);
    }
    __syncthreads();
    int fr2 = tid >> 7;
    int j = tid & 127;
    const float* zz = zsh + fr2*32;
    float a0 = fcb[j], a1 = fcb[j+128];
    const float4* w0p = (const float4*)(fcw + j*32);
    const float4* w1p = (const float4*)(fcw + (j+128)*32);
    #pragma unroll
    for (int k = 0; k < 8; k++) {
        float4 wv0 = w0p[k], wv1 = w1p[k];
        const float* zk = zz + k*4;
        a0 = fmaf(zk[0],wv0.x,fmaf(zk[1],wv0.y,fmaf(zk[2],wv0.z,fmaf(zk[3],wv0.w,a0))));
        a1 = fmaf(zk[0],wv1.x,fmaf(zk[1],wv1.y,fmaf(zk[2],wv1.z,fmaf(zk[3],wv1.w,a1))));
    }
    h[(size_t)(f0+fr2)*256 + j] = a0;
    h[(size_t)(f0+fr2)*256 + j + 128] = a1;
}

// =====================================================================
// Mamba pieces
// =====================================================================
__global__ __launch_bounds__(256) void rmsnorm_kernel(const float* __restrict__ x,
                               const float* __restrict__ w,
                               float* __restrict__ out)
{
    int tok = blockIdx.x*8 + (threadIdx.x >> 5);
    int lane = threadIdx.x & 31;
    const float4* xr = (const float4*)(x + (size_t)tok*256);
    float4 v0 = xr[lane*2], v1 = xr[lane*2+1];
    float ss = v0.x*v0.x + v0.y*v0.y + v0.z*v0.z + v0.w*v0.w
             + v1.x*v1.x + v1.y*v1.y + v1.z*v1.z + v1.w*v1.w;
    #pragma unroll
    for (int o = 16; o > 0; o >>= 1) ss += __shfl_xor_sync(0xffffffffu, ss, o);
    float scale = rsqrtf(ss * (1.f/256.f) + 1e-5f);
    const float4* wr = (const float4*)w;
    float4 w0 = wr[lane*2], w1 = wr[lane*2+1];
    float4 o0, o1;
    o0.x = v0.x*scale*w0.x; o0.y = v0.y*scale*w0.y; o0.z = v0.z*scale*w0.z; o0.w = v0.w*scale*w0.w;
    o1.x = v1.x*scale*w1.x; o1.y = v1.y*scale*w1.y; o1.z = v1.z*scale*w1.z; o1.w = v1.w*scale*w1.w;
    float4* outr = (float4*)(out + (size_t)tok*256);
    outr[lane*2] = o0; outr[lane*2+1] = o1;
}

// tile 64x64, 256 thr, 4x4 micro, f32x2, Kt=32, global-load prefetch
__global__ __launch_bounds__(256) void gemm64_kernel(const float* __restrict__ A,
                              const float* __restrict__ W,
                              float* __restrict__ C,
                              int M, int N, int K)
{
    __shared__ __align__(16) float As[32][68];
    __shared__ __align__(16) float Ws[32][68];
    int bm = blockIdx.y * 64;
    int bn = blockIdx.x * 64;
    int tid = threadIdx.x;
    int tx = tid & 15, ty = tid >> 4;
    u64 acc[4][2];
    #pragma unroll
    for (int i = 0; i < 4; i++) { acc[i][0] = 0ull; acc[i][1] = 0ull; }
    // loader mapping: 2 float4 per matrix per thread
    int r0 = tid >> 3, c0 = tid & 7;           // idx 0..255 -> r 0..31, c 0..7
    int r1 = (tid + 256) >> 3, c1 = tid & 7;   // idx 256..511 -> r 32..63
    const float* Ap0 = &A[(size_t)(bm+r0)*K + c0*4];
    const float* Ap1 = &A[(size_t)(bm+r1)*K + c1*4];
    const float* Wp0 = &W[(size_t)(bn+r0)*K + c0*4];
    const float* Wp1 = &W[(size_t)(bn+r1)*K + c1*4];
    float4 va0 = *(const float4*)Ap0, va1 = *(const float4*)Ap1;
    float4 vw0 = *(const float4*)Wp0, vw1 = *(const float4*)Wp1;
    for (int k0 = 0; k0 < K; k0 += 32) {
        #pragma unroll
        for (int i = 0; i < 4; i++) {
            As[c0*4+i][r0] = (&va0.x)[i];
            As[c1*4+i][r1] = (&va1.x)[i];
            Ws[c0*4+i][r0] = (&vw0.x)[i];
            Ws[c1*4+i][r1] = (&vw1.x)[i];
        }
        __syncthreads();
        if (k0 + 32 < K) {
            va0 = *(const float4*)(Ap0 + k0 + 32);
            va1 = *(const float4*)(Ap1 + k0 + 32);
            vw0 = *(const float4*)(Wp0 + k0 + 32);
            vw1 = *(const float4*)(Wp1 + k0 + 32);
        }
        #pragma unroll
        for (int k = 0; k < 32; k++) {
            float4 a0 = *(const float4*)&As[k][ty*4];
            F4U b0;
            b0.f = *(const float4*)&Ws[k][tx*4];
            u64 bp0 = b0.u[0], bp1 = b0.u[1];
            float av[4] = {a0.x, a0.y, a0.z, a0.w};
            #pragma unroll
            for (int i = 0; i < 4; i++) {
                u64 ad = pk2(av[i], av[i]);
                acc[i][0] = ffma2(ad, bp0, acc[i][0]);
                acc[i][1] = ffma2(ad, bp1, acc[i][1]);
            }
        }
        __syncthreads();
    }
    #pragma unroll
    for (int i = 0; i < 4; i++) {
        int m = bm + ty*4 + i;
        float2 v0 = upk2(acc[i][0]), v1 = upk2(acc[i][1]);
        *(float4*)&C[(size_t)m*N + bn + tx*4] = make_float4(v0.x, v0.y, v1.x, v1.y);
    }
}

// tile 32x64, 256 thr, 2x4 micro, f32x2, Kt=32, prefetch.
// EPI: 1 accumulate, 2 bias+gelu
template<int EPI>
__global__ __launch_bounds__(256) void gemm32x64_kernel(const float* __restrict__ A,
                              const float* __restrict__ W,
                              const float* __restrict__ bias,
                              float* __restrict__ C,
                              int M, int N, int K)
{
    __shared__ __align__(16) float As[32][36];
    __shared__ __align__(16) float Ws[32][68];
    int bm = blockIdx.y * 32;
    int bn = blockIdx.x * 64;
    int tid = threadIdx.x;
    int tx = tid & 15, ty = tid >> 4;
    u64 acc[2][2];
    acc[0][0]=0ull; acc[0][1]=0ull; acc[1][0]=0ull; acc[1][1]=0ull;
    // A: 32x32 = 256 float4, 1 per thread. W: 64x32 = 512 float4, 2 per thread.
    int ra = tid >> 3, ca = tid & 7;
    int rw0 = tid >> 3, cw0 = tid & 7;
    int rw1 = (tid + 256) >> 3, cw1 = tid & 7;
    const float* Ap  = &A[(size_t)(bm+ra)*K + ca*4];
    const float* Wp0 = &W[(size_t)(bn+rw0)*K + cw0*4];
    const float* Wp1 = &W[(size_t)(bn+rw1)*K + cw1*4];
    float4 va  = *(const float4*)Ap;
    float4 vw0 = *(const float4*)Wp0;
    float4 vw1 = *(const float4*)Wp1;
    for (int k0 = 0; k0 < K; k0 += 32) {
        #pragma unroll
        for (int i = 0; i < 4; i++) {
            As[ca*4+i][ra]   = (&va.x)[i];
            Ws[cw0*4+i][rw0] = (&vw0.x)[i];
            Ws[cw1*4+i][rw1] = (&vw1.x)[i];
        }
        __syncthreads();
        if (k0 + 32 < K) {
            va  = *(const float4*)(Ap + k0 + 32);
            vw0 = *(const float4*)(Wp0 + k0 + 32);
            vw1 = *(const float4*)(Wp1 + k0 + 32);
        }
        #pragma unroll
        for (int k = 0; k < 32; k++) {
            float2 a0 = *(const float2*)&As[k][ty*2];
            F4U b0;
            b0.f = *(const float4*)&Ws[k][tx*4];
            u64 bp0 = b0.u[0], bp1 = b0.u[1];
            u64 ad0 = pk2(a0.x, a0.x);
            u64 ad1 = pk2(a0.y, a0.y);
            acc[0][0] = ffma2(ad0, bp0, acc[0][0]);
            acc[0][1] = ffma2(ad0, bp1, acc[0][1]);
            acc[1][0] = ffma2(ad1, bp0, acc[1][0]);
            acc[1][1] = ffma2(ad1, bp1, acc[1][1]);
        }
        __syncthreads();
    }
    #pragma unroll
    for (int i = 0; i < 2; i++) {
        int m = bm + ty*2 + i;
        float2 v0 = upk2(acc[i][0]), v1 = upk2(acc[i][1]);
        float vals[4] = {v0.x, v0.y, v1.x, v1.y};
        size_t base = (size_t)m*N + bn + tx*4;
        if (EPI == 1) {
            float4 old = *(float4*)&C[base];
            old.x += vals[0]; old.y += vals[1]; old.z += vals[2]; old.w += vals[3];
            *(float4*)&C[base] = old;
        } else {
            float4 o;
            float* op = &o.x;
            #pragma unroll
            for (int j = 0; j < 4; j++) {
                float v = vals[j] + bias[bn + tx*4 + j];
                float v3 = v*v*v;
                op[j] = 0.5f * v * (1.f + tanhf(0.7978845608028654f * (v + 0.044715f*v3)));
            }
            *(float4*)&C[base] = o;
        }
    }
}

// Fused conv1d+silu + x_proj + dt_proj: per block 16 tokens.
#define SXIDX(tok, k) ((tok)*512 + (((k) + (tok)*4) & 511))
__global__ __launch_bounds__(256) void xproj_fused_kernel(
    const float* __restrict__ xz,
    const float* __restrict__ cw,
    const float* __restrict__ cb,
    const float* __restrict__ xpw,
    const float* __restrict__ dpw,
    const float* __restrict__ dpb,
    float2* __restrict__ bc,
    float2* __restrict__ du)
{
    __shared__ __align__(16) float sx[16*512];
    __shared__ __align__(16) float buf[48*68];
    __shared__ __align__(16) float sdt[16*16];
    int tok0 = blockIdx.x * 16;
    int tid = threadIdx.x;

    // ---- conv1d + silu from xz into sx ----
    for (int idx = tid; idx < 2048; idx += 256) {
        int e = idx >> 2, k = idx & 3;
        buf[k*512 + e] = cw[idx];
    }
    for (int idx = tid; idx < 512; idx += 256) buf[2048 + idx] = cb[idx];
    __syncthreads();
    int tl0 = tok0 & 255;
    #pragma unroll 1
    for (int s = 0; s < 8; s++) {
        int q = tid + s*256;
        int t = q >> 7;
        int e = (q & 127)*4;
        float4 acc = *(const float4*)&buf[2048 + e];
        #pragma unroll
        for (int k = 0; k < 4; k++) {
            if (tl0 + t - 3 + k >= 0) {
                float4 xv = *(const float4*)&xz[(size_t)(tok0 + t - 3 + k)*1024 + e];
                float4 wv = *(const float4*)&buf[k*512 + e];
                acc.x = fmaf(xv.x, wv.x, acc.x);
                acc.y = fmaf(xv.y, wv.y, acc.y);
                acc.z = fmaf(xv.z, wv.z, acc.z);
                acc.w = fmaf(xv.w, wv.w, acc.w);
            }
        }
        acc.x = acc.x / (1.f + __expf(-acc.x));
        acc.y = acc.y / (1.f + __expf(-acc.y));
        acc.z = acc.z / (1.f + __expf(-acc.z));
        acc.w = acc.w / (1.f + __expf(-acc.w));
        *(float4*)&sx[SXIDX(t, e)] = acc;
    }

    // ---- Phase A: dbc = xin . xpw^T (float4 k-unroll) ----
    int tg = tid & 15;
    int jg = tid >> 4;
    int rot = tg*4;
    const float* sxr = sx + tg*512;
    float acc0 = 0.f, acc1 = 0.f, acc2 = 0.f;
    #pragma unroll 1
    for (int kc = 0; kc < 8; kc++) {
        int k0 = kc*64;
        __syncthreads();
        #pragma unroll
        for (int s = 0; s < 3; s++) {
            int q = tid + s*256;
            int r = q >> 4, c = q & 15;
            float4 v = *(const float4*)&xpw[(size_t)r*512 + k0 + c*4];
            float* dst = buf + r*68 + c*4;
            dst[0]=v.x; dst[1]=v.y; dst[2]=v.z; dst[3]=v.w;
        }
        __syncthreads();
        const float* w0 = buf + (jg*3+0)*68;
        const float* w1 = buf + (jg*3+1)*68;
        const float* w2 = buf + (jg*3+2)*68;
        #pragma unroll
        for (int k4 = 0; k4 < 16; k4++) {
            int kk = (k0 + k4*4 + rot) & 511;
            float4 xv = *(const float4*)&sxr[kk];
            float4 a4 = *(const float4*)&w0[k4*4];
            float4 b4 = *(const float4*)&w1[k4*4];
            float4 c4 = *(const float4*)&w2[k4*4];
            acc0 = fmaf(xv.x,a4.x, fmaf(xv.y,a4.y, fmaf(xv.z,a4.z, fmaf(xv.w,a4.w, acc0))));
            acc1 = fmaf(xv.x,b4.x, fmaf(xv.y,b4.y, fmaf(xv.z,b4.z, fmaf(xv.w,b4.w, acc1))));
            acc2 = fmaf(xv.x,c4.x, fmaf(xv.y,c4.y, fmaf(xv.z,c4.z, fmaf(xv.w,c4.w, acc2))));
        }
    }
    {
        float av[3] = {acc0, acc1, acc2};
        #pragma unroll
        for (int jj = 0; jj < 3; jj++) {
            int j = jg*3 + jj;
            float v = av[jj];
            int tok = tok0 + tg;
            if (j < 16)       sdt[tg*16 + j] = v;
            else if (j < 32)  bc[tok*16 + (j-16)].x = v;
            else              bc[tok*16 + (j-32)].y = v;
        }
    }

    // ---- Phase B ----
    #pragma unroll 1
    for (int ec = 0; ec < 4; ec++) {
        int e0 = ec*128;
        __syncthreads();
        #pragma unroll
        for (int s = 0; s < 2; s++) {
            int q = tid + s*256;
            int r = q >> 2, c = q & 3;
            float4 v = *(const float4*)&dpw[(size_t)(e0+r)*16 + c*4];
            float* dst = buf + r*16 + c*4;
            dst[0]=v.x; dst[1]=v.y; dst[2]=v.z; dst[3]=v.w;
        }
        __syncthreads();
        #pragma unroll 1
        for (int s = 0; s < 8; s++) {
            int idx = tid + s*256;
            int e_l = idx & 127;
            int tok = idx >> 7;
            int e = e0 + e_l;
            const float* dr = sdt + tok*16;
            const float* wr = buf + e_l*16;
            float a = dpb[e];
            #pragma unroll
            for (int k = 0; k < 16; k++) a = fmaf(dr[k], wr[k], a);
            float sp = (a > 20.f) ? a : log1pf(expf(a));
            float u = sx[SXIDX(tok, e)];
            du[(size_t)(tok0+tok)*512 + e] = make_float2(sp, u);
        }
    }
}

// Selective scan: chunked register prefetch + pipelined shfl reduction
__global__ __launch_bounds__(256) void scan_kernel(const float2* __restrict__ du,
                            const float* __restrict__ xz,
                            const float2* __restrict__ bc,
                            const float* __restrict__ A_log,
                            const float* __restrict__ Dp,
                            float* __restrict__ yout)
{
    int tid = blockIdx.x * blockDim.x + threadIdx.x;
    int ch = tid >> 4;
    int n = tid & 15;
    int b = ch >> 9;
    int e = ch & 511;
    float A  = -expf(A_log[e*16 + n]);
    float Dv = Dp[e];
    const float2* duP = du + (size_t)(b*256)*512 + e;
    const float2* bcP = bc + (size_t)(b*256)*16 + n;
    const float*  zP  = xz + (size_t)(b*256)*1024 + 512 + e;
    float* yP = yout + (size_t)(b*256)*512 + e;

    float2 dv[2][8], bv[2][8];
    float  zv[2][8];
    #pragma unroll
    for (int i = 0; i < 8; i++) {
        dv[0][i] = duP[i*512];
        bv[0][i] = bcP[i*16];
    }
    if (n == 0) {
        #pragma unroll
        for (int i = 0; i < 8; i++) zv[0][i] = zP[i*1024];
    }
    float h = 0.f;
    int buf = 0;
    #pragma unroll 1
    for (int c = 0; c < 32; c++) {
        int nb = buf ^ 1;
        if (c < 31) {
            int t1 = c*8 + 8;
            #pragma unroll
            for (int i = 0; i < 8; i++) {
                dv[nb][i] = duP[(t1+i)*512];
                bv[nb][i] = bcP[(t1+i)*16];
            }
            if (n == 0) {
                #pragma unroll
                for (int i = 0; i < 8; i++) zv[nb][i] = zP[(size_t)(t1+i)*1024];
            }
        }
        float part[8];
        #pragma unroll
        for (int i = 0; i < 8; i++) {
            float2 duv = dv[buf][i];
            float2 bcv = bv[buf][i];
            float dA = __expf(duv.x * A);
            h = fmaf(h, dA, duv.x * bcv.x * duv.y);
            part[i] = h * bcv.y;
        }
        #pragma unroll
        for (int o = 8; o > 0; o >>= 1) {
            #pragma unroll
            for (int i = 0; i < 8; i++)
                part[i] += __shfl_down_sync(0xffffffffu, part[i], o, 16);
        }
        if (n == 0) {
            #pragma unroll
            for (int i = 0; i < 8; i++) {
                float z = zv[buf][i];
                float yy = part[i] + dv[buf][i].y * Dv;
                yP[(size_t)(c*8+i)*512] = yy * (z / (1.f + __expf(-z)));
            }
        }
        buf = nb;
    }
}

// =====================================================================
// Head tail
// =====================================================================
__global__ __launch_bounds__(256) void head2_kernel(const float* __restrict__ hh,
                             const float* __restrict__ w,
                             const float* __restrict__ b,
                             float* __restrict__ logits)
{
    int wid = (blockIdx.x * blockDim.x + threadIdx.x) >> 5;
    int lane = threadIdx.x & 31;
    const float* xr = hh + (size_t)wid*64;
    float acc = fmaf(xr[lane], w[lane], xr[lane+32]*w[lane+32]);
    #pragma unroll
    for (int o = 16; o > 0; o >>= 1) acc += __shfl_down_sync(0xffffffffu, acc, o);
    if (lane == 0) logits[wid] = acc + b[0];
}

__global__ __launch_bounds__(256) void softmax_kernel(const float* __restrict__ logits,
                               float* __restrict__ out)
{
    int b = blockIdx.x;
    int t = threadIdx.x;
    float v = logits[b*256 + t];
    __shared__ float red[8];
    __shared__ float sM, sS;
    float m = v;
    #pragma unroll
    for (int o = 16; o > 0; o >>= 1) m = fmaxf(m, __shfl_xor_sync(0xffffffffu, m, o));
    if ((t & 31) == 0) red[t >> 5] = m;
    __syncthreads();
    if (t < 8) {
        float mm = red[t];
        #pragma unroll
        for (int o = 4; o > 0; o >>= 1) mm = fmaxf(mm, __shfl_xor_sync(0xffu, mm, o, 8));
        if (t == 0) sM = mm;
    }
    __syncthreads();
    float e = expf(v - sM);
    float s = e;
    #pragma unroll
    for (int o = 16; o > 0; o >>= 1) s += __shfl_xor_sync(0xffffffffu, s, o);
    __syncthreads();
    if ((t & 31) == 0) red[t >> 5] = s;
    __syncthreads();
    if (t < 8) {
        float ss2 = red[t];
        #pragma unroll
        for (int o = 4; o > 0; o >>= 1) ss2 += __shfl_xor_sync(0xffu, ss2, o, 8);
        if (t == 0) sS = ss2;
    }
    __syncthreads();
    out[b*256 + t] = (t == 0) ? 0.f : e / sS;
}

// =====================================================================
// Launcher
// =====================================================================
extern "C" void kernel_launch(void* const* d_in, const int* in_sizes, int n_in,
                              void* d_out, int out_size)
{
    (void)in_sizes; (void)n_in; (void)out_size;
    const float* x        = (const float*)d_in[0];
    const float* cnn_w1   = (const float*)d_in[1];
    const float* cnn_b1   = (const float*)d_in[2];
    const float* cnn_w2   = (const float*)d_in[3];
    const float* cnn_b2   = (const float*)d_in[4];
    const float* cnn_w3   = (const float*)d_in[5];
    const float* cnn_b3   = (const float*)d_in[6];
    const float* fc_w     = (const float*)d_in[7];
    const float* fc_b     = (const float*)d_in[8];
    const float* norm_w   = (const float*)d_in[9];
    const float* in_proj_w= (const float*)d_in[10];
    const float* conv1d_w = (const float*)d_in[11];
    const float* conv1d_b = (const float*)d_in[12];
    const float* x_proj_w = (const float*)d_in[13];
    const float* dt_proj_w= (const float*)d_in[14];
    const float* dt_proj_b= (const float*)d_in[15];
    const float* A_log    = (const float*)d_in[16];
    const float* Dp       = (const float*)d_in[17];
    const float* out_proj_w=(const float*)d_in[18];
    const float* norm_f_w = (const float*)d_in[19];
    const float* head_w1  = (const float*)d_in[20];
    const float* head_b1  = (const float*)d_in[21];
    const float* head_w2  = (const float*)d_in[22];
    const float* head_b2  = (const float*)d_in[23];
    float* out = (float*)d_out;

    float *f1, *f2, *h, *xn, *xz, *y, *hh, *logits;
    float2 *bc, *du;
    cudaGetSymbolAddress((void**)&f1, g_f1);
    cudaGetSymbolAddress((void**)&f2, g_f2);
    cudaGetSymbolAddress((void**)&h,  g_h);
    cudaGetSymbolAddress((void**)&xn, g_xn);
    cudaGetSymbolAddress((void**)&xz, g_xz);
    cudaGetSymbolAddress((void**)&bc, g_bc);
    cudaGetSymbolAddress((void**)&du, g_du);
    cudaGetSymbolAddress((void**)&y,  g_y);
    cudaGetSymbolAddress((void**)&hh, g_hh);
    cudaGetSymbolAddress((void**)&logits, g_logits);

    // --- CNN encoder ---
    conv1_kernel<<<2048, 512>>>(x, cnn_w1, cnn_b1, f1);
    conv2_kernel<<<2048, 256>>>(f1, cnn_w2, cnn_b2, f2);
    conv3poolfc_kernel<<<1024, 256>>>(f2, cnn_w3, cnn_b3, fc_w, fc_b, h);

    // --- Mamba layers ---
    for (int l = 0; l < 6; l++) {
        const float* nw  = norm_w     + (size_t)l*DM;
        const float* ipw = in_proj_w  + (size_t)l*2*DI*DM;
        const float* cw  = conv1d_w   + (size_t)l*DI*4;
        const float* cb  = conv1d_b   + (size_t)l*DI;
        const float* xpw = x_proj_w   + (size_t)l*48*DI;
        const float* dpw = dt_proj_w  + (size_t)l*DI*DTR;
        const float* dpb = dt_proj_b  + (size_t)l*DI;
        const float* al  = A_log      + (size_t)l*DI*DS;
        const float* dv  = Dp         + (size_t)l*DI;
        const float* opw = out_proj_w + (size_t)l*DM*DI;

        rmsnorm_kernel<<<256, 256>>>(h, nw, xn);
        gemm64_kernel<<<dim3(16, 32), 256>>>(xn, ipw, xz, BT, 1024, 256);
        xproj_fused_kernel<<<128, 256>>>(xz, cw, cb, xpw, dpw, dpb, bc, du);
        scan_kernel<<<BATCH*DI*DS/256, 256>>>(du, xz, bc, al, dv, y);
        gemm32x64_kernel<1><<<dim3(4, 64), 256>>>(y, opw, nullptr, h, BT, 256, 512);
    }

    // --- Head ---
    rmsnorm_kernel<<<256, 256>>>(h, norm_f_w, xn);
    gemm32x64_kernel<2><<<dim3(1, 64), 256>>>(xn, head_w1, head_b1, hh, BT, 64, 256);
    head2_kernel<<<BT*32/256, 256>>>(hh, head_w2, head_b2, logits);
    softmax_kernel<<<BATCH, 256>>>(logits, out);
}

// round 11
// speedup vs baseline: 1.4399x; 1.0213x over previous
#include <cuda_runtime.h>
#include <math.h>

// ---- problem constants ----
#define BATCH   8
#define TT      256
#define BT      2048          // BATCH*TT
#define DM      256           // d_model
#define DI      512           // d_inner
#define DS      16            // d_state
#define DTR     16            // dt_rank

typedef unsigned long long u64;

__device__ __forceinline__ u64 pk2(float lo, float hi) {
    u64 d;
    asm("mov.b64 %0, {%1, %2};" : "=l"(d)
        : "r"(__float_as_uint(lo)), "r"(__float_as_uint(hi)));
    return d;
}
__device__ __forceinline__ u64 ffma2(u64 a, u64 b, u64 c) {
    u64 d;
    asm("fma.rn.f32x2 %0, %1, %2, %3;" : "=l"(d) : "l"(a), "l"(b), "l"(c));
    return d;
}
__device__ __forceinline__ float2 upk2(u64 v) {
    unsigned lo, hi;
    asm("mov.b64 {%0, %1}, %2;" : "=r"(lo), "=r"(hi) : "l"(v));
    return make_float2(__uint_as_float(lo), __uint_as_float(hi));
}
union F4U { float4 f; u64 u[2]; };

// ---- scratch ----
__device__ float  g_f1[2048*16*32*32];
__device__ float  g_f2[2048*32*16*16];
__device__ float  g_h [BT*DM];
__device__ float  g_xn[BT*DM];
__device__ float  g_xz[BT*2*DI];
__device__ float2 g_bc[BT*DS];
__device__ float2 g_du[BT*DI];
__device__ float  g_y [BT*DI];
__device__ float  g_hh[BT*64];
__device__ float  g_logits[BT];

// =====================================================================
// CNN (round-7 measured-good versions)
// =====================================================================
__global__ __launch_bounds__(512) void conv1_kernel(const float* __restrict__ x,
                             const float* __restrict__ w,
                             const float* __restrict__ b,
                             float* __restrict__ out)
{
    __shared__ __align__(16) float sin[65*65];
    __shared__ __align__(16) float sw[144];
    __shared__ __align__(16) float sb[16];
    int f = blockIdx.x;
    const float* xf = x + (size_t)f*4096;
    for (int i = threadIdx.x; i < 65*65; i += 512) {
        int r = i / 65, c = i - r*65;
        sin[i] = (r < 64 && c < 64) ? xf[r*64+c] : 0.f;
    }
    if (threadIdx.x < 144) sw[threadIdx.x] = w[threadIdx.x];
    if (threadIdx.x < 16)  sb[threadIdx.x] = b[threadIdx.x];
    __syncthreads();
    int xg = threadIdx.x & 3;
    int oy = (threadIdx.x >> 2) & 31;
    int cq = threadIdx.x >> 7;
    u64 acc2[4][4];
    #pragma unroll
    for (int c = 0; c < 4; c++) {
        float bb = sb[cq*4+c];
        u64 bp = pk2(bb, bb);
        #pragma unroll
        for (int p = 0; p < 4; p++) acc2[c][p] = bp;
    }
    int i0 = oy*2, j0 = xg*16;
    #pragma unroll
    for (int ky = 0; ky < 3; ky++) {
        const float* rp = sin + (i0+ky)*65 + j0;
        float r[17];
        #pragma unroll
        for (int t = 0; t < 17; t++) r[t] = rp[t];
        u64 pr[12];
        #pragma unroll
        for (int p = 0; p < 4; p++)
            #pragma unroll
            for (int l = 0; l < 3; l++)
                pr[p*3+l] = pk2(r[p*4+l], r[p*4+l+2]);
        #pragma unroll
        for (int c = 0; c < 4; c++) {
            const float* wp = sw + (cq*4+c)*9 + ky*3;
            u64 wd0 = pk2(wp[0], wp[0]);
            u64 wd1 = pk2(wp[1], wp[1]);
            u64 wd2 = pk2(wp[2], wp[2]);
            #pragma unroll
            for (int p = 0; p < 4; p++) {
                acc2[c][p] = ffma2(pr[p*3+0], wd0, acc2[c][p]);
                acc2[c][p] = ffma2(pr[p*3+1], wd1, acc2[c][p]);
                acc2[c][p] = ffma2(pr[p*3+2], wd2, acc2[c][p]);
            }
        }
    }
    #pragma unroll
    for (int c = 0; c < 4; c++)
        #pragma unroll
        for (int p = 0; p < 4; p++) {
            float2 v = upk2(acc2[c][p]);
            float2 o = make_float2(fmaxf(v.x, 0.f), fmaxf(v.y, 0.f));
            *(float2*)&out[((size_t)f*16 + cq*4+c)*1024 + oy*32 + xg*8 + 2*p] = o;
        }
}

__global__ __launch_bounds__(256) void conv2_kernel(const float* __restrict__ in,
                             const float* __restrict__ w,
                             const float* __restrict__ b,
                             float* __restrict__ out)
{
    __shared__ __align__(16) float sin[8*33*34];
    __shared__ __align__(16) float sw[2304];
    int f = blockIdx.x;
    int tid = threadIdx.x;
    int cg  = tid >> 5;
    int lane = tid & 31;
    int oy = lane >> 1;
    int xh = lane & 1;
    u64 acc2[4][4];
    #pragma unroll
    for (int c = 0; c < 4; c++) {
        float bb = __ldg(&b[cg*4+c]);
        u64 bp = pk2(bb, bb);
        #pragma unroll
        for (int p = 0; p < 4; p++) acc2[c][p] = bp;
    }
    #pragma unroll 1
    for (int pass = 0; pass < 2; pass++) {
        int ci0 = pass*8;
        __syncthreads();
        for (int idx = tid; idx < 8*33*33; idx += 256) {
            int ci = idx / 1089;
            int rem = idx - ci*1089;
            int i = rem / 33, j = rem - i*33;
            sin[ci*1122 + i*34 + j] = (i < 32 && j < 32)
                ? in[(size_t)f*16384 + (ci0+ci)*1024 + i*32 + j] : 0.f;
        }
        for (int idx = tid; idx < 2304; idx += 256) {
            int co = idx / 72;
            int rem = idx - co*72;
            int ci_l = rem / 9, k = rem - ci_l*9;
            sw[idx] = w[(co*16 + ci0 + ci_l)*9 + k];
        }
        __syncthreads();
        #pragma unroll 1
        for (int ci = 0; ci < 8; ci++) {
            const float* base = sin + ci*1122 + (2*oy)*34 + xh*16;
            #pragma unroll
            for (int row = 0; row < 3; row++) {
                const float* rp = base + row*34;
                float r[17];
                #pragma unroll
                for (int t = 0; t < 17; t++) r[t] = rp[t];
                u64 pr[12];
                #pragma unroll
                for (int p = 0; p < 4; p++)
                    #pragma unroll
                    for (int l = 0; l < 3; l++)
                        pr[p*3+l] = pk2(r[p*4+l], r[p*4+l+2]);
                #pragma unroll
                for (int c = 0; c < 4; c++) {
                    const float* wp = sw + (cg*4+c)*72 + ci*9 + row*3;
                    u64 wd0 = pk2(wp[0], wp[0]);
                    u64 wd1 = pk2(wp[1], wp[1]);
                    u64 wd2 = pk2(wp[2], wp[2]);
                    #pragma unroll
                    for (int p = 0; p < 4; p++) {
                        acc2[c][p] = ffma2(pr[p*3+0], wd0, acc2[c][p]);
                        acc2[c][p] = ffma2(pr[p*3+1], wd1, acc2[c][p]);
                        acc2[c][p] = ffma2(pr[p*3+2], wd2, acc2[c][p]);
                    }
                }
            }
        }
    }
    #pragma unroll
    for (int c = 0; c < 4; c++)
        #pragma unroll
        for (int p = 0; p < 4; p++) {
            float2 v = upk2(acc2[c][p]);
            float2 o = make_float2(fmaxf(v.x, 0.f), fmaxf(v.y, 0.f));
            *(float2*)&out[((size_t)f*32 + cg*4+c)*256 + oy*16 + xh*8 + 2*p] = o;
        }
}

// conv3 + relu + global avg pool + fc (32->256) fused; 2 frames per block
__global__ __launch_bounds__(256) void conv3poolfc_kernel(const float* __restrict__ in,
                                 const float* __restrict__ w,
                                 const float* __restrict__ b,
                                 const float* __restrict__ fcw,
                                 const float* __restrict__ fcb,
                                 float* __restrict__ h)
{
    __shared__ __align__(16) float sin[2*8*17*18];
    __shared__ __align__(16) float sw[32*8*9];
    __shared__ __align__(16) float zsh[64];
    int f0 = blockIdx.x * 2;
    int tid = threadIdx.x;
    int fr = tid >> 7;
    int t  = tid & 127;
    int cg = t >> 4;
    int oy = (t >> 1) & 7;
    int xh = t & 1;
    u64 acc2[4][2];
    #pragma unroll
    for (int c = 0; c < 4; c++) {
        float bb = __ldg(&b[cg*4+c]);
        u64 bp = pk2(bb, bb);
        acc2[c][0] = bp; acc2[c][1] = bp;
    }
    #pragma unroll 1
    for (int pass = 0; pass < 4; pass++) {
        int ci0 = pass*8;
        __syncthreads();
        for (int idx = tid; idx < 2*8*17*17; idx += 256) {
            int fr2 = idx / 2312;
            int rem = idx - fr2*2312;
            int ci = rem / 289;
            int r2 = rem - ci*289;
            int i = r2 / 17, j = r2 - i*17;
            sin[fr2*2448 + ci*306 + i*18 + j] = (i < 16 && j < 16)
                ? in[(size_t)(f0+fr2)*8192 + (ci0+ci)*256 + i*16 + j] : 0.f;
        }
        for (int idx = tid; idx < 2304; idx += 256) {
            int co = idx / 72;
            int rem = idx - co*72;
            int ci_l = rem / 9, k = rem - ci_l*9;
            sw[idx] = w[(co*32 + ci0 + ci_l)*9 + k];
        }
        __syncthreads();
        #pragma unroll 1
        for (int ci = 0; ci < 8; ci++) {
            const float* base = sin + fr*2448 + ci*306 + (2*oy)*18 + xh*8;
            #pragma unroll
            for (int row = 0; row < 3; row++) {
                const float* rp = base + row*18;
                float r[9];
                #pragma unroll
                for (int q = 0; q < 9; q++) r[q] = rp[q];
                u64 pr[6];
                #pragma unroll
                for (int p = 0; p < 2; p++)
                    #pragma unroll
                    for (int l = 0; l < 3; l++)
                        pr[p*3+l] = pk2(r[p*4+l], r[p*4+l+2]);
                #pragma unroll
                for (int c = 0; c < 4; c++) {
                    const float* wp = sw + (cg*4+c)*72 + ci*9 + row*3;
                    u64 wd0 = pk2(wp[0], wp[0]);
                    u64 wd1 = pk2(wp[1], wp[1]);
                    u64 wd2 = pk2(wp[2], wp[2]);
                    #pragma unroll
                    for (int p = 0; p < 2; p++) {
                        acc2[c][p] = ffma2(pr[p*3+0], wd0, acc2[c][p]);
                        acc2[c][p] = ffma2(pr[p*3+1], wd1, acc2[c][p]);
                        acc2[c][p] = ffma2(pr[p*3+2], wd2, acc2[c][p]);
                    }
                }
            }
        }
    }
    #pragma unroll
    for (int c = 0; c < 4; c++) {
        float2 v0 = upk2(acc2[c][0]), v1 = upk2(acc2[c][1]);
        float s = fmaxf(v0.x,0.f) + fmaxf(v0.y,0.f) + fmaxf(v1.x,0.f) + fmaxf(v1.y,0.f);
        #pragma unroll
        for (int o = 8; o > 0; o >>= 1) s += __shfl_down_sync(0xffffffffu, s, o, 16);
        if (oy == 0 && xh == 0) zsh[fr*32 + cg*4 + c] = s * (1.f/64.f);
    }
    __syncthreads();
    int fr2 = tid >> 7;
    int j = tid & 127;
    const float* zz = zsh + fr2*32;
    float a0 = fcb[j], a1 = fcb[j+128];
    const float4* w0p = (const float4*)(fcw + j*32);
    const float4* w1p = (const float4*)(fcw + (j+128)*32);
    #pragma unroll
    for (int k = 0; k < 8; k++) {
        float4 wv0 = w0p[k], wv1 = w1p[k];
        const float* zk = zz + k*4;
        a0 = fmaf(zk[0],wv0.x,fmaf(zk[1],wv0.y,fmaf(zk[2],wv0.z,fmaf(zk[3],wv0.w,a0))));
        a1 = fmaf(zk[0],wv1.x,fmaf(zk[1],wv1.y,fmaf(zk[2],wv1.z,fmaf(zk[3],wv1.w,a1))));
    }
    h[(size_t)(f0+fr2)*256 + j] = a0;
    h[(size_t)(f0+fr2)*256 + j + 128] = a1;
}

// =====================================================================
// Mamba pieces
// =====================================================================
__global__ __launch_bounds__(256) void rmsnorm_kernel(const float* __restrict__ x,
                               const float* __restrict__ w,
                               float* __restrict__ out)
{
    int tok = blockIdx.x*8 + (threadIdx.x >> 5);
    int lane = threadIdx.x & 31;
    const float4* xr = (const float4*)(x + (size_t)tok*256);
    float4 v0 = xr[lane*2], v1 = xr[lane*2+1];
    float ss = v0.x*v0.x + v0.y*v0.y + v0.z*v0.z + v0.w*v0.w
             + v1.x*v1.x + v1.y*v1.y + v1.z*v1.z + v1.w*v1.w;
    #pragma unroll
    for (int o = 16; o > 0; o >>= 1) ss += __shfl_xor_sync(0xffffffffu, ss, o);
    float scale = rsqrtf(ss * (1.f/256.f) + 1e-5f);
    const float4* wr = (const float4*)w;
    float4 w0 = wr[lane*2], w1 = wr[lane*2+1];
    float4 o0, o1;
    o0.x = v0.x*scale*w0.x; o0.y = v0.y*scale*w0.y; o0.z = v0.z*scale*w0.z; o0.w = v0.w*scale*w0.w;
    o1.x = v1.x*scale*w1.x; o1.y = v1.y*scale*w1.y; o1.z = v1.z*scale*w1.z; o1.w = v1.w*scale*w1.w;
    float4* outr = (float4*)(out + (size_t)tok*256);
    outr[lane*2] = o0; outr[lane*2+1] = o1;
}

// tile 128x128, 256 thr, 8x8 micro (4 row-pairs x 8 cols), f32x2,
// Kt=16, global-load register prefetch. LDS:FMA = 1B/FMA (peak-balanced).
__global__ __launch_bounds__(256) void gemm128_kernel(const float* __restrict__ A,
                              const float* __restrict__ W,
                              float* __restrict__ C,
                              int M, int N, int K)
{
    __shared__ __align__(16) float As[16][132];
    __shared__ __align__(16) float Ws[16][132];
    int bm = blockIdx.y * 128;
    int bn = blockIdx.x * 128;
    int tid = threadIdx.x;
    int tx = tid & 15, ty = tid >> 4;
    // loaders: 2 float4 per matrix per thread
    int r0 = tid >> 2, c0 = tid & 3;   // rows 0..63
    int r1 = r0 + 64;                  // rows 64..127
    const float* Ap0 = &A[(size_t)(bm+r0)*K + c0*4];
    const float* Ap1 = &A[(size_t)(bm+r1)*K + c0*4];
    const float* Wp0 = &W[(size_t)(bn+r0)*K + c0*4];
    const float* Wp1 = &W[(size_t)(bn+r1)*K + c0*4];
    float4 va0 = *(const float4*)Ap0, va1 = *(const float4*)Ap1;
    float4 vw0 = *(const float4*)Wp0, vw1 = *(const float4*)Wp1;
    u64 acc[4][8];
    #pragma unroll
    for (int i = 0; i < 4; i++)
        #pragma unroll
        for (int j = 0; j < 8; j++) acc[i][j] = 0ull;
    for (int k0 = 0; k0 < K; k0 += 16) {
        #pragma unroll
        for (int i = 0; i < 4; i++) {
            As[c0*4+i][r0] = (&va0.x)[i];
            As[c0*4+i][r1] = (&va1.x)[i];
            Ws[c0*4+i][r0] = (&vw0.x)[i];
            Ws[c0*4+i][r1] = (&vw1.x)[i];
        }
        __syncthreads();
        if (k0 + 16 < K) {
            va0 = *(const float4*)(Ap0 + k0 + 16);
            va1 = *(const float4*)(Ap1 + k0 + 16);
            vw0 = *(const float4*)(Wp0 + k0 + 16);
            vw1 = *(const float4*)(Wp1 + k0 + 16);
        }
        #pragma unroll
        for (int k = 0; k < 16; k++) {
            F4U au0, au1;
            au0.f = *(const float4*)&As[k][ty*8];
            au1.f = *(const float4*)&As[k][ty*8+4];
            float4 w0 = *(const float4*)&Ws[k][tx*8];
            float4 w1 = *(const float4*)&Ws[k][tx*8+4];
            u64 wv[8];
            wv[0] = pk2(w0.x, w0.x); wv[1] = pk2(w0.y, w0.y);
            wv[2] = pk2(w0.z, w0.z); wv[3] = pk2(w0.w, w0.w);
            wv[4] = pk2(w1.x, w1.x); wv[5] = pk2(w1.y, w1.y);
            wv[6] = pk2(w1.z, w1.z); wv[7] = pk2(w1.w, w1.w);
            u64 ap[4] = { au0.u[0], au0.u[1], au1.u[0], au1.u[1] };
            #pragma unroll
            for (int i = 0; i < 4; i++)
                #pragma unroll
                for (int j = 0; j < 8; j++)
                    acc[i][j] = ffma2(ap[i], wv[j], acc[i][j]);
        }
        __syncthreads();
    }
    // acc[i][j]: rows (ty*8+2i, ty*8+2i+1), col tx*8+j
    #pragma unroll
    for (int i = 0; i < 4; i++) {
        int m0 = bm + ty*8 + 2*i;
        float lo[8], hi[8];
        #pragma unroll
        for (int j = 0; j < 8; j++) {
            float2 v = upk2(acc[i][j]);
            lo[j] = v.x; hi[j] = v.y;
        }
        float* c0p = &C[(size_t)m0*N + bn + tx*8];
        float* c1p = &C[(size_t)(m0+1)*N + bn + tx*8];
        *(float4*)c0p       = make_float4(lo[0], lo[1], lo[2], lo[3]);
        *(float4*)(c0p + 4) = make_float4(lo[4], lo[5], lo[6], lo[7]);
        *(float4*)c1p       = make_float4(hi[0], hi[1], hi[2], hi[3]);
        *(float4*)(c1p + 4) = make_float4(hi[4], hi[5], hi[6], hi[7]);
    }
}

// tile 32x64, 256 thr, 2x4 micro, f32x2, Kt=16, prefetch (round-7 exact).
// EPI: 1 accumulate, 2 bias+gelu
template<int EPI>
__global__ __launch_bounds__(256) void gemm32x64_kernel(const float* __restrict__ A,
                              const float* __restrict__ W,
                              const float* __restrict__ bias,
                              float* __restrict__ C,
                              int M, int N, int K)
{
    __shared__ __align__(16) float As[16][36];
    __shared__ __align__(16) float Ws[16][68];
    int bm = blockIdx.y * 32;
    int bn = blockIdx.x * 64;
    int tid = threadIdx.x;
    int tx = tid & 15, ty = tid >> 4;
    int r = tid >> 2, c = tid & 3;
    const float* Ap = &A[(size_t)(bm+r)*K + c*4];
    const float* Wp = &W[(size_t)(bn+r)*K + c*4];
    float4 va;
    if (tid < 128) va = *(const float4*)Ap;
    float4 vw = *(const float4*)Wp;
    u64 acc[2][2];
    acc[0][0]=0ull; acc[0][1]=0ull; acc[1][0]=0ull; acc[1][1]=0ull;
    for (int k0 = 0; k0 < K; k0 += 16) {
        if (tid < 128) {
            As[c*4+0][r] = va.x; As[c*4+1][r] = va.y; As[c*4+2][r] = va.z; As[c*4+3][r] = va.w;
        }
        Ws[c*4+0][r] = vw.x; Ws[c*4+1][r] = vw.y; Ws[c*4+2][r] = vw.z; Ws[c*4+3][r] = vw.w;
        __syncthreads();
        if (k0 + 16 < K) {
            if (tid < 128) va = *(const float4*)(Ap + k0 + 16);
            vw = *(const float4*)(Wp + k0 + 16);
        }
        #pragma unroll
        for (int k = 0; k < 16; k++) {
            float2 a0 = *(const float2*)&As[k][ty*2];
            F4U b0;
            b0.f = *(const float4*)&Ws[k][tx*4];
            u64 bp0 = b0.u[0], bp1 = b0.u[1];
            u64 ad0 = pk2(a0.x, a0.x);
            u64 ad1 = pk2(a0.y, a0.y);
            acc[0][0] = ffma2(ad0, bp0, acc[0][0]);
            acc[0][1] = ffma2(ad0, bp1, acc[0][1]);
            acc[1][0] = ffma2(ad1, bp0, acc[1][0]);
            acc[1][1] = ffma2(ad1, bp1, acc[1][1]);
        }
        __syncthreads();
    }
    #pragma unroll
    for (int i = 0; i < 2; i++) {
        int m = bm + ty*2 + i;
        float2 v0 = upk2(acc[i][0]), v1 = upk2(acc[i][1]);
        float vals[4] = {v0.x, v0.y, v1.x, v1.y};
        size_t base = (size_t)m*N + bn + tx*4;
        if (EPI == 1) {
            float4 old = *(float4*)&C[base];
            old.x += vals[0]; old.y += vals[1]; old.z += vals[2]; old.w += vals[3];
            *(float4*)&C[base] = old;
        } else {
            float4 o;
            float* op = &o.x;
            #pragma unroll
            for (int j = 0; j < 4; j++) {
                float v = vals[j] + bias[bn + tx*4 + j];
                float v3 = v*v*v;
                op[j] = 0.5f * v * (1.f + tanhf(0.7978845608028654f * (v + 0.044715f*v3)));
            }
            *(float4*)&C[base] = o;
        }
    }
}

// Fused conv1d+silu + x_proj + dt_proj: per block 16 tokens.
#define SXIDX(tok, k) ((tok)*512 + (((k) + (tok)*4) & 511))
__global__ __launch_bounds__(256) void xproj_fused_kernel(
    const float* __restrict__ xz,
    const float* __restrict__ cw,
    const float* __restrict__ cb,
    const float* __restrict__ xpw,
    const float* __restrict__ dpw,
    const float* __restrict__ dpb,
    float2* __restrict__ bc,
    float2* __restrict__ du)
{
    __shared__ __align__(16) float sx[16*512];
    __shared__ __align__(16) float buf[48*68];
    __shared__ __align__(16) float sdt[16*16];
    int tok0 = blockIdx.x * 16;
    int tid = threadIdx.x;

    // ---- conv1d + silu from xz into sx ----
    for (int idx = tid; idx < 2048; idx += 256) {
        int e = idx >> 2, k = idx & 3;
        buf[k*512 + e] = cw[idx];
    }
    for (int idx = tid; idx < 512; idx += 256) buf[2048 + idx] = cb[idx];
    __syncthreads();
    int tl0 = tok0 & 255;
    #pragma unroll 1
    for (int s = 0; s < 8; s++) {
        int q = tid + s*256;
        int t = q >> 7;
        int e = (q & 127)*4;
        float4 acc = *(const float4*)&buf[2048 + e];
        #pragma unroll
        for (int k = 0; k < 4; k++) {
            if (tl0 + t - 3 + k >= 0) {
                float4 xv = *(const float4*)&xz[(size_t)(tok0 + t - 3 + k)*1024 + e];
                float4 wv = *(const float4*)&buf[k*512 + e];
                acc.x = fmaf(xv.x, wv.x, acc.x);
                acc.y = fmaf(xv.y, wv.y, acc.y);
                acc.z = fmaf(xv.z, wv.z, acc.z);
                acc.w = fmaf(xv.w, wv.w, acc.w);
            }
        }
        acc.x = acc.x / (1.f + __expf(-acc.x));
        acc.y = acc.y / (1.f + __expf(-acc.y));
        acc.z = acc.z / (1.f + __expf(-acc.z));
        acc.w = acc.w / (1.f + __expf(-acc.w));
        *(float4*)&sx[SXIDX(t, e)] = acc;
    }

    // ---- Phase A: dbc = xin . xpw^T (float4 k-unroll) ----
    int tg = tid & 15;
    int jg = tid >> 4;
    int rot = tg*4;
    const float* sxr = sx + tg*512;
    float acc0 = 0.f, acc1 = 0.f, acc2 = 0.f;
    #pragma unroll 1
    for (int kc = 0; kc < 8; kc++) {
        int k0 = kc*64;
        __syncthreads();
        #pragma unroll
        for (int s = 0; s < 3; s++) {
            int q = tid + s*256;
            int r = q >> 4, c = q & 15;
            float4 v = *(const float4*)&xpw[(size_t)r*512 + k0 + c*4];
            float* dst = buf + r*68 + c*4;
            dst[0]=v.x; dst[1]=v.y; dst[2]=v.z; dst[3]=v.w;
        }
        __syncthreads();
        const float* w0 = buf + (jg*3+0)*68;
        const float* w1 = buf + (jg*3+1)*68;
        const float* w2 = buf + (jg*3+2)*68;
        #pragma unroll
        for (int k4 = 0; k4 < 16; k4++) {
            int kk = (k0 + k4*4 + rot) & 511;
            float4 xv = *(const float4*)&sxr[kk];
            float4 a4 = *(const float4*)&w0[k4*4];
            float4 b4 = *(const float4*)&w1[k4*4];
            float4 c4 = *(const float4*)&w2[k4*4];
            acc0 = fmaf(xv.x,a4.x, fmaf(xv.y,a4.y, fmaf(xv.z,a4.z, fmaf(xv.w,a4.w, acc0))));
            acc1 = fmaf(xv.x,b4.x, fmaf(xv.y,b4.y, fmaf(xv.z,b4.z, fmaf(xv.w,b4.w, acc1))));
            acc2 = fmaf(xv.x,c4.x, fmaf(xv.y,c4.y, fmaf(xv.z,c4.z, fmaf(xv.w,c4.w, acc2))));
        }
    }
    {
        float av[3] = {acc0, acc1, acc2};
        #pragma unroll
        for (int jj = 0; jj < 3; jj++) {
            int j = jg*3 + jj;
            float v = av[jj];
            int tok = tok0 + tg;
            if (j < 16)       sdt[tg*16 + j] = v;
            else if (j < 32)  bc[tok*16 + (j-16)].x = v;
            else              bc[tok*16 + (j-32)].y = v;
        }
    }

    // ---- Phase B ----
    #pragma unroll 1
    for (int ec = 0; ec < 4; ec++) {
        int e0 = ec*128;
        __syncthreads();
        #pragma unroll
        for (int s = 0; s < 2; s++) {
            int q = tid + s*256;
            int r = q >> 2, c = q & 3;
            float4 v = *(const float4*)&dpw[(size_t)(e0+r)*16 + c*4];
            float* dst = buf + r*16 + c*4;
            dst[0]=v.x; dst[1]=v.y; dst[2]=v.z; dst[3]=v.w;
        }
        __syncthreads();
        #pragma unroll 1
        for (int s = 0; s < 8; s++) {
            int idx = tid + s*256;
            int e_l = idx & 127;
            int tok = idx >> 7;
            int e = e0 + e_l;
            const float* dr = sdt + tok*16;
            const float* wr = buf + e_l*16;
            float a = dpb[e];
            #pragma unroll
            for (int k = 0; k < 16; k++) a = fmaf(dr[k], wr[k], a);
            float sp = (a > 20.f) ? a : log1pf(expf(a));
            float u = sx[SXIDX(tok, e)];
            du[(size_t)(tok0+tok)*512 + e] = make_float2(sp, u);
        }
    }
}

// Selective scan: chunked register prefetch + pipelined shfl reduction
__global__ __launch_bounds__(256) void scan_kernel(const float2* __restrict__ du,
                            const float* __restrict__ xz,
                            const float2* __restrict__ bc,
                            const float* __restrict__ A_log,
                            const float* __restrict__ Dp,
                            float* __restrict__ yout)
{
    int tid = blockIdx.x * blockDim.x + threadIdx.x;
    int ch = tid >> 4;
    int n = tid & 15;
    int b = ch >> 9;
    int e = ch & 511;
    float A  = -expf(A_log[e*16 + n]);
    float Dv = Dp[e];
    const float2* duP = du + (size_t)(b*256)*512 + e;
    const float2* bcP = bc + (size_t)(b*256)*16 + n;
    const float*  zP  = xz + (size_t)(b*256)*1024 + 512 + e;
    float* yP = yout + (size_t)(b*256)*512 + e;

    float2 dv[2][8], bv[2][8];
    float  zv[2][8];
    #pragma unroll
    for (int i = 0; i < 8; i++) {
        dv[0][i] = duP[i*512];
        bv[0][i] = bcP[i*16];
    }
    if (n == 0) {
        #pragma unroll
        for (int i = 0; i < 8; i++) zv[0][i] = zP[i*1024];
    }
    float h = 0.f;
    int buf = 0;
    #pragma unroll 1
    for (int c = 0; c < 32; c++) {
        int nb = buf ^ 1;
        if (c < 31) {
            int t1 = c*8 + 8;
            #pragma unroll
            for (int i = 0; i < 8; i++) {
                dv[nb][i] = duP[(t1+i)*512];
                bv[nb][i] = bcP[(t1+i)*16];
            }
            if (n == 0) {
                #pragma unroll
                for (int i = 0; i < 8; i++) zv[nb][i] = zP[(size_t)(t1+i)*1024];
            }
        }
        float part[8];
        #pragma unroll
        for (int i = 0; i < 8; i++) {
            float2 duv = dv[buf][i];
            float2 bcv = bv[buf][i];
            float dA = __expf(duv.x * A);
            h = fmaf(h, dA, duv.x * bcv.x * duv.y);
            part[i] = h * bcv.y;
        }
        #pragma unroll
        for (int o = 8; o > 0; o >>= 1) {
            #pragma unroll
            for (int i = 0; i < 8; i++)
                part[i] += __shfl_down_sync(0xffffffffu, part[i], o, 16);
        }
        if (n == 0) {
            #pragma unroll
            for (int i = 0; i < 8; i++) {
                float z = zv[buf][i];
                float yy = part[i] + dv[buf][i].y * Dv;
                yP[(size_t)(c*8+i)*512] = yy * (z / (1.f + __expf(-z)));
            }
        }
        buf = nb;
    }
}

// =====================================================================
// Head tail
// =====================================================================
__global__ __launch_bounds__(256) void head2_kernel(const float* __restrict__ hh,
                             const float* __restrict__ w,
                             const float* __restrict__ b,
                             float* __restrict__ logits)
{
    int wid = (blockIdx.x * blockDim.x + threadIdx.x) >> 5;
    int lane = threadIdx.x & 31;
    const float* xr = hh + (size_t)wid*64;
    float acc = fmaf(xr[lane], w[lane], xr[lane+32]*w[lane+32]);
    #pragma unroll
    for (int o = 16; o > 0; o >>= 1) acc += __shfl_down_sync(0xffffffffu, acc, o);
    if (lane == 0) logits[wid] = acc + b[0];
}

__global__ __launch_bounds__(256) void softmax_kernel(const float* __restrict__ logits,
                               float* __restrict__ out)
{
    int b = blockIdx.x;
    int t = threadIdx.x;
    float v = logits[b*256 + t];
    __shared__ float red[8];
    __shared__ float sM, sS;
    float m = v;
    #pragma unroll
    for (int o = 16; o > 0; o >>= 1) m = fmaxf(m, __shfl_xor_sync(0xffffffffu, m, o));
    if ((t & 31) == 0) red[t >> 5] = m;
    __syncthreads();
    if (t < 8) {
        float mm = red[t];
        #pragma unroll
        for (int o = 4; o > 0; o >>= 1) mm = fmaxf(mm, __shfl_xor_sync(0xffu, mm, o, 8));
        if (t == 0) sM = mm;
    }
    __syncthreads();
    float e = expf(v - sM);
    float s = e;
    #pragma unroll
    for (int o = 16; o > 0; o >>= 1) s += __shfl_xor_sync(0xffffffffu, s, o);
    __syncthreads();
    if ((t & 31) == 0) red[t >> 5] = s;
    __syncthreads();
    if (t < 8) {
        float ss2 = red[t];
        #pragma unroll
        for (int o = 4; o > 0; o >>= 1) ss2 += __shfl_xor_sync(0xffu, ss2, o, 8);
        if (t == 0) sS = ss2;
    }
    __syncthreads();
    out[b*256 + t] = (t == 0) ? 0.f : e / sS;
}

// =====================================================================
// Launcher
// =====================================================================
extern "C" void kernel_launch(void* const* d_in, const int* in_sizes, int n_in,
                              void* d_out, int out_size)
{
    (void)in_sizes; (void)n_in; (void)out_size;
    const float* x        = (const float*)d_in[0];
    const float* cnn_w1   = (const float*)d_in[1];
    const float* cnn_b1   = (const float*)d_in[2];
    const float* cnn_w2   = (const float*)d_in[3];
    const float* cnn_b2   = (const float*)d_in[4];
    const float* cnn_w3   = (const float*)d_in[5];
    const float* cnn_b3   = (const float*)d_in[6];
    const float* fc_w     = (const float*)d_in[7];
    const float* fc_b     = (const float*)d_in[8];
    const float* norm_w   = (const float*)d_in[9];
    const float* in_proj_w= (const float*)d_in[10];
    const float* conv1d_w = (const float*)d_in[11];
    const float* conv1d_b = (const float*)d_in[12];
    const float* x_proj_w = (const float*)d_in[13];
    const float* dt_proj_w= (const float*)d_in[14];
    const float* dt_proj_b= (const float*)d_in[15];
    const float* A_log    = (const float*)d_in[16];
    const float* Dp       = (const float*)d_in[17];
    const float* out_proj_w=(const float*)d_in[18];
    const float* norm_f_w = (const float*)d_in[19];
    const float* head_w1  = (const float*)d_in[20];
    const float* head_b1  = (const float*)d_in[21];
    const float* head_w2  = (const float*)d_in[22];
    const float* head_b2  = (const float*)d_in[23];
    float* out = (float*)d_out;

    float *f1, *f2, *h, *xn, *xz, *y, *hh, *logits;
    float2 *bc, *du;
    cudaGetSymbolAddress((void**)&f1, g_f1);
    cudaGetSymbolAddress((void**)&f2, g_f2);
    cudaGetSymbolAddress((void**)&h,  g_h);
    cudaGetSymbolAddress((void**)&xn, g_xn);
    cudaGetSymbolAddress((void**)&xz, g_xz);
    cudaGetSymbolAddress((void**)&bc, g_bc);
    cudaGetSymbolAddress((void**)&du, g_du);
    cudaGetSymbolAddress((void**)&y,  g_y);
    cudaGetSymbolAddress((void**)&hh, g_hh);
    cudaGetSymbolAddress((void**)&logits, g_logits);

    // --- CNN encoder ---
    conv1_kernel<<<2048, 512>>>(x, cnn_w1, cnn_b1, f1);
    conv2_kernel<<<2048, 256>>>(f1, cnn_w2, cnn_b2, f2);
    conv3poolfc_kernel<<<1024, 256>>>(f2, cnn_w3, cnn_b3, fc_w, fc_b, h);

    // --- Mamba layers ---
    for (int l = 0; l < 6; l++) {
        const float* nw  = norm_w     + (size_t)l*DM;
        const float* ipw = in_proj_w  + (size_t)l*2*DI*DM;
        const float* cw  = conv1d_w   + (size_t)l*DI*4;
        const float* cb  = conv1d_b   + (size_t)l*DI;
        const float* xpw = x_proj_w   + (size_t)l*48*DI;
        const float* dpw = dt_proj_w  + (size_t)l*DI*DTR;
        const float* dpb = dt_proj_b  + (size_t)l*DI;
        const float* al  = A_log      + (size_t)l*DI*DS;
        const float* dv  = Dp         + (size_t)l*DI;
        const float* opw = out_proj_w + (size_t)l*DM*DI;

        rmsnorm_kernel<<<256, 256>>>(h, nw, xn);
        gemm128_kernel<<<dim3(8, 16), 256>>>(xn, ipw, xz, BT, 1024, 256);
        xproj_fused_kernel<<<128, 256>>>(xz, cw, cb, xpw, dpw, dpb, bc, du);
        scan_kernel<<<BATCH*DI*DS/256, 256>>>(du, xz, bc, al, dv, y);
        gemm32x64_kernel<1><<<dim3(4, 64), 256>>>(y, opw, nullptr, h, BT, 256, 512);
    }

    // --- Head ---
    rmsnorm_kernel<<<256, 256>>>(h, norm_f_w, xn);
    gemm32x64_kernel<2><<<dim3(1, 64), 256>>>(xn, head_w1, head_b1, hh, BT, 64, 256);
    head2_kernel<<<BT*32/256, 256>>>(hh, head_w2, head_b2, logits);
    softmax_kernel<<<BATCH, 256>>>(logits, out);
}

// round 12
// speedup vs baseline: 1.4566x; 1.0116x over previous
#include <cuda_runtime.h>
#include <math.h>

// ---- problem constants ----
#define BATCH   8
#define TT      256
#define BT      2048          // BATCH*TT
#define DM      256           // d_model
#define DI      512           // d_inner
#define DS      16            // d_state
#define DTR     16            // dt_rank

typedef unsigned long long u64;

__device__ __forceinline__ u64 pk2(float lo, float hi) {
    u64 d;
    asm("mov.b64 %0, {%1, %2};" : "=l"(d)
        : "r"(__float_as_uint(lo)), "r"(__float_as_uint(hi)));
    return d;
}
__device__ __forceinline__ u64 ffma2(u64 a, u64 b, u64 c) {
    u64 d;
    asm("fma.rn.f32x2 %0, %1, %2, %3;" : "=l"(d) : "l"(a), "l"(b), "l"(c));
    return d;
}
__device__ __forceinline__ float2 upk2(u64 v) {
    unsigned lo, hi;
    asm("mov.b64 {%0, %1}, %2;" : "=r"(lo), "=r"(hi) : "l"(v));
    return make_float2(__uint_as_float(lo), __uint_as_float(hi));
}
union F4U { float4 f; u64 u[2]; };

// ---- scratch ----
__device__ float  g_f1[2048*16*32*32];
__device__ float  g_f2[2048*32*16*16];
__device__ float  g_h [BT*DM];
__device__ float  g_rms[BT];
__device__ float  g_xz[BT*2*DI];
__device__ float2 g_bc[BT*DS];
__device__ float2 g_du[BT*DI];
__device__ float  g_y [BT*DI];
__device__ float  g_hh[BT*64];
__device__ float  g_logits[BT];

// =====================================================================
// CNN (round-7 measured-good versions)
// =====================================================================
__global__ __launch_bounds__(512) void conv1_kernel(const float* __restrict__ x,
                             const float* __restrict__ w,
                             const float* __restrict__ b,
                             float* __restrict__ out)
{
    __shared__ __align__(16) float sin[65*65];
    __shared__ __align__(16) float sw[144];
    __shared__ __align__(16) float sb[16];
    int f = blockIdx.x;
    const float* xf = x + (size_t)f*4096;
    for (int i = threadIdx.x; i < 65*65; i += 512) {
        int r = i / 65, c = i - r*65;
        sin[i] = (r < 64 && c < 64) ? xf[r*64+c] : 0.f;
    }
    if (threadIdx.x < 144) sw[threadIdx.x] = w[threadIdx.x];
    if (threadIdx.x < 16)  sb[threadIdx.x] = b[threadIdx.x];
    __syncthreads();
    int xg = threadIdx.x & 3;
    int oy = (threadIdx.x >> 2) & 31;
    int cq = threadIdx.x >> 7;
    u64 acc2[4][4];
    #pragma unroll
    for (int c = 0; c < 4; c++) {
        float bb = sb[cq*4+c];
        u64 bp = pk2(bb, bb);
        #pragma unroll
        for (int p = 0; p < 4; p++) acc2[c][p] = bp;
    }
    int i0 = oy*2, j0 = xg*16;
    #pragma unroll
    for (int ky = 0; ky < 3; ky++) {
        const float* rp = sin + (i0+ky)*65 + j0;
        float r[17];
        #pragma unroll
        for (int t = 0; t < 17; t++) r[t] = rp[t];
        u64 pr[12];
        #pragma unroll
        for (int p = 0; p < 4; p++)
            #pragma unroll
            for (int l = 0; l < 3; l++)
                pr[p*3+l] = pk2(r[p*4+l], r[p*4+l+2]);
        #pragma unroll
        for (int c = 0; c < 4; c++) {
            const float* wp = sw + (cq*4+c)*9 + ky*3;
            u64 wd0 = pk2(wp[0], wp[0]);
            u64 wd1 = pk2(wp[1], wp[1]);
            u64 wd2 = pk2(wp[2], wp[2]);
            #pragma unroll
            for (int p = 0; p < 4; p++) {
                acc2[c][p] = ffma2(pr[p*3+0], wd0, acc2[c][p]);
                acc2[c][p] = ffma2(pr[p*3+1], wd1, acc2[c][p]);
                acc2[c][p] = ffma2(pr[p*3+2], wd2, acc2[c][p]);
            }
        }
    }
    #pragma unroll
    for (int c = 0; c < 4; c++)
        #pragma unroll
        for (int p = 0; p < 4; p++) {
            float2 v = upk2(acc2[c][p]);
            float2 o = make_float2(fmaxf(v.x, 0.f), fmaxf(v.y, 0.f));
            *(float2*)&out[((size_t)f*16 + cq*4+c)*1024 + oy*32 + xg*8 + 2*p] = o;
        }
}

__global__ __launch_bounds__(256) void conv2_kernel(const float* __restrict__ in,
                             const float* __restrict__ w,
                             const float* __restrict__ b,
                             float* __restrict__ out)
{
    __shared__ __align__(16) float sin[8*33*34];
    __shared__ __align__(16) float sw[2304];
    int f = blockIdx.x;
    int tid = threadIdx.x;
    int cg  = tid >> 5;
    int lane = tid & 31;
    int oy = lane >> 1;
    int xh = lane & 1;
    u64 acc2[4][4];
    #pragma unroll
    for (int c = 0; c < 4; c++) {
        float bb = __ldg(&b[cg*4+c]);
        u64 bp = pk2(bb, bb);
        #pragma unroll
        for (int p = 0; p < 4; p++) acc2[c][p] = bp;
    }
    #pragma unroll 1
    for (int pass = 0; pass < 2; pass++) {
        int ci0 = pass*8;
        __syncthreads();
        for (int idx = tid; idx < 8*33*33; idx += 256) {
            int ci = idx / 1089;
            int rem = idx - ci*1089;
            int i = rem / 33, j = rem - i*33;
            sin[ci*1122 + i*34 + j] = (i < 32 && j < 32)
                ? in[(size_t)f*16384 + (ci0+ci)*1024 + i*32 + j] : 0.f;
        }
        for (int idx = tid; idx < 2304; idx += 256) {
            int co = idx / 72;
            int rem = idx - co*72;
            int ci_l = rem / 9, k = rem - ci_l*9;
            sw[idx] = w[(co*16 + ci0 + ci_l)*9 + k];
        }
        __syncthreads();
        #pragma unroll 1
        for (int ci = 0; ci < 8; ci++) {
            const float* base = sin + ci*1122 + (2*oy)*34 + xh*16;
            #pragma unroll
            for (int row = 0; row < 3; row++) {
                const float* rp = base + row*34;
                float r[17];
                #pragma unroll
                for (int t = 0; t < 17; t++) r[t] = rp[t];
                u64 pr[12];
                #pragma unroll
                for (int p = 0; p < 4; p++)
                    #pragma unroll
                    for (int l = 0; l < 3; l++)
                        pr[p*3+l] = pk2(r[p*4+l], r[p*4+l+2]);
                #pragma unroll
                for (int c = 0; c < 4; c++) {
                    const float* wp = sw + (cg*4+c)*72 + ci*9 + row*3;
                    u64 wd0 = pk2(wp[0], wp[0]);
                    u64 wd1 = pk2(wp[1], wp[1]);
                    u64 wd2 = pk2(wp[2], wp[2]);
                    #pragma unroll
                    for (int p = 0; p < 4; p++) {
                        acc2[c][p] = ffma2(pr[p*3+0], wd0, acc2[c][p]);
                        acc2[c][p] = ffma2(pr[p*3+1], wd1, acc2[c][p]);
                        acc2[c][p] = ffma2(pr[p*3+2], wd2, acc2[c][p]);
                    }
                }
            }
        }
    }
    #pragma unroll
    for (int c = 0; c < 4; c++)
        #pragma unroll
        for (int p = 0; p < 4; p++) {
            float2 v = upk2(acc2[c][p]);
            float2 o = make_float2(fmaxf(v.x, 0.f), fmaxf(v.y, 0.f));
            *(float2*)&out[((size_t)f*32 + cg*4+c)*256 + oy*16 + xh*8 + 2*p] = o;
        }
}

// conv3 + relu + global avg pool + fc (32->256) fused; 2 frames per block
__global__ __launch_bounds__(256) void conv3poolfc_kernel(const float* __restrict__ in,
                                 const float* __restrict__ w,
                                 const float* __restrict__ b,
                                 const float* __restrict__ fcw,
                                 const float* __restrict__ fcb,
                                 float* __restrict__ h)
{
    __shared__ __align__(16) float sin[2*8*17*18];
    __shared__ __align__(16) float sw[32*8*9];
    __shared__ __align__(16) float zsh[64];
    int f0 = blockIdx.x * 2;
    int tid = threadIdx.x;
    int fr = tid >> 7;
    int t  = tid & 127;
    int cg = t >> 4;
    int oy = (t >> 1) & 7;
    int xh = t & 1;
    u64 acc2[4][2];
    #pragma unroll
    for (int c = 0; c < 4; c++) {
        float bb = __ldg(&b[cg*4+c]);
        u64 bp = pk2(bb, bb);
        acc2[c][0] = bp; acc2[c][1] = bp;
    }
    #pragma unroll 1
    for (int pass = 0; pass < 4; pass++) {
        int ci0 = pass*8;
        __syncthreads();
        for (int idx = tid; idx < 2*8*17*17; idx += 256) {
            int fr2 = idx / 2312;
            int rem = idx - fr2*2312;
            int ci = rem / 289;
            int r2 = rem - ci*289;
            int i = r2 / 17, j = r2 - i*17;
            sin[fr2*2448 + ci*306 + i*18 + j] = (i < 16 && j < 16)
                ? in[(size_t)(f0+fr2)*8192 + (ci0+ci)*256 + i*16 + j] : 0.f;
        }
        for (int idx = tid; idx < 2304; idx += 256) {
            int co = idx / 72;
            int rem = idx - co*72;
            int ci_l = rem / 9, k = rem - ci_l*9;
            sw[idx] = w[(co*32 + ci0 + ci_l)*9 + k];
        }
        __syncthreads();
        #pragma unroll 1
        for (int ci = 0; ci < 8; ci++) {
            const float* base = sin + fr*2448 + ci*306 + (2*oy)*18 + xh*8;
            #pragma unroll
            for (int row = 0; row < 3; row++) {
                const float* rp = base + row*18;
                float r[9];
                #pragma unroll
                for (int q = 0; q < 9; q++) r[q] = rp[q];
                u64 pr[6];
                #pragma unroll
                for (int p = 0; p < 2; p++)
                    #pragma unroll
                    for (int l = 0; l < 3; l++)
                        pr[p*3+l] = pk2(r[p*4+l], r[p*4+l+2]);
                #pragma unroll
                for (int c = 0; c < 4; c++) {
                    const float* wp = sw + (cg*4+c)*72 + ci*9 + row*3;
                    u64 wd0 = pk2(wp[0], wp[0]);
                    u64 wd1 = pk2(wp[1], wp[1]);
                    u64 wd2 = pk2(wp[2], wp[2]);
                    #pragma unroll
                    for (int p = 0; p < 2; p++) {
                        acc2[c][p] = ffma2(pr[p*3+0], wd0, acc2[c][p]);
                        acc2[c][p] = ffma2(pr[p*3+1], wd1, acc2[c][p]);
                        acc2[c][p] = ffma2(pr[p*3+2], wd2, acc2[c][p]);
                    }
                }
            }
        }
    }
    #pragma unroll
    for (int c = 0; c < 4; c++) {
        float2 v0 = upk2(acc2[c][0]), v1 = upk2(acc2[c][1]);
        float s = fmaxf(v0.x,0.f) + fmaxf(v0.y,0.f) + fmaxf(v1.x,0.f) + fmaxf(v1.y,0.f);
        #pragma unroll
        for (int o = 8; o > 0; o >>= 1) s += __shfl_down_sync(0xffffffffu, s, o, 16);
        if (oy == 0 && xh == 0) zsh[fr*32 + cg*4 + c] = s * (1.f/64.f);
    }
    __syncthreads();
    int fr2 = tid >> 7;
    int j = tid & 127;
    const float* zz = zsh + fr2*32;
    float a0 = fcb[j], a1 = fcb[j+128];
    const float4* w0p = (const float4*)(fcw + j*32);
    const float4* w1p = (const float4*)(fcw + (j+128)*32);
    #pragma unroll
    for (int k = 0; k < 8; k++) {
        float4 wv0 = w0p[k], wv1 = w1p[k];
        const float* zk = zz + k*4;
        a0 = fmaf(zk[0],wv0.x,fmaf(zk[1],wv0.y,fmaf(zk[2],wv0.z,fmaf(zk[3],wv0.w,a0))));
        a1 = fmaf(zk[0],wv1.x,fmaf(zk[1],wv1.y,fmaf(zk[2],wv1.z,fmaf(zk[3],wv1.w,a1))));
    }
    h[(size_t)(f0+fr2)*256 + j] = a0;
    h[(size_t)(f0+fr2)*256 + j + 128] = a1;
}

// =====================================================================
// Mamba pieces
// =====================================================================
// rmsnorm scale only: sc[tok] = rsqrt(mean(h^2)+eps)
__global__ __launch_bounds__(256) void rms_scale_kernel(const float* __restrict__ x,
                               float* __restrict__ sc)
{
    int tok = blockIdx.x*8 + (threadIdx.x >> 5);
    int lane = threadIdx.x & 31;
    const float4* xr = (const float4*)(x + (size_t)tok*256);
    float4 v0 = xr[lane*2], v1 = xr[lane*2+1];
    float ss = v0.x*v0.x + v0.y*v0.y + v0.z*v0.z + v0.w*v0.w
             + v1.x*v1.x + v1.y*v1.y + v1.z*v1.z + v1.w*v1.w;
    #pragma unroll
    for (int o = 16; o > 0; o >>= 1) ss += __shfl_xor_sync(0xffffffffu, ss, o);
    if (lane == 0) sc[tok] = rsqrtf(ss * (1.f/256.f) + 1e-5f);
}

// tile 128x128, 256 thr, 8x8 micro (4 row-pairs x 8 cols), f32x2,
// Kt=16, global-load register prefetch. A normalized on load: A*scale[m]*nw[k].
__global__ __launch_bounds__(256) void gemm128_kernel(const float* __restrict__ A,
                              const float* __restrict__ scale,
                              const float* __restrict__ nw,
                              const float* __restrict__ W,
                              float* __restrict__ C,
                              int M, int N, int K)
{
    __shared__ __align__(16) float As[16][132];
    __shared__ __align__(16) float Ws[16][132];
    int bm = blockIdx.y * 128;
    int bn = blockIdx.x * 128;
    int tid = threadIdx.x;
    int tx = tid & 15, ty = tid >> 4;
    int r0 = tid >> 2, c0 = tid & 3;   // rows 0..63
    int r1 = r0 + 64;                  // rows 64..127
    const float* Ap0 = &A[(size_t)(bm+r0)*K + c0*4];
    const float* Ap1 = &A[(size_t)(bm+r1)*K + c0*4];
    const float* Wp0 = &W[(size_t)(bn+r0)*K + c0*4];
    const float* Wp1 = &W[(size_t)(bn+r1)*K + c0*4];
    float sc0 = __ldg(&scale[bm+r0]);
    float sc1 = __ldg(&scale[bm+r1]);
    float4 va0 = *(const float4*)Ap0, va1 = *(const float4*)Ap1;
    float4 vw0 = *(const float4*)Wp0, vw1 = *(const float4*)Wp1;
    float4 vnw = *(const float4*)&nw[c0*4];
    u64 acc[4][8];
    #pragma unroll
    for (int i = 0; i < 4; i++)
        #pragma unroll
        for (int j = 0; j < 8; j++) acc[i][j] = 0ull;
    for (int k0 = 0; k0 < K; k0 += 16) {
        #pragma unroll
        for (int i = 0; i < 4; i++) {
            float nv = (&vnw.x)[i];
            As[c0*4+i][r0] = (&va0.x)[i] * sc0 * nv;
            As[c0*4+i][r1] = (&va1.x)[i] * sc1 * nv;
            Ws[c0*4+i][r0] = (&vw0.x)[i];
            Ws[c0*4+i][r1] = (&vw1.x)[i];
        }
        __syncthreads();
        if (k0 + 16 < K) {
            va0 = *(const float4*)(Ap0 + k0 + 16);
            va1 = *(const float4*)(Ap1 + k0 + 16);
            vw0 = *(const float4*)(Wp0 + k0 + 16);
            vw1 = *(const float4*)(Wp1 + k0 + 16);
            vnw = *(const float4*)&nw[k0 + 16 + c0*4];
        }
        #pragma unroll
        for (int k = 0; k < 16; k++) {
            F4U au0, au1;
            au0.f = *(const float4*)&As[k][ty*8];
            au1.f = *(const float4*)&As[k][ty*8+4];
            float4 w0 = *(const float4*)&Ws[k][tx*8];
            float4 w1 = *(const float4*)&Ws[k][tx*8+4];
            u64 wv[8];
            wv[0] = pk2(w0.x, w0.x); wv[1] = pk2(w0.y, w0.y);
            wv[2] = pk2(w0.z, w0.z); wv[3] = pk2(w0.w, w0.w);
            wv[4] = pk2(w1.x, w1.x); wv[5] = pk2(w1.y, w1.y);
            wv[6] = pk2(w1.z, w1.z); wv[7] = pk2(w1.w, w1.w);
            u64 ap[4] = { au0.u[0], au0.u[1], au1.u[0], au1.u[1] };
            #pragma unroll
            for (int i = 0; i < 4; i++)
                #pragma unroll
                for (int j = 0; j < 8; j++)
                    acc[i][j] = ffma2(ap[i], wv[j], acc[i][j]);
        }
        __syncthreads();
    }
    #pragma unroll
    for (int i = 0; i < 4; i++) {
        int m0 = bm + ty*8 + 2*i;
        float lo[8], hi[8];
        #pragma unroll
        for (int j = 0; j < 8; j++) {
            float2 v = upk2(acc[i][j]);
            lo[j] = v.x; hi[j] = v.y;
        }
        float* c0p = &C[(size_t)m0*N + bn + tx*8];
        float* c1p = &C[(size_t)(m0+1)*N + bn + tx*8];
        *(float4*)c0p       = make_float4(lo[0], lo[1], lo[2], lo[3]);
        *(float4*)(c0p + 4) = make_float4(lo[4], lo[5], lo[6], lo[7]);
        *(float4*)c1p       = make_float4(hi[0], hi[1], hi[2], hi[3]);
        *(float4*)(c1p + 4) = make_float4(hi[4], hi[5], hi[6], hi[7]);
    }
}

// tile 64x64, 256 thr, 16 outputs (2 row-pairs x 4 cols), f32x2, Kt=16,
// prefetch. EPI: 1 accumulate, 2 bias+gelu. NORM: A*scale[m]*nw[k] on load.
template<int EPI, int NORM>
__global__ __launch_bounds__(256) void gemm64_kernel(const float* __restrict__ A,
                              const float* __restrict__ scale,
                              const float* __restrict__ nw,
                              const float* __restrict__ W,
                              const float* __restrict__ bias,
                              float* __restrict__ C,
                              int M, int N, int K)
{
    __shared__ __align__(16) float As[16][68];
    __shared__ __align__(16) float Ws[16][68];
    int bm = blockIdx.y * 64;
    int bn = blockIdx.x * 64;
    int tid = threadIdx.x;
    int tx = tid & 15, ty = tid >> 4;
    int r = tid >> 2, c = tid & 3;
    const float* Ap = &A[(size_t)(bm+r)*K + c*4];
    const float* Wp = &W[(size_t)(bn+r)*K + c*4];
    float4 va = *(const float4*)Ap;
    float4 vw = *(const float4*)Wp;
    float sc = 1.f;
    float4 vnw;
    if (NORM) {
        sc = __ldg(&scale[bm+r]);
        vnw = *(const float4*)&nw[c*4];
    }
    u64 acc[2][4];
    #pragma unroll
    for (int p = 0; p < 2; p++)
        #pragma unroll
        for (int j = 0; j < 4; j++) acc[p][j] = 0ull;
    for (int k0 = 0; k0 < K; k0 += 16) {
        #pragma unroll
        for (int i = 0; i < 4; i++) {
            float av = (&va.x)[i];
            if (NORM) av *= sc * (&vnw.x)[i];
            As[c*4+i][r] = av;
            Ws[c*4+i][r] = (&vw.x)[i];
        }
        __syncthreads();
        if (k0 + 16 < K) {
            va = *(const float4*)(Ap + k0 + 16);
            vw = *(const float4*)(Wp + k0 + 16);
            if (NORM) vnw = *(const float4*)&nw[k0 + 16 + c*4];
        }
        #pragma unroll
        for (int k = 0; k < 16; k++) {
            F4U au;
            au.f = *(const float4*)&As[k][ty*4];
            float4 w4 = *(const float4*)&Ws[k][tx*4];
            u64 wv0 = pk2(w4.x, w4.x);
            u64 wv1 = pk2(w4.y, w4.y);
            u64 wv2 = pk2(w4.z, w4.z);
            u64 wv3 = pk2(w4.w, w4.w);
            acc[0][0] = ffma2(au.u[0], wv0, acc[0][0]);
            acc[0][1] = ffma2(au.u[0], wv1, acc[0][1]);
            acc[0][2] = ffma2(au.u[0], wv2, acc[0][2]);
            acc[0][3] = ffma2(au.u[0], wv3, acc[0][3]);
            acc[1][0] = ffma2(au.u[1], wv0, acc[1][0]);
            acc[1][1] = ffma2(au.u[1], wv1, acc[1][1]);
            acc[1][2] = ffma2(au.u[1], wv2, acc[1][2]);
            acc[1][3] = ffma2(au.u[1], wv3, acc[1][3]);
        }
        __syncthreads();
    }
    #pragma unroll
    for (int p = 0; p < 2; p++) {
        int m0 = bm + ty*4 + 2*p;
        float lo[4], hi[4];
        #pragma unroll
        for (int j = 0; j < 4; j++) {
            float2 v = upk2(acc[p][j]);
            lo[j] = v.x; hi[j] = v.y;
        }
        size_t base0 = (size_t)m0*N + bn + tx*4;
        size_t base1 = (size_t)(m0+1)*N + bn + tx*4;
        if (EPI == 1) {
            float4 o0 = *(float4*)&C[base0];
            float4 o1 = *(float4*)&C[base1];
            o0.x += lo[0]; o0.y += lo[1]; o0.z += lo[2]; o0.w += lo[3];
            o1.x += hi[0]; o1.y += hi[1]; o1.z += hi[2]; o1.w += hi[3];
            *(float4*)&C[base0] = o0;
            *(float4*)&C[base1] = o1;
        } else {
            float4 o0, o1;
            float* p0 = &o0.x;
            float* p1 = &o1.x;
            #pragma unroll
            for (int j = 0; j < 4; j++) {
                float bb = bias[bn + tx*4 + j];
                float v = lo[j] + bb;
                float v3 = v*v*v;
                p0[j] = 0.5f * v * (1.f + tanhf(0.7978845608028654f * (v + 0.044715f*v3)));
                v = hi[j] + bb;
                v3 = v*v*v;
                p1[j] = 0.5f * v * (1.f + tanhf(0.7978845608028654f * (v + 0.044715f*v3)));
            }
            *(float4*)&C[base0] = o0;
            *(float4*)&C[base1] = o1;
        }
    }
}

// Fused conv1d+silu + x_proj + dt_proj: per block 16 tokens.
#define SXIDX(tok, k) ((tok)*512 + (((k) + (tok)*4) & 511))
__global__ __launch_bounds__(256) void xproj_fused_kernel(
    const float* __restrict__ xz,
    const float* __restrict__ cw,
    const float* __restrict__ cb,
    const float* __restrict__ xpw,
    const float* __restrict__ dpw,
    const float* __restrict__ dpb,
    float2* __restrict__ bc,
    float2* __restrict__ du)
{
    __shared__ __align__(16) float sx[16*512];
    __shared__ __align__(16) float buf[48*68];
    __shared__ __align__(16) float sdt[16*16];
    int tok0 = blockIdx.x * 16;
    int tid = threadIdx.x;

    // ---- conv1d + silu from xz into sx ----
    for (int idx = tid; idx < 2048; idx += 256) {
        int e = idx >> 2, k = idx & 3;
        buf[k*512 + e] = cw[idx];
    }
    for (int idx = tid; idx < 512; idx += 256) buf[2048 + idx] = cb[idx];
    __syncthreads();
    int tl0 = tok0 & 255;
    #pragma unroll 1
    for (int s = 0; s < 8; s++) {
        int q = tid + s*256;
        int t = q >> 7;
        int e = (q & 127)*4;
        float4 acc = *(const float4*)&buf[2048 + e];
        #pragma unroll
        for (int k = 0; k < 4; k++) {
            if (tl0 + t - 3 + k >= 0) {
                float4 xv = *(const float4*)&xz[(size_t)(tok0 + t - 3 + k)*1024 + e];
                float4 wv = *(const float4*)&buf[k*512 + e];
                acc.x = fmaf(xv.x, wv.x, acc.x);
                acc.y = fmaf(xv.y, wv.y, acc.y);
                acc.z = fmaf(xv.z, wv.z, acc.z);
                acc.w = fmaf(xv.w, wv.w, acc.w);
            }
        }
        acc.x = acc.x / (1.f + __expf(-acc.x));
        acc.y = acc.y / (1.f + __expf(-acc.y));
        acc.z = acc.z / (1.f + __expf(-acc.z));
        acc.w = acc.w / (1.f + __expf(-acc.w));
        *(float4*)&sx[SXIDX(t, e)] = acc;
    }

    // ---- Phase A: dbc = xin . xpw^T (float4 k-unroll) ----
    int tg = tid & 15;
    int jg = tid >> 4;
    int rot = tg*4;
    const float* sxr = sx + tg*512;
    float acc0 = 0.f, acc1 = 0.f, acc2 = 0.f;
    #pragma unroll 1
    for (int kc = 0; kc < 8; kc++) {
        int k0 = kc*64;
        __syncthreads();
        #pragma unroll
        for (int s = 0; s < 3; s++) {
            int q = tid + s*256;
            int r = q >> 4, c = q & 15;
            float4 v = *(const float4*)&xpw[(size_t)r*512 + k0 + c*4];
            float* dst = buf + r*68 + c*4;
            dst[0]=v.x; dst[1]=v.y; dst[2]=v.z; dst[3]=v.w;
        }
        __syncthreads();
        const float* w0 = buf + (jg*3+0)*68;
        const float* w1 = buf + (jg*3+1)*68;
        const float* w2 = buf + (jg*3+2)*68;
        #pragma unroll
        for (int k4 = 0; k4 < 16; k4++) {
            int kk = (k0 + k4*4 + rot) & 511;
            float4 xv = *(const float4*)&sxr[kk];
            float4 a4 = *(const float4*)&w0[k4*4];
            float4 b4 = *(const float4*)&w1[k4*4];
            float4 c4 = *(const float4*)&w2[k4*4];
            acc0 = fmaf(xv.x,a4.x, fmaf(xv.y,a4.y, fmaf(xv.z,a4.z, fmaf(xv.w,a4.w, acc0))));
            acc1 = fmaf(xv.x,b4.x, fmaf(xv.y,b4.y, fmaf(xv.z,b4.z, fmaf(xv.w,b4.w, acc1))));
            acc2 = fmaf(xv.x,c4.x, fmaf(xv.y,c4.y, fmaf(xv.z,c4.z, fmaf(xv.w,c4.w, acc2))));
        }
    }
    {
        float av[3] = {acc0, acc1, acc2};
        #pragma unroll
        for (int jj = 0; jj < 3; jj++) {
            int j = jg*3 + jj;
            float v = av[jj];
            int tok = tok0 + tg;
            if (j < 16)       sdt[tg*16 + j] = v;
            else if (j < 32)  bc[tok*16 + (j-16)].x = v;
            else              bc[tok*16 + (j-32)].y = v;
        }
    }

    // ---- Phase B ----
    #pragma unroll 1
    for (int ec = 0; ec < 4; ec++) {
        int e0 = ec*128;
        __syncthreads();
        #pragma unroll
        for (int s = 0; s < 2; s++) {
            int q = tid + s*256;
            int r = q >> 2, c = q & 3;
            float4 v = *(const float4*)&dpw[(size_t)(e0+r)*16 + c*4];
            float* dst = buf + r*16 + c*4;
            dst[0]=v.x; dst[1]=v.y; dst[2]=v.z; dst[3]=v.w;
        }
        __syncthreads();
        #pragma unroll 1
        for (int s = 0; s < 8; s++) {
            int idx = tid + s*256;
            int e_l = idx & 127;
            int tok = idx >> 7;
            int e = e0 + e_l;
            const float* dr = sdt + tok*16;
            const float* wr = buf + e_l*16;
            float a = dpb[e];
            #pragma unroll
            for (int k = 0; k < 16; k++) a = fmaf(dr[k], wr[k], a);
            float sp = (a > 20.f) ? a : log1pf(expf(a));
            float u = sx[SXIDX(tok, e)];
            du[(size_t)(tok0+tok)*512 + e] = make_float2(sp, u);
        }
    }
}

// Selective scan: chunked register prefetch + pipelined shfl reduction
__global__ __launch_bounds__(256) void scan_kernel(const float2* __restrict__ du,
                            const float* __restrict__ xz,
                            const float2* __restrict__ bc,
                            const float* __restrict__ A_log,
                            const float* __restrict__ Dp,
                            float* __restrict__ yout)
{
    int tid = blockIdx.x * blockDim.x + threadIdx.x;
    int ch = tid >> 4;
    int n = tid & 15;
    int b = ch >> 9;
    int e = ch & 511;
    float A  = -expf(A_log[e*16 + n]);
    float Dv = Dp[e];
    const float2* duP = du + (size_t)(b*256)*512 + e;
    const float2* bcP = bc + (size_t)(b*256)*16 + n;
    const float*  zP  = xz + (size_t)(b*256)*1024 + 512 + e;
    float* yP = yout + (size_t)(b*256)*512 + e;

    float2 dv[2][8], bv[2][8];
    float  zv[2][8];
    #pragma unroll
    for (int i = 0; i < 8; i++) {
        dv[0][i] = duP[i*512];
        bv[0][i] = bcP[i*16];
    }
    if (n == 0) {
        #pragma unroll
        for (int i = 0; i < 8; i++) zv[0][i] = zP[i*1024];
    }
    float h = 0.f;
    int buf = 0;
    #pragma unroll 1
    for (int c = 0; c < 32; c++) {
        int nb = buf ^ 1;
        if (c < 31) {
            int t1 = c*8 + 8;
            #pragma unroll
            for (int i = 0; i < 8; i++) {
                dv[nb][i] = duP[(t1+i)*512];
                bv[nb][i] = bcP[(t1+i)*16];
            }
            if (n == 0) {
                #pragma unroll
                for (int i = 0; i < 8; i++) zv[nb][i] = zP[(size_t)(t1+i)*1024];
            }
        }
        float part[8];
        #pragma unroll
        for (int i = 0; i < 8; i++) {
            float2 duv = dv[buf][i];
            float2 bcv = bv[buf][i];
            float dA = __expf(duv.x * A);
            h = fmaf(h, dA, duv.x * bcv.x * duv.y);
            part[i] = h * bcv.y;
        }
        #pragma unroll
        for (int o = 8; o > 0; o >>= 1) {
            #pragma unroll
            for (int i = 0; i < 8; i++)
                part[i] += __shfl_down_sync(0xffffffffu, part[i], o, 16);
        }
        if (n == 0) {
            #pragma unroll
            for (int i = 0; i < 8; i++) {
                float z = zv[buf][i];
                float yy = part[i] + dv[buf][i].y * Dv;
                yP[(size_t)(c*8+i)*512] = yy * (z / (1.f + __expf(-z)));
            }
        }
        buf = nb;
    }
}

// =====================================================================
// Head tail
// =====================================================================
__global__ __launch_bounds__(256) void head2_kernel(const float* __restrict__ hh,
                             const float* __restrict__ w,
                             const float* __restrict__ b,
                             float* __restrict__ logits)
{
    int wid = (blockIdx.x * blockDim.x + threadIdx.x) >> 5;
    int lane = threadIdx.x & 31;
    const float* xr = hh + (size_t)wid*64;
    float acc = fmaf(xr[lane], w[lane], xr[lane+32]*w[lane+32]);
    #pragma unroll
    for (int o = 16; o > 0; o >>= 1) acc += __shfl_down_sync(0xffffffffu, acc, o);
    if (lane == 0) logits[wid] = acc + b[0];
}

__global__ __launch_bounds__(256) void softmax_kernel(const float* __restrict__ logits,
                               float* __restrict__ out)
{
    int b = blockIdx.x;
    int t = threadIdx.x;
    float v = logits[b*256 + t];
    __shared__ float red[8];
    __shared__ float sM, sS;
    float m = v;
    #pragma unroll
    for (int o = 16; o > 0; o >>= 1) m = fmaxf(m, __shfl_xor_sync(0xffffffffu, m, o));
    if ((t & 31) == 0) red[t >> 5] = m;
    __syncthreads();
    if (t < 8) {
        float mm = red[t];
        #pragma unroll
        for (int o = 4; o > 0; o >>= 1) mm = fmaxf(mm, __shfl_xor_sync(0xffu, mm, o, 8));
        if (t == 0) sM = mm;
    }
    __syncthreads();
    float e = expf(v - sM);
    float s = e;
    #pragma unroll
    for (int o = 16; o > 0; o >>= 1) s += __shfl_xor_sync(0xffffffffu, s, o);
    __syncthreads();
    if ((t & 31) == 0) red[t >> 5] = s;
    __syncthreads();
    if (t < 8) {
        float ss2 = red[t];
        #pragma unroll
        for (int o = 4; o > 0; o >>= 1) ss2 += __shfl_xor_sync(0xffu, ss2, o, 8);
        if (t == 0) sS = ss2;
    }
    __syncthreads();
    out[b*256 + t] = (t == 0) ? 0.f : e / sS;
}

// =====================================================================
// Launcher
// =====================================================================
extern "C" void kernel_launch(void* const* d_in, const int* in_sizes, int n_in,
                              void* d_out, int out_size)
{
    (void)in_sizes; (void)n_in; (void)out_size;
    const float* x        = (const float*)d_in[0];
    const float* cnn_w1   = (const float*)d_in[1];
    const float* cnn_b1   = (const float*)d_in[2];
    const float* cnn_w2   = (const float*)d_in[3];
    const float* cnn_b2   = (const float*)d_in[4];
    const float* cnn_w3   = (const float*)d_in[5];
    const float* cnn_b3   = (const float*)d_in[6];
    const float* fc_w     = (const float*)d_in[7];
    const float* fc_b     = (const float*)d_in[8];
    const float* norm_w   = (const float*)d_in[9];
    const float* in_proj_w= (const float*)d_in[10];
    const float* conv1d_w = (const float*)d_in[11];
    const float* conv1d_b = (const float*)d_in[12];
    const float* x_proj_w = (const float*)d_in[13];
    const float* dt_proj_w= (const float*)d_in[14];
    const float* dt_proj_b= (const float*)d_in[15];
    const float* A_log    = (const float*)d_in[16];
    const float* Dp       = (const float*)d_in[17];
    const float* out_proj_w=(const float*)d_in[18];
    const float* norm_f_w = (const float*)d_in[19];
    const float* head_w1  = (const float*)d_in[20];
    const float* head_b1  = (const float*)d_in[21];
    const float* head_w2  = (const float*)d_in[22];
    const float* head_b2  = (const float*)d_in[23];
    float* out = (float*)d_out;

    float *f1, *f2, *h, *rms, *xz, *y, *hh, *logits;
    float2 *bc, *du;
    cudaGetSymbolAddress((void**)&f1, g_f1);
    cudaGetSymbolAddress((void**)&f2, g_f2);
    cudaGetSymbolAddress((void**)&h,  g_h);
    cudaGetSymbolAddress((void**)&rms, g_rms);
    cudaGetSymbolAddress((void**)&xz, g_xz);
    cudaGetSymbolAddress((void**)&bc, g_bc);
    cudaGetSymbolAddress((void**)&du, g_du);
    cudaGetSymbolAddress((void**)&y,  g_y);
    cudaGetSymbolAddress((void**)&hh, g_hh);
    cudaGetSymbolAddress((void**)&logits, g_logits);

    // --- CNN encoder ---
    conv1_kernel<<<2048, 512>>>(x, cnn_w1, cnn_b1, f1);
    conv2_kernel<<<2048, 256>>>(f1, cnn_w2, cnn_b2, f2);
    conv3poolfc_kernel<<<1024, 256>>>(f2, cnn_w3, cnn_b3, fc_w, fc_b, h);

    // --- Mamba layers ---
    for (int l = 0; l < 6; l++) {
        const float* nw  = norm_w     + (size_t)l*DM;
        const float* ipw = in_proj_w  + (size_t)l*2*DI*DM;
        const float* cw  = conv1d_w   + (size_t)l*DI*4;
        const float* cb  = conv1d_b   + (size_t)l*DI;
        const float* xpw = x_proj_w   + (size_t)l*48*DI;
        const float* dpw = dt_proj_w  + (size_t)l*DI*DTR;
        const float* dpb = dt_proj_b  + (size_t)l*DI;
        const float* al  = A_log      + (size_t)l*DI*DS;
        const float* dv  = Dp         + (size_t)l*DI;
        const float* opw = out_proj_w + (size_t)l*DM*DI;

        rms_scale_kernel<<<256, 256>>>(h, rms);
        gemm128_kernel<<<dim3(8, 16), 256>>>(h, rms, nw, ipw, xz, BT, 1024, 256);
        xproj_fused_kernel<<<128, 256>>>(xz, cw, cb, xpw, dpw, dpb, bc, du);
        scan_kernel<<<BATCH*DI*DS/256, 256>>>(du, xz, bc, al, dv, y);
        gemm64_kernel<1,0><<<dim3(4, 32), 256>>>(y, nullptr, nullptr, opw, nullptr, h, BT, 256, 512);
    }

    // --- Head ---
    rms_scale_kernel<<<256, 256>>>(h, rms);
    gemm64_kernel<2,1><<<dim3(1, 32), 256>>>(h, rms, norm_f_w, head_w1, head_b1, hh, BT, 64, 256);
    head2_kernel<<<BT*32/256, 256>>>(hh, head_w2, head_b2, logits);
    softmax_kernel<<<BATCH, 256>>>(logits, out);
}

// round 13
// speedup vs baseline: 1.5040x; 1.0325x over previous
#include <cuda_runtime.h>
#include <math.h>

// ---- problem constants ----
#define BATCH   8
#define TT      256
#define BT      2048          // BATCH*TT
#define DM      256           // d_model
#define DI      512           // d_inner
#define DS      16            // d_state
#define DTR     16            // dt_rank

typedef unsigned long long u64;

__device__ __forceinline__ u64 pk2(float lo, float hi) {
    u64 d;
    asm("mov.b64 %0, {%1, %2};" : "=l"(d)
        : "r"(__float_as_uint(lo)), "r"(__float_as_uint(hi)));
    return d;
}
__device__ __forceinline__ u64 ffma2(u64 a, u64 b, u64 c) {
    u64 d;
    asm("fma.rn.f32x2 %0, %1, %2, %3;" : "=l"(d) : "l"(a), "l"(b), "l"(c));
    return d;
}
__device__ __forceinline__ float2 upk2(u64 v) {
    unsigned lo, hi;
    asm("mov.b64 {%0, %1}, %2;" : "=r"(lo), "=r"(hi) : "l"(v));
    return make_float2(__uint_as_float(lo), __uint_as_float(hi));
}
union F4U { float4 f; u64 u[2]; };

// ---- scratch ----
__device__ float  g_h [BT*DM];
__device__ float  g_rms[BT];
__device__ float  g_xz[BT*2*DI];
__device__ float2 g_bc[BT*DS];
__device__ float2 g_du[BT*DI];
__device__ float  g_y [BT*DI];
__device__ float  g_hh[BT*64];
__device__ float  g_logits[BT];

// =====================================================================
// Fully fused CNN: conv1+conv2+conv3+pool+fc, one frame per block.
// Dynamic smem layout (floats):
//   f1   @ 0      : 16*33*34 = 17952   (conv1 output, padded)
//   bb   @ 17952  : 9792               (input 65x65, then f2 [32][17][18])
//   wbuf @ 27744  : 4608               (staged weights)
//   zsh  @ 32352  : 32                 (pooled features)
// total 32384 floats = 129536 B
// =====================================================================
#define CNN_F1   0
#define CNN_BB   17952
#define CNN_WB   27744
#define CNN_ZS   32352
#define CNN_SMEM (32384*4)

__global__ __launch_bounds__(256) void cnn_kernel(
    const float* __restrict__ x,
    const float* __restrict__ w1, const float* __restrict__ b1,
    const float* __restrict__ w2, const float* __restrict__ b2,
    const float* __restrict__ w3, const float* __restrict__ b3,
    const float* __restrict__ fcw, const float* __restrict__ fcb,
    float* __restrict__ h)
{
    extern __shared__ __align__(16) float smem[];
    float* f1   = smem + CNN_F1;
    float* bb   = smem + CNN_BB;
    float* wbuf = smem + CNN_WB;
    float* zsh  = smem + CNN_ZS;
    int f = blockIdx.x;
    int tid = threadIdx.x;

    // ---- phase 0: load input (65x65 padded) + conv1 weights ----
    const float* xf = x + (size_t)f*4096;
    for (int i = tid; i < 65*65; i += 256) {
        int r = i / 65, c = i - r*65;
        bb[i] = (r < 64 && c < 64) ? xf[r*64+c] : 0.f;
    }
    if (tid < 144) wbuf[tid] = w1[tid];
    if (tid < 16)  wbuf[144+tid] = b1[tid];
    __syncthreads();

    // ---- phase 1: conv1 -> f1 (stride2 SAME, relu) ----
    {
        int xg = tid & 3;             // 8 ox each
        int oy = (tid >> 2) & 31;
        int ch = tid >> 7;            // 0..1 -> 8 co each
        u64 acc2[8][4];
        #pragma unroll
        for (int c = 0; c < 8; c++) {
            float bbv = wbuf[144 + ch*8 + c];
            u64 bp = pk2(bbv, bbv);
            #pragma unroll
            for (int p = 0; p < 4; p++) acc2[c][p] = bp;
        }
        int i0 = oy*2, j0 = xg*16;
        #pragma unroll
        for (int ky = 0; ky < 3; ky++) {
            const float* rp = bb + (i0+ky)*65 + j0;
            float r[17];
            #pragma unroll
            for (int t = 0; t < 17; t++) r[t] = rp[t];
            u64 pr[12];
            #pragma unroll
            for (int p = 0; p < 4; p++)
                #pragma unroll
                for (int l = 0; l < 3; l++)
                    pr[p*3+l] = pk2(r[p*4+l], r[p*4+l+2]);
            #pragma unroll
            for (int c = 0; c < 8; c++) {
                const float* wp = wbuf + (ch*8+c)*9 + ky*3;
                u64 wd0 = pk2(wp[0], wp[0]);
                u64 wd1 = pk2(wp[1], wp[1]);
                u64 wd2 = pk2(wp[2], wp[2]);
                #pragma unroll
                for (int p = 0; p < 4; p++) {
                    acc2[c][p] = ffma2(pr[p*3+0], wd0, acc2[c][p]);
                    acc2[c][p] = ffma2(pr[p*3+1], wd1, acc2[c][p]);
                    acc2[c][p] = ffma2(pr[p*3+2], wd2, acc2[c][p]);
                }
            }
        }
        #pragma unroll
        for (int c = 0; c < 8; c++)
            #pragma unroll
            for (int p = 0; p < 4; p++) {
                float2 v = upk2(acc2[c][p]);
                *(float2*)&f1[(ch*8+c)*1122 + oy*34 + xg*8 + 2*p]
                    = make_float2(fmaxf(v.x, 0.f), fmaxf(v.y, 0.f));
            }
    }
    // zero f1 pads: row 32 (all 34 cols) + col 32 (rows 0..31)
    for (int idx = tid; idx < 16*34; idx += 256) {
        int ci = idx / 34, j = idx - ci*34;
        f1[ci*1122 + 32*34 + j] = 0.f;
    }
    for (int idx = tid; idx < 16*32; idx += 256) {
        int ci = idx >> 5, i = idx & 31;
        f1[ci*1122 + i*34 + 32] = 0.f;
    }
    __syncthreads();

    // ---- phase 2: conv2 (16ci, weights staged once) ----
    {
        // stage all conv2 weights (4608 floats, natural order)
        for (int idx = tid; idx < 4608; idx += 256) wbuf[idx] = w2[idx];
        __syncthreads();

        int cg  = tid >> 5;      // 4 co each
        int lane = tid & 31;
        int oy2 = lane >> 1;     // 0..15
        int xh  = lane & 1;      // 8 ox each
        u64 acc2[4][4];
        #pragma unroll
        for (int c = 0; c < 4; c++) {
            float bbv = __ldg(&b2[cg*4+c]);
            u64 bp = pk2(bbv, bbv);
            #pragma unroll
            for (int p = 0; p < 4; p++) acc2[c][p] = bp;
        }
        #pragma unroll 1
        for (int ci = 0; ci < 16; ci++) {
            const float* base = f1 + ci*1122 + (2*oy2)*34 + xh*16;
            #pragma unroll
            for (int row = 0; row < 3; row++) {
                const float* rp = base + row*34;
                float r[17];
                #pragma unroll
                for (int t = 0; t < 17; t++) r[t] = rp[t];
                u64 pr[12];
                #pragma unroll
                for (int p = 0; p < 4; p++)
                    #pragma unroll
                    for (int l = 0; l < 3; l++)
                        pr[p*3+l] = pk2(r[p*4+l], r[p*4+l+2]);
                #pragma unroll
                for (int c = 0; c < 4; c++) {
                    const float* wp = wbuf + ((cg*4+c)*16 + ci)*9 + row*3;
                    u64 wd0 = pk2(wp[0], wp[0]);
                    u64 wd1 = pk2(wp[1], wp[1]);
                    u64 wd2 = pk2(wp[2], wp[2]);
                    #pragma unroll
                    for (int p = 0; p < 4; p++) {
                        acc2[c][p] = ffma2(pr[p*3+0], wd0, acc2[c][p]);
                        acc2[c][p] = ffma2(pr[p*3+1], wd1, acc2[c][p]);
                        acc2[c][p] = ffma2(pr[p*3+2], wd2, acc2[c][p]);
                    }
                }
            }
        }
        __syncthreads();   // f1/input reads done; bb free for f2
        // write f2 [32][17][18] with relu into bb
        #pragma unroll
        for (int c = 0; c < 4; c++)
            #pragma unroll
            for (int p = 0; p < 4; p++) {
                float2 v = upk2(acc2[c][p]);
                *(float2*)&bb[(cg*4+c)*306 + oy2*18 + xh*8 + 2*p]
                    = make_float2(fmaxf(v.x, 0.f), fmaxf(v.y, 0.f));
            }
        // zero f2 pads: row 16 (18 cols) + col 16 (rows 0..15)
        for (int idx = tid; idx < 32*18; idx += 256) {
            int co = idx / 18, j = idx - co*18;
            bb[co*306 + 16*18 + j] = 0.f;
        }
        for (int idx = tid; idx < 32*16; idx += 256) {
            int co = idx >> 4, i = idx & 15;
            bb[co*306 + i*18 + 16] = 0.f;
        }
    }

    // ---- phase 3: conv3 + relu + avg pool (2 weight passes of 16 ci) ----
    {
        int cg  = tid >> 5;       // 4 co each (one warp per cg)
        int oy3 = (tid >> 2) & 7;
        int xq  = tid & 3;        // 2 ox each
        u64 acc3[4];
        #pragma unroll
        for (int c = 0; c < 4; c++) {
            float bbv = __ldg(&b3[cg*4+c]);
            acc3[c] = pk2(bbv, bbv);
        }
        #pragma unroll 1
        for (int pass = 0; pass < 2; pass++) {
            int ci0 = pass*16;
            __syncthreads();
            for (int idx = tid; idx < 4608; idx += 256) {
                int co = idx / 144;
                int rem = idx - co*144;
                int ci_l = rem / 9, k = rem - ci_l*9;
                wbuf[idx] = w3[(co*32 + ci0 + ci_l)*9 + k];
            }
            __syncthreads();
            #pragma unroll 1
            for (int ci = 0; ci < 16; ci++) {
                const float* base = bb + (ci0+ci)*306 + (2*oy3)*18 + xq*4;
                #pragma unroll
                for (int row = 0; row < 3; row++) {
                    const float* rp = base + row*18;
                    float r[5];
                    #pragma unroll
                    for (int q = 0; q < 5; q++) r[q] = rp[q];
                    u64 p0 = pk2(r[0], r[2]);
                    u64 p1 = pk2(r[1], r[3]);
                    u64 p2 = pk2(r[2], r[4]);
                    #pragma unroll
                    for (int c = 0; c < 4; c++) {
                        const float* wp = wbuf + ((cg*4+c)*16 + ci)*9 + row*3;
                        u64 wd0 = pk2(wp[0], wp[0]);
                        u64 wd1 = pk2(wp[1], wp[1]);
                        u64 wd2 = pk2(wp[2], wp[2]);
                        acc3[c] = ffma2(p0, wd0, acc3[c]);
                        acc3[c] = ffma2(p1, wd1, acc3[c]);
                        acc3[c] = ffma2(p2, wd2, acc3[c]);
                    }
                }
            }
        }
        // pool: reduce over the 32 lanes of this cg-warp
        #pragma unroll
        for (int c = 0; c < 4; c++) {
            float2 v = upk2(acc3[c]);
            float s = fmaxf(v.x, 0.f) + fmaxf(v.y, 0.f);
            #pragma unroll
            for (int o = 16; o > 0; o >>= 1) s += __shfl_down_sync(0xffffffffu, s, o);
            if ((tid & 31) == 0) zsh[cg*4 + c] = s * (1.f/64.f);
        }
    }
    __syncthreads();

    // ---- phase 4: fc 32 -> 256 ----
    {
        int j = tid;
        float a = __ldg(&fcb[j]);
        const float4* wp = (const float4*)(fcw + j*32);
        #pragma unroll
        for (int k = 0; k < 8; k++) {
            float4 wv = __ldg(&wp[k]);
            const float* zk = zsh + k*4;
            a = fmaf(zk[0],wv.x, fmaf(zk[1],wv.y, fmaf(zk[2],wv.z, fmaf(zk[3],wv.w, a))));
        }
        h[(size_t)f*256 + j] = a;
    }
}

// =====================================================================
// Mamba pieces (round-12 measured-best, unchanged)
// =====================================================================
__global__ __launch_bounds__(256) void rms_scale_kernel(const float* __restrict__ x,
                               float* __restrict__ sc)
{
    int tok = blockIdx.x*8 + (threadIdx.x >> 5);
    int lane = threadIdx.x & 31;
    const float4* xr = (const float4*)(x + (size_t)tok*256);
    float4 v0 = xr[lane*2], v1 = xr[lane*2+1];
    float ss = v0.x*v0.x + v0.y*v0.y + v0.z*v0.z + v0.w*v0.w
             + v1.x*v1.x + v1.y*v1.y + v1.z*v1.z + v1.w*v1.w;
    #pragma unroll
    for (int o = 16; o > 0; o >>= 1) ss += __shfl_xor_sync(0xffffffffu, ss, o);
    if (lane == 0) sc[tok] = rsqrtf(ss * (1.f/256.f) + 1e-5f);
}

// tile 128x128, 256 thr, 8x8 micro, f32x2, Kt=16, prefetch; A normalized on load.
__global__ __launch_bounds__(256) void gemm128_kernel(const float* __restrict__ A,
                              const float* __restrict__ scale,
                              const float* __restrict__ nw,
                              const float* __restrict__ W,
                              float* __restrict__ C,
                              int M, int N, int K)
{
    __shared__ __align__(16) float As[16][132];
    __shared__ __align__(16) float Ws[16][132];
    int bm = blockIdx.y * 128;
    int bn = blockIdx.x * 128;
    int tid = threadIdx.x;
    int tx = tid & 15, ty = tid >> 4;
    int r0 = tid >> 2, c0 = tid & 3;
    int r1 = r0 + 64;
    const float* Ap0 = &A[(size_t)(bm+r0)*K + c0*4];
    const float* Ap1 = &A[(size_t)(bm+r1)*K + c0*4];
    const float* Wp0 = &W[(size_t)(bn+r0)*K + c0*4];
    const float* Wp1 = &W[(size_t)(bn+r1)*K + c0*4];
    float sc0 = __ldg(&scale[bm+r0]);
    float sc1 = __ldg(&scale[bm+r1]);
    float4 va0 = *(const float4*)Ap0, va1 = *(const float4*)Ap1;
    float4 vw0 = *(const float4*)Wp0, vw1 = *(const float4*)Wp1;
    float4 vnw = *(const float4*)&nw[c0*4];
    u64 acc[4][8];
    #pragma unroll
    for (int i = 0; i < 4; i++)
        #pragma unroll
        for (int j = 0; j < 8; j++) acc[i][j] = 0ull;
    for (int k0 = 0; k0 < K; k0 += 16) {
        #pragma unroll
        for (int i = 0; i < 4; i++) {
            float nv = (&vnw.x)[i];
            As[c0*4+i][r0] = (&va0.x)[i] * sc0 * nv;
            As[c0*4+i][r1] = (&va1.x)[i] * sc1 * nv;
            Ws[c0*4+i][r0] = (&vw0.x)[i];
            Ws[c0*4+i][r1] = (&vw1.x)[i];
        }
        __syncthreads();
        if (k0 + 16 < K) {
            va0 = *(const float4*)(Ap0 + k0 + 16);
            va1 = *(const float4*)(Ap1 + k0 + 16);
            vw0 = *(const float4*)(Wp0 + k0 + 16);
            vw1 = *(const float4*)(Wp1 + k0 + 16);
            vnw = *(const float4*)&nw[k0 + 16 + c0*4];
        }
        #pragma unroll
        for (int k = 0; k < 16; k++) {
            F4U au0, au1;
            au0.f = *(const float4*)&As[k][ty*8];
            au1.f = *(const float4*)&As[k][ty*8+4];
            float4 w0 = *(const float4*)&Ws[k][tx*8];
            float4 w1 = *(const float4*)&Ws[k][tx*8+4];
            u64 wv[8];
            wv[0] = pk2(w0.x, w0.x); wv[1] = pk2(w0.y, w0.y);
            wv[2] = pk2(w0.z, w0.z); wv[3] = pk2(w0.w, w0.w);
            wv[4] = pk2(w1.x, w1.x); wv[5] = pk2(w1.y, w1.y);
            wv[6] = pk2(w1.z, w1.z); wv[7] = pk2(w1.w, w1.w);
            u64 ap[4] = { au0.u[0], au0.u[1], au1.u[0], au1.u[1] };
            #pragma unroll
            for (int i = 0; i < 4; i++)
                #pragma unroll
                for (int j = 0; j < 8; j++)
                    acc[i][j] = ffma2(ap[i], wv[j], acc[i][j]);
        }
        __syncthreads();
    }
    #pragma unroll
    for (int i = 0; i < 4; i++) {
        int m0 = bm + ty*8 + 2*i;
        float lo[8], hi[8];
        #pragma unroll
        for (int j = 0; j < 8; j++) {
            float2 v = upk2(acc[i][j]);
            lo[j] = v.x; hi[j] = v.y;
        }
        float* c0p = &C[(size_t)m0*N + bn + tx*8];
        float* c1p = &C[(size_t)(m0+1)*N + bn + tx*8];
        *(float4*)c0p       = make_float4(lo[0], lo[1], lo[2], lo[3]);
        *(float4*)(c0p + 4) = make_float4(lo[4], lo[5], lo[6], lo[7]);
        *(float4*)c1p       = make_float4(hi[0], hi[1], hi[2], hi[3]);
        *(float4*)(c1p + 4) = make_float4(hi[4], hi[5], hi[6], hi[7]);
    }
}

// tile 64x64, 256 thr, 16 outputs, f32x2, Kt=16, prefetch.
// EPI: 1 accumulate, 2 bias+gelu. NORM: A*scale[m]*nw[k] on load.
template<int EPI, int NORM>
__global__ __launch_bounds__(256) void gemm64_kernel(const float* __restrict__ A,
                              const float* __restrict__ scale,
                              const float* __restrict__ nw,
                              const float* __restrict__ W,
                              const float* __restrict__ bias,
                              float* __restrict__ C,
                              int M, int N, int K)
{
    __shared__ __align__(16) float As[16][68];
    __shared__ __align__(16) float Ws[16][68];
    int bm = blockIdx.y * 64;
    int bn = blockIdx.x * 64;
    int tid = threadIdx.x;
    int tx = tid & 15, ty = tid >> 4;
    int r = tid >> 2, c = tid & 3;
    const float* Ap = &A[(size_t)(bm+r)*K + c*4];
    const float* Wp = &W[(size_t)(bn+r)*K + c*4];
    float4 va = *(const float4*)Ap;
    float4 vw = *(const float4*)Wp;
    float sc = 1.f;
    float4 vnw;
    if (NORM) {
        sc = __ldg(&scale[bm+r]);
        vnw = *(const float4*)&nw[c*4];
    }
    u64 acc[2][4];
    #pragma unroll
    for (int p = 0; p < 2; p++)
        #pragma unroll
        for (int j = 0; j < 4; j++) acc[p][j] = 0ull;
    for (int k0 = 0; k0 < K; k0 += 16) {
        #pragma unroll
        for (int i = 0; i < 4; i++) {
            float av = (&va.x)[i];
            if (NORM) av *= sc * (&vnw.x)[i];
            As[c*4+i][r] = av;
            Ws[c*4+i][r] = (&vw.x)[i];
        }
        __syncthreads();
        if (k0 + 16 < K) {
            va = *(const float4*)(Ap + k0 + 16);
            vw = *(const float4*)(Wp + k0 + 16);
            if (NORM) vnw = *(const float4*)&nw[k0 + 16 + c*4];
        }
        #pragma unroll
        for (int k = 0; k < 16; k++) {
            F4U au;
            au.f = *(const float4*)&As[k][ty*4];
            float4 w4 = *(const float4*)&Ws[k][tx*4];
            u64 wv0 = pk2(w4.x, w4.x);
            u64 wv1 = pk2(w4.y, w4.y);
            u64 wv2 = pk2(w4.z, w4.z);
            u64 wv3 = pk2(w4.w, w4.w);
            acc[0][0] = ffma2(au.u[0], wv0, acc[0][0]);
            acc[0][1] = ffma2(au.u[0], wv1, acc[0][1]);
            acc[0][2] = ffma2(au.u[0], wv2, acc[0][2]);
            acc[0][3] = ffma2(au.u[0], wv3, acc[0][3]);
            acc[1][0] = ffma2(au.u[1], wv0, acc[1][0]);
            acc[1][1] = ffma2(au.u[1], wv1, acc[1][1]);
            acc[1][2] = ffma2(au.u[1], wv2, acc[1][2]);
            acc[1][3] = ffma2(au.u[1], wv3, acc[1][3]);
        }
        __syncthreads();
    }
    #pragma unroll
    for (int p = 0; p < 2; p++) {
        int m0 = bm + ty*4 + 2*p;
        float lo[4], hi[4];
        #pragma unroll
        for (int j = 0; j < 4; j++) {
            float2 v = upk2(acc[p][j]);
            lo[j] = v.x; hi[j] = v.y;
        }
        size_t base0 = (size_t)m0*N + bn + tx*4;
        size_t base1 = (size_t)(m0+1)*N + bn + tx*4;
        if (EPI == 1) {
            float4 o0 = *(float4*)&C[base0];
            float4 o1 = *(float4*)&C[base1];
            o0.x += lo[0]; o0.y += lo[1]; o0.z += lo[2]; o0.w += lo[3];
            o1.x += hi[0]; o1.y += hi[1]; o1.z += hi[2]; o1.w += hi[3];
            *(float4*)&C[base0] = o0;
            *(float4*)&C[base1] = o1;
        } else {
            float4 o0, o1;
            float* p0 = &o0.x;
            float* p1 = &o1.x;
            #pragma unroll
            for (int j = 0; j < 4; j++) {
                float bb = bias[bn + tx*4 + j];
                float v = lo[j] + bb;
                float v3 = v*v*v;
                p0[j] = 0.5f * v * (1.f + tanhf(0.7978845608028654f * (v + 0.044715f*v3)));
                v = hi[j] + bb;
                v3 = v*v*v;
                p1[j] = 0.5f * v * (1.f + tanhf(0.7978845608028654f * (v + 0.044715f*v3)));
            }
            *(float4*)&C[base0] = o0;
            *(float4*)&C[base1] = o1;
        }
    }
}

// Fused conv1d+silu + x_proj + dt_proj: per block 16 tokens.
#define SXIDX(tok, k) ((tok)*512 + (((k) + (tok)*4) & 511))
__global__ __launch_bounds__(256) void xproj_fused_kernel(
    const float* __restrict__ xz,
    const float* __restrict__ cw,
    const float* __restrict__ cb,
    const float* __restrict__ xpw,
    const float* __restrict__ dpw,
    const float* __restrict__ dpb,
    float2* __restrict__ bc,
    float2* __restrict__ du)
{
    __shared__ __align__(16) float sx[16*512];
    __shared__ __align__(16) float buf[48*68];
    __shared__ __align__(16) float sdt[16*16];
    int tok0 = blockIdx.x * 16;
    int tid = threadIdx.x;

    for (int idx = tid; idx < 2048; idx += 256) {
        int e = idx >> 2, k = idx & 3;
        buf[k*512 + e] = cw[idx];
    }
    for (int idx = tid; idx < 512; idx += 256) buf[2048 + idx] = cb[idx];
    __syncthreads();
    int tl0 = tok0 & 255;
    #pragma unroll 1
    for (int s = 0; s < 8; s++) {
        int q = tid + s*256;
        int t = q >> 7;
        int e = (q & 127)*4;
        float4 acc = *(const float4*)&buf[2048 + e];
        #pragma unroll
        for (int k = 0; k < 4; k++) {
            if (tl0 + t - 3 + k >= 0) {
                float4 xv = *(const float4*)&xz[(size_t)(tok0 + t - 3 + k)*1024 + e];
                float4 wv = *(const float4*)&buf[k*512 + e];
                acc.x = fmaf(xv.x, wv.x, acc.x);
                acc.y = fmaf(xv.y, wv.y, acc.y);
                acc.z = fmaf(xv.z, wv.z, acc.z);
                acc.w = fmaf(xv.w, wv.w, acc.w);
            }
        }
        acc.x = acc.x / (1.f + __expf(-acc.x));
        acc.y = acc.y / (1.f + __expf(-acc.y));
        acc.z = acc.z / (1.f + __expf(-acc.z));
        acc.w = acc.w / (1.f + __expf(-acc.w));
        *(float4*)&sx[SXIDX(t, e)] = acc;
    }

    int tg = tid & 15;
    int jg = tid >> 4;
    int rot = tg*4;
    const float* sxr = sx + tg*512;
    float acc0 = 0.f, acc1 = 0.f, acc2 = 0.f;
    #pragma unroll 1
    for (int kc = 0; kc < 8; kc++) {
        int k0 = kc*64;
        __syncthreads();
        #pragma unroll
        for (int s = 0; s < 3; s++) {
            int q = tid + s*256;
            int r = q >> 4, c = q & 15;
            float4 v = *(const float4*)&xpw[(size_t)r*512 + k0 + c*4];
            float* dst = buf + r*68 + c*4;
            dst[0]=v.x; dst[1]=v.y; dst[2]=v.z; dst[3]=v.w;
        }
        __syncthreads();
        const float* w0 = buf + (jg*3+0)*68;
        const float* w1 = buf + (jg*3+1)*68;
        const float* w2 = buf + (jg*3+2)*68;
        #pragma unroll
        for (int k4 = 0; k4 < 16; k4++) {
            int kk = (k0 + k4*4 + rot) & 511;
            float4 xv = *(const float4*)&sxr[kk];
            float4 a4 = *(const float4*)&w0[k4*4];
            float4 b4 = *(const float4*)&w1[k4*4];
            float4 c4 = *(const float4*)&w2[k4*4];
            acc0 = fmaf(xv.x,a4.x, fmaf(xv.y,a4.y, fmaf(xv.z,a4.z, fmaf(xv.w,a4.w, acc0))));
            acc1 = fmaf(xv.x,b4.x, fmaf(xv.y,b4.y, fmaf(xv.z,b4.z, fmaf(xv.w,b4.w, acc1))));
            acc2 = fmaf(xv.x,c4.x, fmaf(xv.y,c4.y, fmaf(xv.z,c4.z, fmaf(xv.w,c4.w, acc2))));
        }
    }
    {
        float av[3] = {acc0, acc1, acc2};
        #pragma unroll
        for (int jj = 0; jj < 3; jj++) {
            int j = jg*3 + jj;
            float v = av[jj];
            int tok = tok0 + tg;
            if (j < 16)       sdt[tg*16 + j] = v;
            else if (j < 32)  bc[tok*16 + (j-16)].x = v;
            else              bc[tok*16 + (j-32)].y = v;
        }
    }

    #pragma unroll 1
    for (int ec = 0; ec < 4; ec++) {
        int e0 = ec*128;
        __syncthreads();
        #pragma unroll
        for (int s = 0; s < 2; s++) {
            int q = tid + s*256;
            int r = q >> 2, c = q & 3;
            float4 v = *(const float4*)&dpw[(size_t)(e0+r)*16 + c*4];
            float* dst = buf + r*16 + c*4;
            dst[0]=v.x; dst[1]=v.y; dst[2]=v.z; dst[3]=v.w;
        }
        __syncthreads();
        #pragma unroll 1
        for (int s = 0; s < 8; s++) {
            int idx = tid + s*256;
            int e_l = idx & 127;
            int tok = idx >> 7;
            int e = e0 + e_l;
            const float* dr = sdt + tok*16;
            const float* wr = buf + e_l*16;
            float a = dpb[e];
            #pragma unroll
            for (int k = 0; k < 16; k++) a = fmaf(dr[k], wr[k], a);
            float sp = (a > 20.f) ? a : log1pf(expf(a));
            float u = sx[SXIDX(tok, e)];
            du[(size_t)(tok0+tok)*512 + e] = make_float2(sp, u);
        }
    }
}

// Selective scan: chunked register prefetch + pipelined shfl reduction
__global__ __launch_bounds__(256) void scan_kernel(const float2* __restrict__ du,
                            const float* __restrict__ xz,
                            const float2* __restrict__ bc,
                            const float* __restrict__ A_log,
                            const float* __restrict__ Dp,
                            float* __restrict__ yout)
{
    int tid = blockIdx.x * blockDim.x + threadIdx.x;
    int ch = tid >> 4;
    int n = tid & 15;
    int b = ch >> 9;
    int e = ch & 511;
    float A  = -expf(A_log[e*16 + n]);
    float Dv = Dp[e];
    const float2* duP = du + (size_t)(b*256)*512 + e;
    const float2* bcP = bc + (size_t)(b*256)*16 + n;
    const float*  zP  = xz + (size_t)(b*256)*1024 + 512 + e;
    float* yP = yout + (size_t)(b*256)*512 + e;

    float2 dv[2][8], bv[2][8];
    float  zv[2][8];
    #pragma unroll
    for (int i = 0; i < 8; i++) {
        dv[0][i] = duP[i*512];
        bv[0][i] = bcP[i*16];
    }
    if (n == 0) {
        #pragma unroll
        for (int i = 0; i < 8; i++) zv[0][i] = zP[i*1024];
    }
    float h = 0.f;
    int buf = 0;
    #pragma unroll 1
    for (int c = 0; c < 32; c++) {
        int nb = buf ^ 1;
        if (c < 31) {
            int t1 = c*8 + 8;
            #pragma unroll
            for (int i = 0; i < 8; i++) {
                dv[nb][i] = duP[(t1+i)*512];
                bv[nb][i] = bcP[(t1+i)*16];
            }
            if (n == 0) {
                #pragma unroll
                for (int i = 0; i < 8; i++) zv[nb][i] = zP[(size_t)(t1+i)*1024];
            }
        }
        float part[8];
        #pragma unroll
        for (int i = 0; i < 8; i++) {
            float2 duv = dv[buf][i];
            float2 bcv = bv[buf][i];
            float dA = __expf(duv.x * A);
            h = fmaf(h, dA, duv.x * bcv.x * duv.y);
            part[i] = h * bcv.y;
        }
        #pragma unroll
        for (int o = 8; o > 0; o >>= 1) {
            #pragma unroll
            for (int i = 0; i < 8; i++)
                part[i] += __shfl_down_sync(0xffffffffu, part[i], o, 16);
        }
        if (n == 0) {
            #pragma unroll
            for (int i = 0; i < 8; i++) {
                float z = zv[buf][i];
                float yy = part[i] + dv[buf][i].y * Dv;
                yP[(size_t)(c*8+i)*512] = yy * (z / (1.f + __expf(-z)));
            }
        }
        buf = nb;
    }
}

// =====================================================================
// Head tail
// =====================================================================
__global__ __launch_bounds__(256) void head2_kernel(const float* __restrict__ hh,
                             const float* __restrict__ w,
                             const float* __restrict__ b,
                             float* __restrict__ logits)
{
    int wid = (blockIdx.x * blockDim.x + threadIdx.x) >> 5;
    int lane = threadIdx.x & 31;
    const float* xr = hh + (size_t)wid*64;
    float acc = fmaf(xr[lane], w[lane], xr[lane+32]*w[lane+32]);
    #pragma unroll
    for (int o = 16; o > 0; o >>= 1) acc += __shfl_down_sync(0xffffffffu, acc, o);
    if (lane == 0) logits[wid] = acc + b[0];
}

__global__ __launch_bounds__(256) void softmax_kernel(const float* __restrict__ logits,
                               float* __restrict__ out)
{
    int b = blockIdx.x;
    int t = threadIdx.x;
    float v = logits[b*256 + t];
    __shared__ float red[8];
    __shared__ float sM, sS;
    float m = v;
    #pragma unroll
    for (int o = 16; o > 0; o >>= 1) m = fmaxf(m, __shfl_xor_sync(0xffffffffu, m, o));
    if ((t & 31) == 0) red[t >> 5] = m;
    __syncthreads();
    if (t < 8) {
        float mm = red[t];
        #pragma unroll
        for (int o = 4; o > 0; o >>= 1) mm = fmaxf(mm, __shfl_xor_sync(0xffu, mm, o, 8));
        if (t == 0) sM = mm;
    }
    __syncthreads();
    float e = expf(v - sM);
    float s = e;
    #pragma unroll
    for (int o = 16; o > 0; o >>= 1) s += __shfl_xor_sync(0xffffffffu, s, o);
    __syncthreads();
    if ((t & 31) == 0) red[t >> 5] = s;
    __syncthreads();
    if (t < 8) {
        float ss2 = red[t];
        #pragma unroll
        for (int o = 4; o > 0; o >>= 1) ss2 += __shfl_xor_sync(0xffu, ss2, o, 8);
        if (t == 0) sS = ss2;
    }
    __syncthreads();
    out[b*256 + t] = (t == 0) ? 0.f : e / sS;
}

// =====================================================================
// Launcher
// =====================================================================
extern "C" void kernel_launch(void* const* d_in, const int* in_sizes, int n_in,
                              void* d_out, int out_size)
{
    (void)in_sizes; (void)n_in; (void)out_size;
    const float* x        = (const float*)d_in[0];
    const float* cnn_w1   = (const float*)d_in[1];
    const float* cnn_b1   = (const float*)d_in[2];
    const float* cnn_w2   = (const float*)d_in[3];
    const float* cnn_b2   = (const float*)d_in[4];
    const float* cnn_w3   = (const float*)d_in[5];
    const float* cnn_b3   = (const float*)d_in[6];
    const float* fc_w     = (const float*)d_in[7];
    const float* fc_b     = (const float*)d_in[8];
    const float* norm_w   = (const float*)d_in[9];
    const float* in_proj_w= (const float*)d_in[10];
    const float* conv1d_w = (const float*)d_in[11];
    const float* conv1d_b = (const float*)d_in[12];
    const float* x_proj_w = (const float*)d_in[13];
    const float* dt_proj_w= (const float*)d_in[14];
    const float* dt_proj_b= (const float*)d_in[15];
    const float* A_log    = (const float*)d_in[16];
    const float* Dp       = (const float*)d_in[17];
    const float* out_proj_w=(const float*)d_in[18];
    const float* norm_f_w = (const float*)d_in[19];
    const float* head_w1  = (const float*)d_in[20];
    const float* head_b1  = (const float*)d_in[21];
    const float* head_w2  = (const float*)d_in[22];
    const float* head_b2  = (const float*)d_in[23];
    float* out = (float*)d_out;

    float *h, *rms, *xz, *y, *hh, *logits;
    float2 *bc, *du;
    cudaGetSymbolAddress((void**)&h,  g_h);
    cudaGetSymbolAddress((void**)&rms, g_rms);
    cudaGetSymbolAddress((void**)&xz, g_xz);
    cudaGetSymbolAddress((void**)&bc, g_bc);
    cudaGetSymbolAddress((void**)&du, g_du);
    cudaGetSymbolAddress((void**)&y,  g_y);
    cudaGetSymbolAddress((void**)&hh, g_hh);
    cudaGetSymbolAddress((void**)&logits, g_logits);

    cudaFuncSetAttribute(cnn_kernel,
        cudaFuncAttributeMaxDynamicSharedMemorySize, CNN_SMEM);

    // --- CNN encoder (fully fused) ---
    cnn_kernel<<<2048, 256, CNN_SMEM>>>(x, cnn_w1, cnn_b1, cnn_w2, cnn_b2,
                                        cnn_w3, cnn_b3, fc_w, fc_b, h);

    // --- Mamba layers ---
    for (int l = 0; l < 6; l++) {
        const float* nw  = norm_w     + (size_t)l*DM;
        const float* ipw = in_proj_w  + (size_t)l*2*DI*DM;
        const float* cw  = conv1d_w   + (size_t)l*DI*4;
        const float* cb  = conv1d_b   + (size_t)l*DI;
        const float* xpw = x_proj_w   + (size_t)l*48*DI;
        const float* dpw = dt_proj_w  + (size_t)l*DI*DTR;
        const float* dpb = dt_proj_b  + (size_t)l*DI;
        const float* al  = A_log      + (size_t)l*DI*DS;
        const float* dv  = Dp         + (size_t)l*DI;
        const float* opw = out_proj_w + (size_t)l*DM*DI;

        rms_scale_kernel<<<256, 256>>>(h, rms);
        gemm128_kernel<<<dim3(8, 16), 256>>>(h, rms, nw, ipw, xz, BT, 1024, 256);
        xproj_fused_kernel<<<128, 256>>>(xz, cw, cb, xpw, dpw, dpb, bc, du);
        scan_kernel<<<BATCH*DI*DS/256, 256>>>(du, xz, bc, al, dv, y);
        gemm64_kernel<1,0><<<dim3(4, 32), 256>>>(y, nullptr, nullptr, opw, nullptr, h, BT, 256, 512);
    }

    // --- Head ---
    rms_scale_kernel<<<256, 256>>>(h, rms);
    gemm64_kernel<2,1><<<dim3(1, 32), 256>>>(h, rms, norm_f_w, head_w1, head_b1, hh, BT, 64, 256);
    head2_kernel<<<BT*32/256, 256>>>(hh, head_w2, head_b2, logits);
    softmax_kernel<<<BATCH, 256>>>(logits, out);
}

// round 14
// speedup vs baseline: 1.5675x; 1.0423x over previous
#include <cuda_runtime.h>
#include <math.h>

// ---- problem constants ----
#define BATCH   8
#define TT      256
#define BT      2048          // BATCH*TT
#define DM      256           // d_model
#define DI      512           // d_inner
#define DS      16            // d_state
#define DTR     16            // dt_rank

typedef unsigned long long u64;

__device__ __forceinline__ u64 pk2(float lo, float hi) {
    u64 d;
    asm("mov.b64 %0, {%1, %2};" : "=l"(d)
        : "r"(__float_as_uint(lo)), "r"(__float_as_uint(hi)));
    return d;
}
__device__ __forceinline__ u64 ffma2(u64 a, u64 b, u64 c) {
    u64 d;
    asm("fma.rn.f32x2 %0, %1, %2, %3;" : "=l"(d) : "l"(a), "l"(b), "l"(c));
    return d;
}
__device__ __forceinline__ float2 upk2(u64 v) {
    unsigned lo, hi;
    asm("mov.b64 {%0, %1}, %2;" : "=r"(lo), "=r"(hi) : "l"(v));
    return make_float2(__uint_as_float(lo), __uint_as_float(hi));
}
union F4U { float4 f; u64 u[2]; };

// ---- scratch ----
__device__ float  g_h [BT*DM];
__device__ float  g_rms[BT];
__device__ float  g_xz[BT*2*DI];
__device__ float2 g_bc[BT*DS];
__device__ float2 g_du[BT*DI];
__device__ float  g_y [BT*DI];
__device__ float  g_hh[BT*64];
__device__ float  g_logits[BT];

// =====================================================================
// Fully fused CNN, 85KB smem (2 blocks/SM). conv1 produces 8 channels
// per pass; conv2 accumulates in registers across passes.
// Layout (floats):
//   bb   @0     : 9792  (input 65x65, later f2 [32][17][18])
//   f1h  @9792  : 8976  (8 x 33x34 conv1 half-output)
//   w2b  @18768 : 2304  (staged conv2/conv3 weights)
//   w1b  @21072 : 160   (conv1 w+b)
//   zsh  @21232 : 32
// =====================================================================
#define CNN_BB 0
#define CNN_F1 9792
#define CNN_W2 18768
#define CNN_W1 21072
#define CNN_ZS 21232
#define CNN_SMEM (21264*4)

__global__ __launch_bounds__(256) void cnn_kernel(
    const float* __restrict__ x,
    const float* __restrict__ w1, const float* __restrict__ b1,
    const float* __restrict__ w2, const float* __restrict__ b2,
    const float* __restrict__ w3, const float* __restrict__ b3,
    const float* __restrict__ fcw, const float* __restrict__ fcb,
    float* __restrict__ h)
{
    extern __shared__ __align__(16) float smem[];
    float* bb   = smem + CNN_BB;
    float* f1h  = smem + CNN_F1;
    float* w2b  = smem + CNN_W2;
    float* w1b  = smem + CNN_W1;
    float* zsh  = smem + CNN_ZS;
    int f = blockIdx.x;
    int tid = threadIdx.x;

    // ---- phase 0: input + conv1 weights ----
    const float* xf = x + (size_t)f*4096;
    for (int i = tid; i < 65*65; i += 256) {
        int r = i / 65, c = i - r*65;
        bb[i] = (r < 64 && c < 64) ? xf[r*64+c] : 0.f;
    }
    if (tid < 144) w1b[tid] = w1[tid];
    if (tid < 16)  w1b[144+tid] = b1[tid];

    // conv2 persistent accumulators
    int cg2  = tid >> 5;      // 4 co each
    int lane = tid & 31;
    int oy2 = lane >> 1;      // 0..15
    int xh  = lane & 1;       // 8 ox each
    u64 c2acc[4][4];
    #pragma unroll
    for (int c = 0; c < 4; c++) {
        float bbv = __ldg(&b2[cg2*4+c]);
        u64 bp = pk2(bbv, bbv);
        #pragma unroll
        for (int p = 0; p < 4; p++) c2acc[c][p] = bp;
    }

    // ---- conv1 (8 ch/pass) + conv2 accumulate ----
    #pragma unroll 1
    for (int pass = 0; pass < 2; pass++) {
        int ci0 = pass*8;
        __syncthreads();    // bb loaded / f1h,w2b free
        // conv1 for channels ci0..ci0+7 into f1h
        {
            int xg = tid & 3;
            int oy = (tid >> 2) & 31;
            int ch = tid >> 7;        // 0..1 -> 4 co each
            u64 acc1[4][4];
            #pragma unroll
            for (int c = 0; c < 4; c++) {
                float bbv = w1b[144 + ci0 + ch*4 + c];
                u64 bp = pk2(bbv, bbv);
                #pragma unroll
                for (int p = 0; p < 4; p++) acc1[c][p] = bp;
            }
            int i0 = oy*2, j0 = xg*16;
            #pragma unroll
            for (int ky = 0; ky < 3; ky++) {
                const float* rp = bb + (i0+ky)*65 + j0;
                float r[17];
                #pragma unroll
                for (int t = 0; t < 17; t++) r[t] = rp[t];
                u64 pr[12];
                #pragma unroll
                for (int p = 0; p < 4; p++)
                    #pragma unroll
                    for (int l = 0; l < 3; l++)
                        pr[p*3+l] = pk2(r[p*4+l], r[p*4+l+2]);
                #pragma unroll
                for (int c = 0; c < 4; c++) {
                    const float* wp = w1b + (ci0 + ch*4+c)*9 + ky*3;
                    u64 wd0 = pk2(wp[0], wp[0]);
                    u64 wd1 = pk2(wp[1], wp[1]);
                    u64 wd2 = pk2(wp[2], wp[2]);
                    #pragma unroll
                    for (int p = 0; p < 4; p++) {
                        acc1[c][p] = ffma2(pr[p*3+0], wd0, acc1[c][p]);
                        acc1[c][p] = ffma2(pr[p*3+1], wd1, acc1[c][p]);
                        acc1[c][p] = ffma2(pr[p*3+2], wd2, acc1[c][p]);
                    }
                }
            }
            #pragma unroll
            for (int c = 0; c < 4; c++)
                #pragma unroll
                for (int p = 0; p < 4; p++) {
                    float2 v = upk2(acc1[c][p]);
                    *(float2*)&f1h[(ch*4+c)*1122 + oy*34 + xg*8 + 2*p]
                        = make_float2(fmaxf(v.x, 0.f), fmaxf(v.y, 0.f));
                }
        }
        // zero f1h pads: row 32 + col 32
        for (int idx = tid; idx < 8*34; idx += 256) {
            int ci = idx / 34, j = idx - ci*34;
            f1h[ci*1122 + 32*34 + j] = 0.f;
        }
        for (int idx = tid; idx < 8*32; idx += 256) {
            int ci = idx >> 5, i = idx & 31;
            f1h[ci*1122 + i*34 + 32] = 0.f;
        }
        // stage conv2 weights for this ci range
        for (int idx = tid; idx < 2304; idx += 256) {
            int co = idx / 72;
            int rem = idx - co*72;
            int ci_l = rem / 9, k = rem - ci_l*9;
            w2b[idx] = w2[(co*16 + ci0 + ci_l)*9 + k];
        }
        __syncthreads();
        // conv2 accumulate over 8 local ci
        #pragma unroll 1
        for (int ci = 0; ci < 8; ci++) {
            const float* base = f1h + ci*1122 + (2*oy2)*34 + xh*16;
            #pragma unroll
            for (int row = 0; row < 3; row++) {
                const float* rp = base + row*34;
                float r[17];
                #pragma unroll
                for (int t = 0; t < 17; t++) r[t] = rp[t];
                u64 pr[12];
                #pragma unroll
                for (int p = 0; p < 4; p++)
                    #pragma unroll
                    for (int l = 0; l < 3; l++)
                        pr[p*3+l] = pk2(r[p*4+l], r[p*4+l+2]);
                #pragma unroll
                for (int c = 0; c < 4; c++) {
                    const float* wp = w2b + (cg2*4+c)*72 + ci*9 + row*3;
                    u64 wd0 = pk2(wp[0], wp[0]);
                    u64 wd1 = pk2(wp[1], wp[1]);
                    u64 wd2 = pk2(wp[2], wp[2]);
                    #pragma unroll
                    for (int p = 0; p < 4; p++) {
                        c2acc[c][p] = ffma2(pr[p*3+0], wd0, c2acc[c][p]);
                        c2acc[c][p] = ffma2(pr[p*3+1], wd1, c2acc[c][p]);
                        c2acc[c][p] = ffma2(pr[p*3+2], wd2, c2acc[c][p]);
                    }
                }
            }
        }
    }
    __syncthreads();   // input reads done; bb free for f2
    // write f2 [32][17][18] with relu into bb
    #pragma unroll
    for (int c = 0; c < 4; c++)
        #pragma unroll
        for (int p = 0; p < 4; p++) {
            float2 v = upk2(c2acc[c][p]);
            *(float2*)&bb[(cg2*4+c)*306 + oy2*18 + xh*8 + 2*p]
                = make_float2(fmaxf(v.x, 0.f), fmaxf(v.y, 0.f));
        }
    for (int idx = tid; idx < 32*18; idx += 256) {
        int co = idx / 18, j = idx - co*18;
        bb[co*306 + 16*18 + j] = 0.f;
    }
    for (int idx = tid; idx < 32*16; idx += 256) {
        int co = idx >> 4, i = idx & 15;
        bb[co*306 + i*18 + 16] = 0.f;
    }

    // ---- conv3 + relu + pool (4 weight passes of 8 ci) ----
    {
        int cg  = tid >> 5;
        int oy3 = (tid >> 2) & 7;
        int xq  = tid & 3;
        u64 acc3[4];
        #pragma unroll
        for (int c = 0; c < 4; c++) {
            float bbv = __ldg(&b3[cg*4+c]);
            acc3[c] = pk2(bbv, bbv);
        }
        #pragma unroll 1
        for (int pass = 0; pass < 4; pass++) {
            int ci0 = pass*8;
            __syncthreads();
            for (int idx = tid; idx < 2304; idx += 256) {
                int co = idx / 72;
                int rem = idx - co*72;
                int ci_l = rem / 9, k = rem - ci_l*9;
                w2b[idx] = w3[(co*32 + ci0 + ci_l)*9 + k];
            }
            __syncthreads();
            #pragma unroll 1
            for (int ci = 0; ci < 8; ci++) {
                const float* base = bb + (ci0+ci)*306 + (2*oy3)*18 + xq*4;
                #pragma unroll
                for (int row = 0; row < 3; row++) {
                    const float* rp = base + row*18;
                    float r[5];
                    #pragma unroll
                    for (int q = 0; q < 5; q++) r[q] = rp[q];
                    u64 p0 = pk2(r[0], r[2]);
                    u64 p1 = pk2(r[1], r[3]);
                    u64 p2 = pk2(r[2], r[4]);
                    #pragma unroll
                    for (int c = 0; c < 4; c++) {
                        const float* wp = w2b + (cg*4+c)*72 + ci*9 + row*3;
                        u64 wd0 = pk2(wp[0], wp[0]);
                        u64 wd1 = pk2(wp[1], wp[1]);
                        u64 wd2 = pk2(wp[2], wp[2]);
                        acc3[c] = ffma2(p0, wd0, acc3[c]);
                        acc3[c] = ffma2(p1, wd1, acc3[c]);
                        acc3[c] = ffma2(p2, wd2, acc3[c]);
                    }
                }
            }
        }
        #pragma unroll
        for (int c = 0; c < 4; c++) {
            float2 v = upk2(acc3[c]);
            float s = fmaxf(v.x, 0.f) + fmaxf(v.y, 0.f);
            #pragma unroll
            for (int o = 16; o > 0; o >>= 1) s += __shfl_down_sync(0xffffffffu, s, o);
            if ((tid & 31) == 0) zsh[cg*4 + c] = s * (1.f/64.f);
        }
    }
    __syncthreads();

    // ---- fc 32 -> 256 ----
    {
        int j = tid;
        float a = __ldg(&fcb[j]);
        const float4* wp = (const float4*)(fcw + j*32);
        #pragma unroll
        for (int k = 0; k < 8; k++) {
            float4 wv = __ldg(&wp[k]);
            const float* zk = zsh + k*4;
            a = fmaf(zk[0],wv.x, fmaf(zk[1],wv.y, fmaf(zk[2],wv.z, fmaf(zk[3],wv.w, a))));
        }
        h[(size_t)f*256 + j] = a;
    }
}

// =====================================================================
// Mamba pieces
// =====================================================================
__global__ __launch_bounds__(256) void rms_scale_kernel(const float* __restrict__ x,
                               float* __restrict__ sc)
{
    int tok = blockIdx.x*8 + (threadIdx.x >> 5);
    int lane = threadIdx.x & 31;
    const float4* xr = (const float4*)(x + (size_t)tok*256);
    float4 v0 = xr[lane*2], v1 = xr[lane*2+1];
    float ss = v0.x*v0.x + v0.y*v0.y + v0.z*v0.z + v0.w*v0.w
             + v1.x*v1.x + v1.y*v1.y + v1.z*v1.z + v1.w*v1.w;
    #pragma unroll
    for (int o = 16; o > 0; o >>= 1) ss += __shfl_xor_sync(0xffffffffu, ss, o);
    if (lane == 0) sc[tok] = rsqrtf(ss * (1.f/256.f) + 1e-5f);
}

// tile 128x128, 256 thr, 8x8 micro, f32x2, Kt=16, prefetch; A normalized on load.
__global__ __launch_bounds__(256) void gemm128_kernel(const float* __restrict__ A,
                              const float* __restrict__ scale,
                              const float* __restrict__ nw,
                              const float* __restrict__ W,
                              float* __restrict__ C,
                              int M, int N, int K)
{
    __shared__ __align__(16) float As[16][132];
    __shared__ __align__(16) float Ws[16][132];
    int bm = blockIdx.y * 128;
    int bn = blockIdx.x * 128;
    int tid = threadIdx.x;
    int tx = tid & 15, ty = tid >> 4;
    int r0 = tid >> 2, c0 = tid & 3;
    int r1 = r0 + 64;
    const float* Ap0 = &A[(size_t)(bm+r0)*K + c0*4];
    const float* Ap1 = &A[(size_t)(bm+r1)*K + c0*4];
    const float* Wp0 = &W[(size_t)(bn+r0)*K + c0*4];
    const float* Wp1 = &W[(size_t)(bn+r1)*K + c0*4];
    float sc0 = __ldg(&scale[bm+r0]);
    float sc1 = __ldg(&scale[bm+r1]);
    float4 va0 = *(const float4*)Ap0, va1 = *(const float4*)Ap1;
    float4 vw0 = *(const float4*)Wp0, vw1 = *(const float4*)Wp1;
    float4 vnw = *(const float4*)&nw[c0*4];
    u64 acc[4][8];
    #pragma unroll
    for (int i = 0; i < 4; i++)
        #pragma unroll
        for (int j = 0; j < 8; j++) acc[i][j] = 0ull;
    for (int k0 = 0; k0 < K; k0 += 16) {
        #pragma unroll
        for (int i = 0; i < 4; i++) {
            float nv = (&vnw.x)[i];
            As[c0*4+i][r0] = (&va0.x)[i] * sc0 * nv;
            As[c0*4+i][r1] = (&va1.x)[i] * sc1 * nv;
            Ws[c0*4+i][r0] = (&vw0.x)[i];
            Ws[c0*4+i][r1] = (&vw1.x)[i];
        }
        __syncthreads();
        if (k0 + 16 < K) {
            va0 = *(const float4*)(Ap0 + k0 + 16);
            va1 = *(const float4*)(Ap1 + k0 + 16);
            vw0 = *(const float4*)(Wp0 + k0 + 16);
            vw1 = *(const float4*)(Wp1 + k0 + 16);
            vnw = *(const float4*)&nw[k0 + 16 + c0*4];
        }
        #pragma unroll
        for (int k = 0; k < 16; k++) {
            F4U au0, au1;
            au0.f = *(const float4*)&As[k][ty*8];
            au1.f = *(const float4*)&As[k][ty*8+4];
            float4 w0 = *(const float4*)&Ws[k][tx*8];
            float4 w1 = *(const float4*)&Ws[k][tx*8+4];
            u64 wv[8];
            wv[0] = pk2(w0.x, w0.x); wv[1] = pk2(w0.y, w0.y);
            wv[2] = pk2(w0.z, w0.z); wv[3] = pk2(w0.w, w0.w);
            wv[4] = pk2(w1.x, w1.x); wv[5] = pk2(w1.y, w1.y);
            wv[6] = pk2(w1.z, w1.z); wv[7] = pk2(w1.w, w1.w);
            u64 ap[4] = { au0.u[0], au0.u[1], au1.u[0], au1.u[1] };
            #pragma unroll
            for (int i = 0; i < 4; i++)
                #pragma unroll
                for (int j = 0; j < 8; j++)
                    acc[i][j] = ffma2(ap[i], wv[j], acc[i][j]);
        }
        __syncthreads();
    }
    #pragma unroll
    for (int i = 0; i < 4; i++) {
        int m0 = bm + ty*8 + 2*i;
        float lo[8], hi[8];
        #pragma unroll
        for (int j = 0; j < 8; j++) {
            float2 v = upk2(acc[i][j]);
            lo[j] = v.x; hi[j] = v.y;
        }
        float* c0p = &C[(size_t)m0*N + bn + tx*8];
        float* c1p = &C[(size_t)(m0+1)*N + bn + tx*8];
        *(float4*)c0p       = make_float4(lo[0], lo[1], lo[2], lo[3]);
        *(float4*)(c0p + 4) = make_float4(lo[4], lo[5], lo[6], lo[7]);
        *(float4*)c1p       = make_float4(hi[0], hi[1], hi[2], hi[3]);
        *(float4*)(c1p + 4) = make_float4(hi[4], hi[5], hi[6], hi[7]);
    }
}

// tile 64x64, 256 thr, 16 outputs, f32x2, Kt=16, prefetch.
// EPI: 1 accumulate, 2 bias+gelu. NORM: A*scale[m]*nw[k] on load.
template<int EPI, int NORM>
__global__ __launch_bounds__(256) void gemm64_kernel(const float* __restrict__ A,
                              const float* __restrict__ scale,
                              const float* __restrict__ nw,
                              const float* __restrict__ W,
                              const float* __restrict__ bias,
                              float* __restrict__ C,
                              int M, int N, int K)
{
    __shared__ __align__(16) float As[16][68];
    __shared__ __align__(16) float Ws[16][68];
    int bm = blockIdx.y * 64;
    int bn = blockIdx.x * 64;
    int tid = threadIdx.x;
    int tx = tid & 15, ty = tid >> 4;
    int r = tid >> 2, c = tid & 3;
    const float* Ap = &A[(size_t)(bm+r)*K + c*4];
    const float* Wp = &W[(size_t)(bn+r)*K + c*4];
    float4 va = *(const float4*)Ap;
    float4 vw = *(const float4*)Wp;
    float sc = 1.f;
    float4 vnw;
    if (NORM) {
        sc = __ldg(&scale[bm+r]);
        vnw = *(const float4*)&nw[c*4];
    }
    u64 acc[2][4];
    #pragma unroll
    for (int p = 0; p < 2; p++)
        #pragma unroll
        for (int j = 0; j < 4; j++) acc[p][j] = 0ull;
    for (int k0 = 0; k0 < K; k0 += 16) {
        #pragma unroll
        for (int i = 0; i < 4; i++) {
            float av = (&va.x)[i];
            if (NORM) av *= sc * (&vnw.x)[i];
            As[c*4+i][r] = av;
            Ws[c*4+i][r] = (&vw.x)[i];
        }
        __syncthreads();
        if (k0 + 16 < K) {
            va = *(const float4*)(Ap + k0 + 16);
            vw = *(const float4*)(Wp + k0 + 16);
            if (NORM) vnw = *(const float4*)&nw[k0 + 16 + c*4];
        }
        #pragma unroll
        for (int k = 0; k < 16; k++) {
            F4U au;
            au.f = *(const float4*)&As[k][ty*4];
            float4 w4 = *(const float4*)&Ws[k][tx*4];
            u64 wv0 = pk2(w4.x, w4.x);
            u64 wv1 = pk2(w4.y, w4.y);
            u64 wv2 = pk2(w4.z, w4.z);
            u64 wv3 = pk2(w4.w, w4.w);
            acc[0][0] = ffma2(au.u[0], wv0, acc[0][0]);
            acc[0][1] = ffma2(au.u[0], wv1, acc[0][1]);
            acc[0][2] = ffma2(au.u[0], wv2, acc[0][2]);
            acc[0][3] = ffma2(au.u[0], wv3, acc[0][3]);
            acc[1][0] = ffma2(au.u[1], wv0, acc[1][0]);
            acc[1][1] = ffma2(au.u[1], wv1, acc[1][1]);
            acc[1][2] = ffma2(au.u[1], wv2, acc[1][2]);
            acc[1][3] = ffma2(au.u[1], wv3, acc[1][3]);
        }
        __syncthreads();
    }
    #pragma unroll
    for (int p = 0; p < 2; p++) {
        int m0 = bm + ty*4 + 2*p;
        float lo[4], hi[4];
        #pragma unroll
        for (int j = 0; j < 4; j++) {
            float2 v = upk2(acc[p][j]);
            lo[j] = v.x; hi[j] = v.y;
        }
        size_t base0 = (size_t)m0*N + bn + tx*4;
        size_t base1 = (size_t)(m0+1)*N + bn + tx*4;
        if (EPI == 1) {
            float4 o0 = *(float4*)&C[base0];
            float4 o1 = *(float4*)&C[base1];
            o0.x += lo[0]; o0.y += lo[1]; o0.z += lo[2]; o0.w += lo[3];
            o1.x += hi[0]; o1.y += hi[1]; o1.z += hi[2]; o1.w += hi[3];
            *(float4*)&C[base0] = o0;
            *(float4*)&C[base1] = o1;
        } else {
            float4 o0, o1;
            float* p0 = &o0.x;
            float* p1 = &o1.x;
            #pragma unroll
            for (int j = 0; j < 4; j++) {
                float bb = bias[bn + tx*4 + j];
                float v = lo[j] + bb;
                float v3 = v*v*v;
                p0[j] = 0.5f * v * (1.f + tanhf(0.7978845608028654f * (v + 0.044715f*v3)));
                v = hi[j] + bb;
                v3 = v*v*v;
                p1[j] = 0.5f * v * (1.f + tanhf(0.7978845608028654f * (v + 0.044715f*v3)));
            }
            *(float4*)&C[base0] = o0;
            *(float4*)&C[base1] = o1;
        }
    }
}

// Fused conv1d+silu + x_proj + dt_proj: 16 tokens/block, double-buffered weights.
#define SXIDX(tok, k) ((tok)*512 + (((k) + (tok)*4) & 511))
__global__ __launch_bounds__(256) void xproj_fused_kernel(
    const float* __restrict__ xz,
    const float* __restrict__ cw,
    const float* __restrict__ cb,
    const float* __restrict__ xpw,
    const float* __restrict__ dpw,
    const float* __restrict__ dpb,
    float2* __restrict__ bc,
    float2* __restrict__ du)
{
    __shared__ __align__(16) float sx[16*512];
    __shared__ __align__(16) float bufA[48*68];
    __shared__ __align__(16) float bufB[48*68];
    __shared__ __align__(16) float sdt[16*16];
    float* bufs[2] = { bufA, bufB };
    int tok0 = blockIdx.x * 16;
    int tid = threadIdx.x;

    // ---- conv1d + silu from xz into sx (conv weights in bufA) ----
    for (int idx = tid; idx < 2048; idx += 256) {
        int e = idx >> 2, k = idx & 3;
        bufA[k*512 + e] = cw[idx];
    }
    for (int idx = tid; idx < 512; idx += 256) bufA[2048 + idx] = cb[idx];
    __syncthreads();
    int tl0 = tok0 & 255;
    #pragma unroll 1
    for (int s = 0; s < 8; s++) {
        int q = tid + s*256;
        int t = q >> 7;
        int e = (q & 127)*4;
        float4 acc = *(const float4*)&bufA[2048 + e];
        #pragma unroll
        for (int k = 0; k < 4; k++) {
            if (tl0 + t - 3 + k >= 0) {
                float4 xv = *(const float4*)&xz[(size_t)(tok0 + t - 3 + k)*1024 + e];
                float4 wv = *(const float4*)&bufA[k*512 + e];
                acc.x = fmaf(xv.x, wv.x, acc.x);
                acc.y = fmaf(xv.y, wv.y, acc.y);
                acc.z = fmaf(xv.z, wv.z, acc.z);
                acc.w = fmaf(xv.w, wv.w, acc.w);
            }
        }
        acc.x = acc.x / (1.f + __expf(-acc.x));
        acc.y = acc.y / (1.f + __expf(-acc.y));
        acc.z = acc.z / (1.f + __expf(-acc.z));
        acc.w = acc.w / (1.f + __expf(-acc.w));
        *(float4*)&sx[SXIDX(t, e)] = acc;
    }

    // ---- Phase A: dbc = xin . xpw^T, double-buffered w chunks ----
    int tg = tid & 15;
    int jg = tid >> 4;
    int rot = tg*4;
    const float* sxr = sx + tg*512;
    int wr_ = tid >> 4, wc_ = tid & 15;   // loader: 3 float4 per thread per chunk
    float4 pre0 = *(const float4*)&xpw[(size_t)(wr_   )*512 + wc_*4];
    float4 pre1 = *(const float4*)&xpw[(size_t)(wr_+16)*512 + wc_*4];
    float4 pre2 = *(const float4*)&xpw[(size_t)(wr_+32)*512 + wc_*4];
    __syncthreads();   // conv1d reads of bufA done
    {
        float* d0 = bufA + (wr_   )*68 + wc_*4;
        float* d1 = bufA + (wr_+16)*68 + wc_*4;
        float* d2 = bufA + (wr_+32)*68 + wc_*4;
        d0[0]=pre0.x; d0[1]=pre0.y; d0[2]=pre0.z; d0[3]=pre0.w;
        d1[0]=pre1.x; d1[1]=pre1.y; d1[2]=pre1.z; d1[3]=pre1.w;
        d2[0]=pre2.x; d2[1]=pre2.y; d2[2]=pre2.z; d2[3]=pre2.w;
    }
    __syncthreads();
    float acc0 = 0.f, acc1 = 0.f, acc2 = 0.f;
    #pragma unroll 1
    for (int kc = 0; kc < 8; kc++) {
        int k0 = kc*64;
        if (kc < 7) {
            int kn = k0 + 64;
            pre0 = *(const float4*)&xpw[(size_t)(wr_   )*512 + kn + wc_*4];
            pre1 = *(const float4*)&xpw[(size_t)(wr_+16)*512 + kn + wc_*4];
            pre2 = *(const float4*)&xpw[(size_t)(wr_+32)*512 + kn + wc_*4];
        }
        const float* cur = bufs[kc & 1];
        const float* w0 = cur + (jg*3+0)*68;
        const float* w1 = cur + (jg*3+1)*68;
        const float* w2 = cur + (jg*3+2)*68;
        #pragma unroll
        for (int k4 = 0; k4 < 16; k4++) {
            int kk = (k0 + k4*4 + rot) & 511;
            float4 xv = *(const float4*)&sxr[kk];
            float4 a4 = *(const float4*)&w0[k4*4];
            float4 b4 = *(const float4*)&w1[k4*4];
            float4 c4 = *(const float4*)&w2[k4*4];
            acc0 = fmaf(xv.x,a4.x, fmaf(xv.y,a4.y, fmaf(xv.z,a4.z, fmaf(xv.w,a4.w, acc0))));
            acc1 = fmaf(xv.x,b4.x, fmaf(xv.y,b4.y, fmaf(xv.z,b4.z, fmaf(xv.w,b4.w, acc1))));
            acc2 = fmaf(xv.x,c4.x, fmaf(xv.y,c4.y, fmaf(xv.z,c4.z, fmaf(xv.w,c4.w, acc2))));
        }
        if (kc < 7) {
            float* nxt = bufs[(kc+1) & 1];
            float* d0 = nxt + (wr_   )*68 + wc_*4;
            float* d1 = nxt + (wr_+16)*68 + wc_*4;
            float* d2 = nxt + (wr_+32)*68 + wc_*4;
            d0[0]=pre0.x; d0[1]=pre0.y; d0[2]=pre0.z; d0[3]=pre0.w;
            d1[0]=pre1.x; d1[1]=pre1.y; d1[2]=pre1.z; d1[3]=pre1.w;
            d2[0]=pre2.x; d2[1]=pre2.y; d2[2]=pre2.z; d2[3]=pre2.w;
            __syncthreads();
        }
    }
    {
        float av[3] = {acc0, acc1, acc2};
        #pragma unroll
        for (int jj = 0; jj < 3; jj++) {
            int j = jg*3 + jj;
            float v = av[jj];
            int tok = tok0 + tg;
            if (j < 16)       sdt[tg*16 + j] = v;
            else if (j < 32)  bc[tok*16 + (j-16)].x = v;
            else              bc[tok*16 + (j-32)].y = v;
        }
    }

    // ---- Phase B: double-buffered dpw chunks (128x16 each) ----
    int dr_ = tid >> 1, dc_ = tid & 1;   // 256 float4 per chunk, 1 per thread
    float4 dpre = *(const float4*)&dpw[(size_t)dr_*16 + dc_*8];
    float4 dpre2 = *(const float4*)&dpw[(size_t)dr_*16 + dc_*8 + 4];
    __syncthreads();   // sdt written; bufA last read at kc=6
    {
        float* dst = bufA + dr_*16 + dc_*8;
        dst[0]=dpre.x; dst[1]=dpre.y; dst[2]=dpre.z; dst[3]=dpre.w;
        dst[4]=dpre2.x; dst[5]=dpre2.y; dst[6]=dpre2.z; dst[7]=dpre2.w;
    }
    __syncthreads();
    #pragma unroll 1
    for (int ec = 0; ec < 4; ec++) {
        int e0 = ec*128;
        if (ec < 3) {
            dpre  = *(const float4*)&dpw[(size_t)(e0+128+dr_)*16 + dc_*8];
            dpre2 = *(const float4*)&dpw[(size_t)(e0+128+dr_)*16 + dc_*8 + 4];
        }
        const float* cur = bufs[ec & 1];
        #pragma unroll 1
        for (int s = 0; s < 8; s++) {
            int idx = tid + s*256;
            int e_l = idx & 127;
            int tok = idx >> 7;
            int e = e0 + e_l;
            const float* dr = sdt + tok*16;
            const float* wr = cur + e_l*16;
            float a = dpb[e];
            #pragma unroll
            for (int k = 0; k < 16; k++) a = fmaf(dr[k], wr[k], a);
            float sp = (a > 20.f) ? a : log1pf(expf(a));
            float u = sx[SXIDX(tok, e)];
            du[(size_t)(tok0+tok)*512 + e] = make_float2(sp, u);
        }
        if (ec < 3) {
            float* nxt = bufs[(ec+1) & 1];
            float* dst = nxt + dr_*16 + dc_*8;
            dst[0]=dpre.x; dst[1]=dpre.y; dst[2]=dpre.z; dst[3]=dpre.w;
            dst[4]=dpre2.x; dst[5]=dpre2.y; dst[6]=dpre2.z; dst[7]=dpre2.w;
            __syncthreads();
        }
    }
}

// Selective scan: chunked register prefetch + pipelined shfl reduction
__global__ __launch_bounds__(256) void scan_kernel(const float2* __restrict__ du,
                            const float* __restrict__ xz,
                            const float2* __restrict__ bc,
                            const float* __restrict__ A_log,
                            const float* __restrict__ Dp,
                            float* __restrict__ yout)
{
    int tid = blockIdx.x * blockDim.x + threadIdx.x;
    int ch = tid >> 4;
    int n = tid & 15;
    int b = ch >> 9;
    int e = ch & 511;
    float A  = -expf(A_log[e*16 + n]);
    float Dv = Dp[e];
    const float2* duP = du + (size_t)(b*256)*512 + e;
    const float2* bcP = bc + (size_t)(b*256)*16 + n;
    const float*  zP  = xz + (size_t)(b*256)*1024 + 512 + e;
    float* yP = yout + (size_t)(b*256)*512 + e;

    float2 dv[2][8], bv[2][8];
    float  zv[2][8];
    #pragma unroll
    for (int i = 0; i < 8; i++) {
        dv[0][i] = duP[i*512];
        bv[0][i] = bcP[i*16];
    }
    if (n == 0) {
        #pragma unroll
        for (int i = 0; i < 8; i++) zv[0][i] = zP[i*1024];
    }
    float h = 0.f;
    int buf = 0;
    #pragma unroll 1
    for (int c = 0; c < 32; c++) {
        int nb = buf ^ 1;
        if (c < 31) {
            int t1 = c*8 + 8;
            #pragma unroll
            for (int i = 0; i < 8; i++) {
                dv[nb][i] = duP[(t1+i)*512];
                bv[nb][i] = bcP[(t1+i)*16];
            }
            if (n == 0) {
                #pragma unroll
                for (int i = 0; i < 8; i++) zv[nb][i] = zP[(size_t)(t1+i)*1024];
            }
        }
        float part[8];
        #pragma unroll
        for (int i = 0; i < 8; i++) {
            float2 duv = dv[buf][i];
            float2 bcv = bv[buf][i];
            float dA = __expf(duv.x * A);
            h = fmaf(h, dA, duv.x * bcv.x * duv.y);
            part[i] = h * bcv.y;
        }
        #pragma unroll
        for (int o = 8; o > 0; o >>= 1) {
            #pragma unroll
            for (int i = 0; i < 8; i++)
                part[i] += __shfl_down_sync(0xffffffffu, part[i], o, 16);
        }
        if (n == 0) {
            #pragma unroll
            for (int i = 0; i < 8; i++) {
                float z = zv[buf][i];
                float yy = part[i] + dv[buf][i].y * Dv;
                yP[(size_t)(c*8+i)*512] = yy * (z / (1.f + __expf(-z)));
            }
        }
        buf = nb;
    }
}

// =====================================================================
// Head tail
// =====================================================================
__global__ __launch_bounds__(256) void head2_kernel(const float* __restrict__ hh,
                             const float* __restrict__ w,
                             const float* __restrict__ b,
                             float* __restrict__ logits)
{
    int wid = (blockIdx.x * blockDim.x + threadIdx.x) >> 5;
    int lane = threadIdx.x & 31;
    const float* xr = hh + (size_t)wid*64;
    float acc = fmaf(xr[lane], w[lane], xr[lane+32]*w[lane+32]);
    #pragma unroll
    for (int o = 16; o > 0; o >>= 1) acc += __shfl_down_sync(0xffffffffu, acc, o);
    if (lane == 0) logits[wid] = acc + b[0];
}

__global__ __launch_bounds__(256) void softmax_kernel(const float* __restrict__ logits,
                               float* __restrict__ out)
{
    int b = blockIdx.x;
    int t = threadIdx.x;
    float v = logits[b*256 + t];
    __shared__ float red[8];
    __shared__ float sM, sS;
    float m = v;
    #pragma unroll
    for (int o = 16; o > 0; o >>= 1) m = fmaxf(m, __shfl_xor_sync(0xffffffffu, m, o));
    if ((t & 31) == 0) red[t >> 5] = m;
    __syncthreads();
    if (t < 8) {
        float mm = red[t];
        #pragma unroll
        for (int o = 4; o > 0; o >>= 1) mm = fmaxf(mm, __shfl_xor_sync(0xffu, mm, o, 8));
        if (t == 0) sM = mm;
    }
    __syncthreads();
    float e = expf(v - sM);
    float s = e;
    #pragma unroll
    for (int o = 16; o > 0; o >>= 1) s += __shfl_xor_sync(0xffffffffu, s, o);
    __syncthreads();
    if ((t & 31) == 0) red[t >> 5] = s;
    __syncthreads();
    if (t < 8) {
        float ss2 = red[t];
        #pragma unroll
        for (int o = 4; o > 0; o >>= 1) ss2 += __shfl_xor_sync(0xffu, ss2, o, 8);
        if (t == 0) sS = ss2;
    }
    __syncthreads();
    out[b*256 + t] = (t == 0) ? 0.f : e / sS;
}

// =====================================================================
// Launcher
// =====================================================================
extern "C" void kernel_launch(void* const* d_in, const int* in_sizes, int n_in,
                              void* d_out, int out_size)
{
    (void)in_sizes; (void)n_in; (void)out_size;
    const float* x        = (const float*)d_in[0];
    const float* cnn_w1   = (const float*)d_in[1];
    const float* cnn_b1   = (const float*)d_in[2];
    const float* cnn_w2   = (const float*)d_in[3];
    const float* cnn_b2   = (const float*)d_in[4];
    const float* cnn_w3   = (const float*)d_in[5];
    const float* cnn_b3   = (const float*)d_in[6];
    const float* fc_w     = (const float*)d_in[7];
    const float* fc_b     = (const float*)d_in[8];
    const float* norm_w   = (const float*)d_in[9];
    const float* in_proj_w= (const float*)d_in[10];
    const float* conv1d_w = (const float*)d_in[11];
    const float* conv1d_b = (const float*)d_in[12];
    const float* x_proj_w = (const float*)d_in[13];
    const float* dt_proj_w= (const float*)d_in[14];
    const float* dt_proj_b= (const float*)d_in[15];
    const float* A_log    = (const float*)d_in[16];
    const float* Dp       = (const float*)d_in[17];
    const float* out_proj_w=(const float*)d_in[18];
    const float* norm_f_w = (const float*)d_in[19];
    const float* head_w1  = (const float*)d_in[20];
    const float* head_b1  = (const float*)d_in[21];
    const float* head_w2  = (const float*)d_in[22];
    const float* head_b2  = (const float*)d_in[23];
    float* out = (float*)d_out;

    float *h, *rms, *xz, *y, *hh, *logits;
    float2 *bc, *du;
    cudaGetSymbolAddress((void**)&h,  g_h);
    cudaGetSymbolAddress((void**)&rms, g_rms);
    cudaGetSymbolAddress((void**)&xz, g_xz);
    cudaGetSymbolAddress((void**)&bc, g_bc);
    cudaGetSymbolAddress((void**)&du, g_du);
    cudaGetSymbolAddress((void**)&y,  g_y);
    cudaGetSymbolAddress((void**)&hh, g_hh);
    cudaGetSymbolAddress((void**)&logits, g_logits);

    cudaFuncSetAttribute(cnn_kernel,
        cudaFuncAttributeMaxDynamicSharedMemorySize, CNN_SMEM);

    // --- CNN encoder (fully fused, 2 blocks/SM) ---
    cnn_kernel<<<2048, 256, CNN_SMEM>>>(x, cnn_w1, cnn_b1, cnn_w2, cnn_b2,
                                        cnn_w3, cnn_b3, fc_w, fc_b, h);

    // --- Mamba layers ---
    for (int l = 0; l < 6; l++) {
        const float* nw  = norm_w     + (size_t)l*DM;
        const float* ipw = in_proj_w  + (size_t)l*2*DI*DM;
        const float* cw  = conv1d_w   + (size_t)l*DI*4;
        const float* cb  = conv1d_b   + (size_t)l*DI;
        const float* xpw = x_proj_w   + (size_t)l*48*DI;
        const float* dpw = dt_proj_w  + (size_t)l*DI*DTR;
        const float* dpb = dt_proj_b  + (size_t)l*DI;
        const float* al  = A_log      + (size_t)l*DI*DS;
        const float* dv  = Dp         + (size_t)l*DI;
        const float* opw = out_proj_w + (size_t)l*DM*DI;

        rms_scale_kernel<<<256, 256>>>(h, rms);
        gemm128_kernel<<<dim3(8, 16), 256>>>(h, rms, nw, ipw, xz, BT, 1024, 256);
        xproj_fused_kernel<<<128, 256>>>(xz, cw, cb, xpw, dpw, dpb, bc, du);
        scan_kernel<<<BATCH*DI*DS/256, 256>>>(du, xz, bc, al, dv, y);
        gemm64_kernel<1,0><<<dim3(4, 32), 256>>>(y, nullptr, nullptr, opw, nullptr, h, BT, 256, 512);
    }

    // --- Head ---
    rms_scale_kernel<<<256, 256>>>(h, rms);
    gemm64_kernel<2,1><<<dim3(1, 32), 256>>>(h, rms, norm_f_w, head_w1, head_b1, hh, BT, 64, 256);
    head2_kernel<<<BT*32/256, 256>>>(hh, head_w2, head_b2, logits);
    softmax_kernel<<<BATCH, 256>>>(logits, out);
}

// round 15
// speedup vs baseline: 1.6132x; 1.0291x over previous
#include <cuda_runtime.h>
#include <math.h>

// ---- problem constants ----
#define BATCH   8
#define TT      256
#define BT      2048          // BATCH*TT
#define DM      256           // d_model
#define DI      512           // d_inner
#define DS      16            // d_state
#define DTR     16            // dt_rank

typedef unsigned long long u64;

__device__ __forceinline__ u64 pk2(float lo, float hi) {
    u64 d;
    asm("mov.b64 %0, {%1, %2};" : "=l"(d)
        : "r"(__float_as_uint(lo)), "r"(__float_as_uint(hi)));
    return d;
}
__device__ __forceinline__ u64 ffma2(u64 a, u64 b, u64 c) {
    u64 d;
    asm("fma.rn.f32x2 %0, %1, %2, %3;" : "=l"(d) : "l"(a), "l"(b), "l"(c));
    return d;
}
__device__ __forceinline__ float2 upk2(u64 v) {
    unsigned lo, hi;
    asm("mov.b64 {%0, %1}, %2;" : "=r"(lo), "=r"(hi) : "l"(v));
    return make_float2(__uint_as_float(lo), __uint_as_float(hi));
}
union F4U { float4 f; u64 u[2]; };

// ---- scratch ----
__device__ float  g_h [BT*DM];
__device__ float  g_rms[BT];
__device__ float  g_xz[BT*2*DI];
__device__ float2 g_bc[BT*DS];
__device__ float2 g_du[BT*DI];
__device__ float  g_y [BT*DI];
__device__ float  g_hh[BT*64];
__device__ float  g_logits[BT];

// =====================================================================
// Fully fused CNN, 85KB smem (2 blocks/SM). conv1 produces 8 channels
// per pass; conv2 accumulates in registers across passes.
// =====================================================================
#define CNN_BB 0
#define CNN_F1 9792
#define CNN_W2 18768
#define CNN_W1 21072
#define CNN_ZS 21232
#define CNN_SMEM (21264*4)

__global__ __launch_bounds__(256) void cnn_kernel(
    const float* __restrict__ x,
    const float* __restrict__ w1, const float* __restrict__ b1,
    const float* __restrict__ w2, const float* __restrict__ b2,
    const float* __restrict__ w3, const float* __restrict__ b3,
    const float* __restrict__ fcw, const float* __restrict__ fcb,
    float* __restrict__ h)
{
    extern __shared__ __align__(16) float smem[];
    float* bb   = smem + CNN_BB;
    float* f1h  = smem + CNN_F1;
    float* w2b  = smem + CNN_W2;
    float* w1b  = smem + CNN_W1;
    float* zsh  = smem + CNN_ZS;
    int f = blockIdx.x;
    int tid = threadIdx.x;

    const float* xf = x + (size_t)f*4096;
    for (int i = tid; i < 65*65; i += 256) {
        int r = i / 65, c = i - r*65;
        bb[i] = (r < 64 && c < 64) ? xf[r*64+c] : 0.f;
    }
    if (tid < 144) w1b[tid] = w1[tid];
    if (tid < 16)  w1b[144+tid] = b1[tid];

    int cg2  = tid >> 5;
    int lane = tid & 31;
    int oy2 = lane >> 1;
    int xh  = lane & 1;
    u64 c2acc[4][4];
    #pragma unroll
    for (int c = 0; c < 4; c++) {
        float bbv = __ldg(&b2[cg2*4+c]);
        u64 bp = pk2(bbv, bbv);
        #pragma unroll
        for (int p = 0; p < 4; p++) c2acc[c][p] = bp;
    }

    #pragma unroll 1
    for (int pass = 0; pass < 2; pass++) {
        int ci0 = pass*8;
        __syncthreads();
        {
            int xg = tid & 3;
            int oy = (tid >> 2) & 31;
            int ch = tid >> 7;
            u64 acc1[4][4];
            #pragma unroll
            for (int c = 0; c < 4; c++) {
                float bbv = w1b[144 + ci0 + ch*4 + c];
                u64 bp = pk2(bbv, bbv);
                #pragma unroll
                for (int p = 0; p < 4; p++) acc1[c][p] = bp;
            }
            int i0 = oy*2, j0 = xg*16;
            #pragma unroll
            for (int ky = 0; ky < 3; ky++) {
                const float* rp = bb + (i0+ky)*65 + j0;
                float r[17];
                #pragma unroll
                for (int t = 0; t < 17; t++) r[t] = rp[t];
                u64 pr[12];
                #pragma unroll
                for (int p = 0; p < 4; p++)
                    #pragma unroll
                    for (int l = 0; l < 3; l++)
                        pr[p*3+l] = pk2(r[p*4+l], r[p*4+l+2]);
                #pragma unroll
                for (int c = 0; c < 4; c++) {
                    const float* wp = w1b + (ci0 + ch*4+c)*9 + ky*3;
                    u64 wd0 = pk2(wp[0], wp[0]);
                    u64 wd1 = pk2(wp[1], wp[1]);
                    u64 wd2 = pk2(wp[2], wp[2]);
                    #pragma unroll
                    for (int p = 0; p < 4; p++) {
                        acc1[c][p] = ffma2(pr[p*3+0], wd0, acc1[c][p]);
                        acc1[c][p] = ffma2(pr[p*3+1], wd1, acc1[c][p]);
                        acc1[c][p] = ffma2(pr[p*3+2], wd2, acc1[c][p]);
                    }
                }
            }
            #pragma unroll
            for (int c = 0; c < 4; c++)
                #pragma unroll
                for (int p = 0; p < 4; p++) {
                    float2 v = upk2(acc1[c][p]);
                    *(float2*)&f1h[(ch*4+c)*1122 + oy*34 + xg*8 + 2*p]
                        = make_float2(fmaxf(v.x, 0.f), fmaxf(v.y, 0.f));
                }
        }
        for (int idx = tid; idx < 8*34; idx += 256) {
            int ci = idx / 34, j = idx - ci*34;
            f1h[ci*1122 + 32*34 + j] = 0.f;
        }
        for (int idx = tid; idx < 8*32; idx += 256) {
            int ci = idx >> 5, i = idx & 31;
            f1h[ci*1122 + i*34 + 32] = 0.f;
        }
        for (int idx = tid; idx < 2304; idx += 256) {
            int co = idx / 72;
            int rem = idx - co*72;
            int ci_l = rem / 9, k = rem - ci_l*9;
            w2b[idx] = w2[(co*16 + ci0 + ci_l)*9 + k];
        }
        __syncthreads();
        #pragma unroll 1
        for (int ci = 0; ci < 8; ci++) {
            const float* base = f1h + ci*1122 + (2*oy2)*34 + xh*16;
            #pragma unroll
            for (int row = 0; row < 3; row++) {
                const float* rp = base + row*34;
                float r[17];
                #pragma unroll
                for (int t = 0; t < 17; t++) r[t] = rp[t];
                u64 pr[12];
                #pragma unroll
                for (int p = 0; p < 4; p++)
                    #pragma unroll
                    for (int l = 0; l < 3; l++)
                        pr[p*3+l] = pk2(r[p*4+l], r[p*4+l+2]);
                #pragma unroll
                for (int c = 0; c < 4; c++) {
                    const float* wp = w2b + (cg2*4+c)*72 + ci*9 + row*3;
                    u64 wd0 = pk2(wp[0], wp[0]);
                    u64 wd1 = pk2(wp[1], wp[1]);
                    u64 wd2 = pk2(wp[2], wp[2]);
                    #pragma unroll
                    for (int p = 0; p < 4; p++) {
                        c2acc[c][p] = ffma2(pr[p*3+0], wd0, c2acc[c][p]);
                        c2acc[c][p] = ffma2(pr[p*3+1], wd1, c2acc[c][p]);
                        c2acc[c][p] = ffma2(pr[p*3+2], wd2, c2acc[c][p]);
                    }
                }
            }
        }
    }
    __syncthreads();
    #pragma unroll
    for (int c = 0; c < 4; c++)
        #pragma unroll
        for (int p = 0; p < 4; p++) {
            float2 v = upk2(c2acc[c][p]);
            *(float2*)&bb[(cg2*4+c)*306 + oy2*18 + xh*8 + 2*p]
                = make_float2(fmaxf(v.x, 0.f), fmaxf(v.y, 0.f));
        }
    for (int idx = tid; idx < 32*18; idx += 256) {
        int co = idx / 18, j = idx - co*18;
        bb[co*306 + 16*18 + j] = 0.f;
    }
    for (int idx = tid; idx < 32*16; idx += 256) {
        int co = idx >> 4, i = idx & 15;
        bb[co*306 + i*18 + 16] = 0.f;
    }

    {
        int cg  = tid >> 5;
        int oy3 = (tid >> 2) & 7;
        int xq  = tid & 3;
        u64 acc3[4];
        #pragma unroll
        for (int c = 0; c < 4; c++) {
            float bbv = __ldg(&b3[cg*4+c]);
            acc3[c] = pk2(bbv, bbv);
        }
        #pragma unroll 1
        for (int pass = 0; pass < 4; pass++) {
            int ci0 = pass*8;
            __syncthreads();
            for (int idx = tid; idx < 2304; idx += 256) {
                int co = idx / 72;
                int rem = idx - co*72;
                int ci_l = rem / 9, k = rem - ci_l*9;
                w2b[idx] = w3[(co*32 + ci0 + ci_l)*9 + k];
            }
            __syncthreads();
            #pragma unroll 1
            for (int ci = 0; ci < 8; ci++) {
                const float* base = bb + (ci0+ci)*306 + (2*oy3)*18 + xq*4;
                #pragma unroll
                for (int row = 0; row < 3; row++) {
                    const float* rp = base + row*18;
                    float r[5];
                    #pragma unroll
                    for (int q = 0; q < 5; q++) r[q] = rp[q];
                    u64 p0 = pk2(r[0], r[2]);
                    u64 p1 = pk2(r[1], r[3]);
                    u64 p2 = pk2(r[2], r[4]);
                    #pragma unroll
                    for (int c = 0; c < 4; c++) {
                        const float* wp = w2b + (cg*4+c)*72 + ci*9 + row*3;
                        u64 wd0 = pk2(wp[0], wp[0]);
                        u64 wd1 = pk2(wp[1], wp[1]);
                        u64 wd2 = pk2(wp[2], wp[2]);
                        acc3[c] = ffma2(p0, wd0, acc3[c]);
                        acc3[c] = ffma2(p1, wd1, acc3[c]);
                        acc3[c] = ffma2(p2, wd2, acc3[c]);
                    }
                }
            }
        }
        #pragma unroll
        for (int c = 0; c < 4; c++) {
            float2 v = upk2(acc3[c]);
            float s = fmaxf(v.x, 0.f) + fmaxf(v.y, 0.f);
            #pragma unroll
            for (int o = 16; o > 0; o >>= 1) s += __shfl_down_sync(0xffffffffu, s, o);
            if ((tid & 31) == 0) zsh[cg*4 + c] = s * (1.f/64.f);
        }
    }
    __syncthreads();

    {
        int j = tid;
        float a = __ldg(&fcb[j]);
        const float4* wp = (const float4*)(fcw + j*32);
        #pragma unroll
        for (int k = 0; k < 8; k++) {
            float4 wv = __ldg(&wp[k]);
            const float* zk = zsh + k*4;
            a = fmaf(zk[0],wv.x, fmaf(zk[1],wv.y, fmaf(zk[2],wv.z, fmaf(zk[3],wv.w, a))));
        }
        h[(size_t)f*256 + j] = a;
    }
}

// =====================================================================
// Mamba pieces
// =====================================================================
__global__ __launch_bounds__(256) void rms_scale_kernel(const float* __restrict__ x,
                               float* __restrict__ sc)
{
    int tok = blockIdx.x*8 + (threadIdx.x >> 5);
    int lane = threadIdx.x & 31;
    const float4* xr = (const float4*)(x + (size_t)tok*256);
    float4 v0 = xr[lane*2], v1 = xr[lane*2+1];
    float ss = v0.x*v0.x + v0.y*v0.y + v0.z*v0.z + v0.w*v0.w
             + v1.x*v1.x + v1.y*v1.y + v1.z*v1.z + v1.w*v1.w;
    #pragma unroll
    for (int o = 16; o > 0; o >>= 1) ss += __shfl_xor_sync(0xffffffffu, ss, o);
    if (lane == 0) sc[tok] = rsqrtf(ss * (1.f/256.f) + 1e-5f);
}

// tile 128x128, 256 thr, 8x8 micro, f32x2, Kt=16, prefetch; A normalized on load.
__global__ __launch_bounds__(256) void gemm128_kernel(const float* __restrict__ A,
                              const float* __restrict__ scale,
                              const float* __restrict__ nw,
                              const float* __restrict__ W,
                              float* __restrict__ C,
                              int M, int N, int K)
{
    __shared__ __align__(16) float As[16][132];
    __shared__ __align__(16) float Ws[16][132];
    int bm = blockIdx.y * 128;
    int bn = blockIdx.x * 128;
    int tid = threadIdx.x;
    int tx = tid & 15, ty = tid >> 4;
    int r0 = tid >> 2, c0 = tid & 3;
    int r1 = r0 + 64;
    const float* Ap0 = &A[(size_t)(bm+r0)*K + c0*4];
    const float* Ap1 = &A[(size_t)(bm+r1)*K + c0*4];
    const float* Wp0 = &W[(size_t)(bn+r0)*K + c0*4];
    const float* Wp1 = &W[(size_t)(bn+r1)*K + c0*4];
    float sc0 = __ldg(&scale[bm+r0]);
    float sc1 = __ldg(&scale[bm+r1]);
    float4 va0 = *(const float4*)Ap0, va1 = *(const float4*)Ap1;
    float4 vw0 = *(const float4*)Wp0, vw1 = *(const float4*)Wp1;
    float4 vnw = *(const float4*)&nw[c0*4];
    u64 acc[4][8];
    #pragma unroll
    for (int i = 0; i < 4; i++)
        #pragma unroll
        for (int j = 0; j < 8; j++) acc[i][j] = 0ull;
    for (int k0 = 0; k0 < K; k0 += 16) {
        #pragma unroll
        for (int i = 0; i < 4; i++) {
            float nv = (&vnw.x)[i];
            As[c0*4+i][r0] = (&va0.x)[i] * sc0 * nv;
            As[c0*4+i][r1] = (&va1.x)[i] * sc1 * nv;
            Ws[c0*4+i][r0] = (&vw0.x)[i];
            Ws[c0*4+i][r1] = (&vw1.x)[i];
        }
        __syncthreads();
        if (k0 + 16 < K) {
            va0 = *(const float4*)(Ap0 + k0 + 16);
            va1 = *(const float4*)(Ap1 + k0 + 16);
            vw0 = *(const float4*)(Wp0 + k0 + 16);
            vw1 = *(const float4*)(Wp1 + k0 + 16);
            vnw = *(const float4*)&nw[k0 + 16 + c0*4];
        }
        #pragma unroll
        for (int k = 0; k < 16; k++) {
            F4U au0, au1;
            au0.f = *(const float4*)&As[k][ty*8];
            au1.f = *(const float4*)&As[k][ty*8+4];
            float4 w0 = *(const float4*)&Ws[k][tx*8];
            float4 w1 = *(const float4*)&Ws[k][tx*8+4];
            u64 wv[8];
            wv[0] = pk2(w0.x, w0.x); wv[1] = pk2(w0.y, w0.y);
            wv[2] = pk2(w0.z, w0.z); wv[3] = pk2(w0.w, w0.w);
            wv[4] = pk2(w1.x, w1.x); wv[5] = pk2(w1.y, w1.y);
            wv[6] = pk2(w1.z, w1.z); wv[7] = pk2(w1.w, w1.w);
            u64 ap[4] = { au0.u[0], au0.u[1], au1.u[0], au1.u[1] };
            #pragma unroll
            for (int i = 0; i < 4; i++)
                #pragma unroll
                for (int j = 0; j < 8; j++)
                    acc[i][j] = ffma2(ap[i], wv[j], acc[i][j]);
        }
        __syncthreads();
    }
    #pragma unroll
    for (int i = 0; i < 4; i++) {
        int m0 = bm + ty*8 + 2*i;
        float lo[8], hi[8];
        #pragma unroll
        for (int j = 0; j < 8; j++) {
            float2 v = upk2(acc[i][j]);
            lo[j] = v.x; hi[j] = v.y;
        }
        float* c0p = &C[(size_t)m0*N + bn + tx*8];
        float* c1p = &C[(size_t)(m0+1)*N + bn + tx*8];
        *(float4*)c0p       = make_float4(lo[0], lo[1], lo[2], lo[3]);
        *(float4*)(c0p + 4) = make_float4(lo[4], lo[5], lo[6], lo[7]);
        *(float4*)c1p       = make_float4(hi[0], hi[1], hi[2], hi[3]);
        *(float4*)(c1p + 4) = make_float4(hi[4], hi[5], hi[6], hi[7]);
    }
}

// tile 64x64, 256 thr, 16 outputs, f32x2, Kt=16, prefetch.
// EPI: 1 accumulate, 2 bias+gelu. NORM: A*scale[m]*nw[k] on load.
template<int EPI, int NORM>
__global__ __launch_bounds__(256) void gemm64_kernel(const float* __restrict__ A,
                              const float* __restrict__ scale,
                              const float* __restrict__ nw,
                              const float* __restrict__ W,
                              const float* __restrict__ bias,
                              float* __restrict__ C,
                              int M, int N, int K)
{
    __shared__ __align__(16) float As[16][68];
    __shared__ __align__(16) float Ws[16][68];
    int bm = blockIdx.y * 64;
    int bn = blockIdx.x * 64;
    int tid = threadIdx.x;
    int tx = tid & 15, ty = tid >> 4;
    int r = tid >> 2, c = tid & 3;
    const float* Ap = &A[(size_t)(bm+r)*K + c*4];
    const float* Wp = &W[(size_t)(bn+r)*K + c*4];
    float4 va = *(const float4*)Ap;
    float4 vw = *(const float4*)Wp;
    float sc = 1.f;
    float4 vnw;
    if (NORM) {
        sc = __ldg(&scale[bm+r]);
        vnw = *(const float4*)&nw[c*4];
    }
    u64 acc[2][4];
    #pragma unroll
    for (int p = 0; p < 2; p++)
        #pragma unroll
        for (int j = 0; j < 4; j++) acc[p][j] = 0ull;
    for (int k0 = 0; k0 < K; k0 += 16) {
        #pragma unroll
        for (int i = 0; i < 4; i++) {
            float av = (&va.x)[i];
            if (NORM) av *= sc * (&vnw.x)[i];
            As[c*4+i][r] = av;
            Ws[c*4+i][r] = (&vw.x)[i];
        }
        __syncthreads();
        if (k0 + 16 < K) {
            va = *(const float4*)(Ap + k0 + 16);
            vw = *(const float4*)(Wp + k0 + 16);
            if (NORM) vnw = *(const float4*)&nw[k0 + 16 + c*4];
        }
        #pragma unroll
        for (int k = 0; k < 16; k++) {
            F4U au;
            au.f = *(const float4*)&As[k][ty*4];
            float4 w4 = *(const float4*)&Ws[k][tx*4];
            u64 wv0 = pk2(w4.x, w4.x);
            u64 wv1 = pk2(w4.y, w4.y);
            u64 wv2 = pk2(w4.z, w4.z);
            u64 wv3 = pk2(w4.w, w4.w);
            acc[0][0] = ffma2(au.u[0], wv0, acc[0][0]);
            acc[0][1] = ffma2(au.u[0], wv1, acc[0][1]);
            acc[0][2] = ffma2(au.u[0], wv2, acc[0][2]);
            acc[0][3] = ffma2(au.u[0], wv3, acc[0][3]);
            acc[1][0] = ffma2(au.u[1], wv0, acc[1][0]);
            acc[1][1] = ffma2(au.u[1], wv1, acc[1][1]);
            acc[1][2] = ffma2(au.u[1], wv2, acc[1][2]);
            acc[1][3] = ffma2(au.u[1], wv3, acc[1][3]);
        }
        __syncthreads();
    }
    #pragma unroll
    for (int p = 0; p < 2; p++) {
        int m0 = bm + ty*4 + 2*p;
        float lo[4], hi[4];
        #pragma unroll
        for (int j = 0; j < 4; j++) {
            float2 v = upk2(acc[p][j]);
            lo[j] = v.x; hi[j] = v.y;
        }
        size_t base0 = (size_t)m0*N + bn + tx*4;
        size_t base1 = (size_t)(m0+1)*N + bn + tx*4;
        if (EPI == 1) {
            float4 o0 = *(float4*)&C[base0];
            float4 o1 = *(float4*)&C[base1];
            o0.x += lo[0]; o0.y += lo[1]; o0.z += lo[2]; o0.w += lo[3];
            o1.x += hi[0]; o1.y += hi[1]; o1.z += hi[2]; o1.w += hi[3];
            *(float4*)&C[base0] = o0;
            *(float4*)&C[base1] = o1;
        } else {
            float4 o0, o1;
            float* p0 = &o0.x;
            float* p1 = &o1.x;
            #pragma unroll
            for (int j = 0; j < 4; j++) {
                float bb = bias[bn + tx*4 + j];
                float v = lo[j] + bb;
                float v3 = v*v*v;
                p0[j] = 0.5f * v * (1.f + tanhf(0.7978845608028654f * (v + 0.044715f*v3)));
                v = hi[j] + bb;
                v3 = v*v*v;
                p1[j] = 0.5f * v * (1.f + tanhf(0.7978845608028654f * (v + 0.044715f*v3)));
            }
            *(float4*)&C[base0] = o0;
            *(float4*)&C[base1] = o1;
        }
    }
}

// Fused conv1d+silu + x_proj + dt_proj: 8 tokens/block, 128 threads, grid 256.
#define SXIDX(tok, k) ((tok)*512 + (((k) + (tok)*4) & 511))
__global__ __launch_bounds__(128) void xproj_fused_kernel(
    const float* __restrict__ xz,
    const float* __restrict__ cw,
    const float* __restrict__ cb,
    const float* __restrict__ xpw,
    const float* __restrict__ dpw,
    const float* __restrict__ dpb,
    float2* __restrict__ bc,
    float2* __restrict__ du)
{
    __shared__ __align__(16) float sx[8*512];
    __shared__ __align__(16) float buf[48*68];
    __shared__ __align__(16) float sdt[8*16];
    int tok0 = blockIdx.x * 8;
    int tid = threadIdx.x;

    // ---- conv1d + silu from xz into sx ----
    for (int idx = tid; idx < 2048; idx += 128) {
        int e = idx >> 2, k = idx & 3;
        buf[k*512 + e] = cw[idx];
    }
    for (int idx = tid; idx < 512; idx += 128) buf[2048 + idx] = cb[idx];
    __syncthreads();
    int tl0 = tok0 & 255;
    #pragma unroll 1
    for (int s = 0; s < 8; s++) {
        int q = tid + s*128;          // 0..1023 float4 outputs
        int t = q >> 7;               // token 0..7
        int e = (q & 127)*4;
        float4 acc = *(const float4*)&buf[2048 + e];
        #pragma unroll
        for (int k = 0; k < 4; k++) {
            if (tl0 + t - 3 + k >= 0) {
                float4 xv = *(const float4*)&xz[(size_t)(tok0 + t - 3 + k)*1024 + e];
                float4 wv = *(const float4*)&buf[k*512 + e];
                acc.x = fmaf(xv.x, wv.x, acc.x);
                acc.y = fmaf(xv.y, wv.y, acc.y);
                acc.z = fmaf(xv.z, wv.z, acc.z);
                acc.w = fmaf(xv.w, wv.w, acc.w);
            }
        }
        acc.x = acc.x / (1.f + __expf(-acc.x));
        acc.y = acc.y / (1.f + __expf(-acc.y));
        acc.z = acc.z / (1.f + __expf(-acc.z));
        acc.w = acc.w / (1.f + __expf(-acc.w));
        *(float4*)&sx[SXIDX(t, e)] = acc;
    }

    // ---- Phase A: dbc = xin . xpw^T ----
    int tg = tid & 7;        // token 0..7
    int jg = tid >> 3;       // 0..15 -> 3 j each
    int rot = tg*4;
    const float* sxr = sx + tg*512;
    float acc0 = 0.f, acc1 = 0.f, acc2 = 0.f;
    #pragma unroll 1
    for (int kc = 0; kc < 8; kc++) {
        int k0 = kc*64;
        __syncthreads();
        #pragma unroll
        for (int s = 0; s < 6; s++) {
            int q = tid + s*128;      // 0..767 float4
            int r = q >> 4, c = q & 15;
            float4 v = *(const float4*)&xpw[(size_t)r*512 + k0 + c*4];
            float* dst = buf + r*68 + c*4;
            dst[0]=v.x; dst[1]=v.y; dst[2]=v.z; dst[3]=v.w;
        }
        __syncthreads();
        const float* w0 = buf + (jg*3+0)*68;
        const float* w1 = buf + (jg*3+1)*68;
        const float* w2 = buf + (jg*3+2)*68;
        #pragma unroll
        for (int k4 = 0; k4 < 16; k4++) {
            int kk = (k0 + k4*4 + rot) & 511;
            float4 xv = *(const float4*)&sxr[kk];
            float4 a4 = *(const float4*)&w0[k4*4];
            float4 b4 = *(const float4*)&w1[k4*4];
            float4 c4 = *(const float4*)&w2[k4*4];
            acc0 = fmaf(xv.x,a4.x, fmaf(xv.y,a4.y, fmaf(xv.z,a4.z, fmaf(xv.w,a4.w, acc0))));
            acc1 = fmaf(xv.x,b4.x, fmaf(xv.y,b4.y, fmaf(xv.z,b4.z, fmaf(xv.w,b4.w, acc1))));
            acc2 = fmaf(xv.x,c4.x, fmaf(xv.y,c4.y, fmaf(xv.z,c4.z, fmaf(xv.w,c4.w, acc2))));
        }
    }
    {
        float av[3] = {acc0, acc1, acc2};
        #pragma unroll
        for (int jj = 0; jj < 3; jj++) {
            int j = jg*3 + jj;
            float v = av[jj];
            int tok = tok0 + tg;
            if (j < 16)       sdt[tg*16 + j] = v;
            else if (j < 32)  bc[tok*16 + (j-16)].x = v;
            else              bc[tok*16 + (j-32)].y = v;
        }
    }

    // ---- Phase B: delta = softplus(dt . dpw^T + dpb); du = (delta, u) ----
    #pragma unroll 1
    for (int ec = 0; ec < 4; ec++) {
        int e0 = ec*128;
        __syncthreads();
        #pragma unroll
        for (int s = 0; s < 4; s++) {
            int q = tid + s*128;      // 0..511 float4
            int r = q >> 2, c = q & 3;
            float4 v = *(const float4*)&dpw[(size_t)(e0+r)*16 + c*4];
            float* dst = buf + r*16 + c*4;
            dst[0]=v.x; dst[1]=v.y; dst[2]=v.z; dst[3]=v.w;
        }
        __syncthreads();
        #pragma unroll 1
        for (int s = 0; s < 8; s++) {
            int idx = tid + s*128;    // 0..1023
            int e_l = idx & 127;
            int tok = idx >> 7;       // 0..7
            int e = e0 + e_l;
            const float* dr = sdt + tok*16;
            const float* wr = buf + e_l*16;
            float a = dpb[e];
            #pragma unroll
            for (int k = 0; k < 16; k++) a = fmaf(dr[k], wr[k], a);
            float sp = (a > 20.f) ? a : log1pf(expf(a));
            float u = sx[SXIDX(tok, e)];
            du[(size_t)(tok0+tok)*512 + e] = make_float2(sp, u);
        }
    }
}

// Selective scan: chunked register prefetch + pipelined shfl reduction
__global__ __launch_bounds__(256) void scan_kernel(const float2* __restrict__ du,
                            const float* __restrict__ xz,
                            const float2* __restrict__ bc,
                            const float* __restrict__ A_log,
                            const float* __restrict__ Dp,
                            float* __restrict__ yout)
{
    int tid = blockIdx.x * blockDim.x + threadIdx.x;
    int ch = tid >> 4;
    int n = tid & 15;
    int b = ch >> 9;
    int e = ch & 511;
    float A  = -expf(A_log[e*16 + n]);
    float Dv = Dp[e];
    const float2* duP = du + (size_t)(b*256)*512 + e;
    const float2* bcP = bc + (size_t)(b*256)*16 + n;
    const float*  zP  = xz + (size_t)(b*256)*1024 + 512 + e;
    float* yP = yout + (size_t)(b*256)*512 + e;

    float2 dv[2][8], bv[2][8];
    float  zv[2][8];
    #pragma unroll
    for (int i = 0; i < 8; i++) {
        dv[0][i] = duP[i*512];
        bv[0][i] = bcP[i*16];
    }
    if (n == 0) {
        #pragma unroll
        for (int i = 0; i < 8; i++) zv[0][i] = zP[i*1024];
    }
    float h = 0.f;
    int buf = 0;
    #pragma unroll 1
    for (int c = 0; c < 32; c++) {
        int nb = buf ^ 1;
        if (c < 31) {
            int t1 = c*8 + 8;
            #pragma unroll
            for (int i = 0; i < 8; i++) {
                dv[nb][i] = duP[(t1+i)*512];
                bv[nb][i] = bcP[(t1+i)*16];
            }
            if (n == 0) {
                #pragma unroll
                for (int i = 0; i < 8; i++) zv[nb][i] = zP[(size_t)(t1+i)*1024];
            }
        }
        float part[8];
        #pragma unroll
        for (int i = 0; i < 8; i++) {
            float2 duv = dv[buf][i];
            float2 bcv = bv[buf][i];
            float dA = __expf(duv.x * A);
            h = fmaf(h, dA, duv.x * bcv.x * duv.y);
            part[i] = h * bcv.y;
        }
        #pragma unroll
        for (int o = 8; o > 0; o >>= 1) {
            #pragma unroll
            for (int i = 0; i < 8; i++)
                part[i] += __shfl_down_sync(0xffffffffu, part[i], o, 16);
        }
        if (n == 0) {
            #pragma unroll
            for (int i = 0; i < 8; i++) {
                float z = zv[buf][i];
                float yy = part[i] + dv[buf][i].y * Dv;
                yP[(size_t)(c*8+i)*512] = yy * (z / (1.f + __expf(-z)));
            }
        }
        buf = nb;
    }
}

// =====================================================================
// Head tail
// =====================================================================
__global__ __launch_bounds__(256) void head2_kernel(const float* __restrict__ hh,
                             const float* __restrict__ w,
                             const float* __restrict__ b,
                             float* __restrict__ logits)
{
    int wid = (blockIdx.x * blockDim.x + threadIdx.x) >> 5;
    int lane = threadIdx.x & 31;
    const float* xr = hh + (size_t)wid*64;
    float acc = fmaf(xr[lane], w[lane], xr[lane+32]*w[lane+32]);
    #pragma unroll
    for (int o = 16; o > 0; o >>= 1) acc += __shfl_down_sync(0xffffffffu, acc, o);
    if (lane == 0) logits[wid] = acc + b[0];
}

__global__ __launch_bounds__(256) void softmax_kernel(const float* __restrict__ logits,
                               float* __restrict__ out)
{
    int b = blockIdx.x;
    int t = threadIdx.x;
    float v = logits[b*256 + t];
    __shared__ float red[8];
    __shared__ float sM, sS;
    float m = v;
    #pragma unroll
    for (int o = 16; o > 0; o >>= 1) m = fmaxf(m, __shfl_xor_sync(0xffffffffu, m, o));
    if ((t & 31) == 0) red[t >> 5] = m;
    __syncthreads();
    if (t < 8) {
        float mm = red[t];
        #pragma unroll
        for (int o = 4; o > 0; o >>= 1) mm = fmaxf(mm, __shfl_xor_sync(0xffu, mm, o, 8));
        if (t == 0) sM = mm;
    }
    __syncthreads();
    float e = expf(v - sM);
    float s = e;
    #pragma unroll
    for (int o = 16; o > 0; o >>= 1) s += __shfl_xor_sync(0xffffffffu, s, o);
    __syncthreads();
    if ((t & 31) == 0) red[t >> 5] = s;
    __syncthreads();
    if (t < 8) {
        float ss2 = red[t];
        #pragma unroll
        for (int o = 4; o > 0; o >>= 1) ss2 += __shfl_xor_sync(0xffu, ss2, o, 8);
        if (t == 0) sS = ss2;
    }
    __syncthreads();
    out[b*256 + t] = (t == 0) ? 0.f : e / sS;
}

// =====================================================================
// Launcher
// =====================================================================
extern "C" void kernel_launch(void* const* d_in, const int* in_sizes, int n_in,
                              void* d_out, int out_size)
{
    (void)in_sizes; (void)n_in; (void)out_size;
    const float* x        = (const float*)d_in[0];
    const float* cnn_w1   = (const float*)d_in[1];
    const float* cnn_b1   = (const float*)d_in[2];
    const float* cnn_w2   = (const float*)d_in[3];
    const float* cnn_b2   = (const float*)d_in[4];
    const float* cnn_w3   = (const float*)d_in[5];
    const float* cnn_b3   = (const float*)d_in[6];
    const float* fc_w     = (const float*)d_in[7];
    const float* fc_b     = (const float*)d_in[8];
    const float* norm_w   = (const float*)d_in[9];
    const float* in_proj_w= (const float*)d_in[10];
    const float* conv1d_w = (const float*)d_in[11];
    const float* conv1d_b = (const float*)d_in[12];
    const float* x_proj_w = (const float*)d_in[13];
    const float* dt_proj_w= (const float*)d_in[14];
    const float* dt_proj_b= (const float*)d_in[15];
    const float* A_log    = (const float*)d_in[16];
    const float* Dp       = (const float*)d_in[17];
    const float* out_proj_w=(const float*)d_in[18];
    const float* norm_f_w = (const float*)d_in[19];
    const float* head_w1  = (const float*)d_in[20];
    const float* head_b1  = (const float*)d_in[21];
    const float* head_w2  = (const float*)d_in[22];
    const float* head_b2  = (const float*)d_in[23];
    float* out = (float*)d_out;

    float *h, *rms, *xz, *y, *hh, *logits;
    float2 *bc, *du;
    cudaGetSymbolAddress((void**)&h,  g_h);
    cudaGetSymbolAddress((void**)&rms, g_rms);
    cudaGetSymbolAddress((void**)&xz, g_xz);
    cudaGetSymbolAddress((void**)&bc, g_bc);
    cudaGetSymbolAddress((void**)&du, g_du);
    cudaGetSymbolAddress((void**)&y,  g_y);
    cudaGetSymbolAddress((void**)&hh, g_hh);
    cudaGetSymbolAddress((void**)&logits, g_logits);

    cudaFuncSetAttribute(cnn_kernel,
        cudaFuncAttributeMaxDynamicSharedMemorySize, CNN_SMEM);

    // --- CNN encoder (fully fused, 2 blocks/SM) ---
    cnn_kernel<<<2048, 256, CNN_SMEM>>>(x, cnn_w1, cnn_b1, cnn_w2, cnn_b2,
                                        cnn_w3, cnn_b3, fc_w, fc_b, h);

    // --- Mamba layers ---
    for (int l = 0; l < 6; l++) {
        const float* nw  = norm_w     + (size_t)l*DM;
        const float* ipw = in_proj_w  + (size_t)l*2*DI*DM;
        const float* cw  = conv1d_w   + (size_t)l*DI*4;
        const float* cb  = conv1d_b   + (size_t)l*DI;
        const float* xpw = x_proj_w   + (size_t)l*48*DI;
        const float* dpw = dt_proj_w  + (size_t)l*DI*DTR;
        const float* dpb = dt_proj_b  + (size_t)l*DI;
        const float* al  = A_log      + (size_t)l*DI*DS;
        const float* dv  = Dp         + (size_t)l*DI;
        const float* opw = out_proj_w + (size_t)l*DM*DI;

        rms_scale_kernel<<<256, 256>>>(h, rms);
        gemm128_kernel<<<dim3(8, 16), 256>>>(h, rms, nw, ipw, xz, BT, 1024, 256);
        xproj_fused_kernel<<<256, 128>>>(xz, cw, cb, xpw, dpw, dpb, bc, du);
        scan_kernel<<<BATCH*DI*DS/256, 256>>>(du, xz, bc, al, dv, y);
        gemm64_kernel<1,0><<<dim3(4, 32), 256>>>(y, nullptr, nullptr, opw, nullptr, h, BT, 256, 512);
    }

    // --- Head ---
    rms_scale_kernel<<<256, 256>>>(h, rms);
    gemm64_kernel<2,1><<<dim3(1, 32), 256>>>(h, rms, norm_f_w, head_w1, head_b1, hh, BT, 64, 256);
    head2_kernel<<<BT*32/256, 256>>>(hh, head_w2, head_b2, logits);
    softmax_kernel<<<BATCH, 256>>>(logits, out);
}